// round 10
// baseline (speedup 1.0000x reference)
#include <cuda_runtime.h>
#include <cuda_bf16.h>
#include <cstdint>
#include <math.h>

#define SEQ 4096
#define DM  1024
#define NH  16
#define DK  64

using bf16 = __nv_bfloat16;

// ---------------------------------------------------------------------------
// Scratch (__device__ globals: allocation-guard safe) — all bf16 hi/lo pairs
// ---------------------------------------------------------------------------
__device__ bf16 g_xqh[SEQ * DM], g_xql[SEQ * DM];
__device__ bf16 g_xkh[SEQ * DM], g_xkl[SEQ * DM];
__device__ bf16 g_xvh[SEQ * DM], g_xvl[SEQ * DM];
__device__ bf16 g_wqh[DM * DM],  g_wql[DM * DM];
__device__ bf16 g_wkh[DM * DM],  g_wkl[DM * DM];
__device__ bf16 g_wvh[DM * DM],  g_wvl[DM * DM];
__device__ bf16 g_woh[DM * DM],  g_wol[DM * DM];
__device__ bf16 g_Qh[SEQ * DM],  g_Ql[SEQ * DM];
__device__ bf16 g_Kh[SEQ * DM],  g_Kl[SEQ * DM];
__device__ bf16 g_Vh[SEQ * DM],  g_Vl[SEQ * DM];
__device__ bf16 g_oh[SEQ * DM],  g_ol[SEQ * DM];

// ---------------------------------------------------------------------------
// PTX helpers — valid at compute_103 (no tcgen05)
// ---------------------------------------------------------------------------
__device__ __forceinline__ uint32_t smem_u32(const void* p) {
    uint32_t a;
    asm("{ .reg .u64 t; cvta.to.shared.u64 t, %1; cvt.u32.u64 %0, t; }" : "=r"(a) : "l"(p));
    return a;
}
__device__ __forceinline__ void ldsm_x4(uint32_t* r, uint32_t addr) {
    asm volatile("ldmatrix.sync.aligned.m8n8.x4.shared.b16 {%0,%1,%2,%3}, [%4];"
                 : "=r"(r[0]), "=r"(r[1]), "=r"(r[2]), "=r"(r[3]) : "r"(addr));
}
__device__ __forceinline__ void ldsm_x4_trans(uint32_t* r, uint32_t addr) {
    asm volatile("ldmatrix.sync.aligned.m8n8.x4.trans.shared.b16 {%0,%1,%2,%3}, [%4];"
                 : "=r"(r[0]), "=r"(r[1]), "=r"(r[2]), "=r"(r[3]) : "r"(addr));
}
__device__ __forceinline__ void mma_bf16(float* c, const uint32_t* a, const uint32_t* b) {
    asm volatile(
        "mma.sync.aligned.m16n8k16.row.col.f32.bf16.bf16.f32 "
        "{%0,%1,%2,%3}, {%4,%5,%6,%7}, {%8,%9}, {%0,%1,%2,%3};"
        : "+f"(c[0]), "+f"(c[1]), "+f"(c[2]), "+f"(c[3])
        : "r"(a[0]), "r"(a[1]), "r"(a[2]), "r"(a[3]), "r"(b[0]), "r"(b[1]));
}
__device__ __forceinline__ void cp16(uint32_t s, const void* g) {
    asm volatile("cp.async.cg.shared.global [%0], [%1], 16;" :: "r"(s), "l"(g));
}
#define CP_COMMIT() asm volatile("cp.async.commit_group;" ::: "memory")
#define CP_WAIT(n)  asm volatile("cp.async.wait_group %0;" :: "n"(n) : "memory")

__device__ __forceinline__ void split_pack2(float x, float y, uint32_t& hi, uint32_t& lo) {
    __nv_bfloat162 h2 = __floats2bfloat162_rn(x, y);
    float rx = x - __bfloat162float(h2.x);
    float ry = y - __bfloat162float(h2.y);
    __nv_bfloat162 l2 = __floats2bfloat162_rn(rx, ry);
    hi = *reinterpret_cast<uint32_t*>(&h2);
    lo = *reinterpret_cast<uint32_t*>(&l2);
}

// ---------------------------------------------------------------------------
// Fused fp32 -> bf16 hi/lo split
// ---------------------------------------------------------------------------
struct SplitArgs {
    const float* x[4];
    bf16* h[4];
    bf16* l[4];
};

__global__ __launch_bounds__(256) void split_multi(SplitArgs a, int n)
{
    int z = blockIdx.y;
    const float* x = a.x[z];
    bf16 *h = a.h[z], *l = a.l[z];
    int i = (blockIdx.x * 256 + threadIdx.x) * 4;
    if (i >= n) return;
    float4 v = *reinterpret_cast<const float4*>(x + i);
    uint32_t h01, l01, h23, l23;
    split_pack2(v.x, v.y, h01, l01);
    split_pack2(v.z, v.w, h23, l23);
    *reinterpret_cast<uint32_t*>(h + i)     = h01;
    *reinterpret_cast<uint32_t*>(h + i + 2) = h23;
    *reinterpret_cast<uint32_t*>(l + i)     = l01;
    *reinterpret_cast<uint32_t*>(l + i + 2) = l23;
}

// ---------------------------------------------------------------------------
// HMMA GEMM body: Y = A @ B^T, 3xBF16 split, 3-stage cp.async pipeline,
// single __syncthreads per K tile. CTA 128x128 (8 warps 64x32), BK=32.
// ---------------------------------------------------------------------------
#define GLD 40
#define GSTAGE_B 40960   // 4 tiles * 128 * GLD * 2 bytes

template<bool SPLIT_OUT>
__device__ __forceinline__ void gemm_body(
    const bf16* __restrict__ Ah, const bf16* __restrict__ Al,
    const bf16* __restrict__ Bh, const bf16* __restrict__ Bl,
    float* __restrict__ Yf, bf16* __restrict__ Yh, bf16* __restrict__ Yl,
    bf16* smg, float oscale)
{
    const int tid  = threadIdx.x;
    const int lane = tid & 31;
    const int wid  = tid >> 5;
    const int wm   = wid >> 2;
    const int wn   = wid & 3;
    const int bm   = blockIdx.y, bn = blockIdx.x;
    const uint32_t uS = smem_u32(smg);

    auto issue = [&](int ktile) {
        const int kt = ktile * 32;
        const uint32_t sbase = uS + (ktile % 3) * GSTAGE_B;
#pragma unroll
        for (int it = 0; it < 8; it++) {
            int idx  = tid + it * 256;
            int tile = idx >> 9;
            int rem  = idx & 511;
            int r    = rem >> 2, j = rem & 3;
            const bf16* gp = (tile == 0 ? Ah : tile == 1 ? Al : tile == 2 ? Bh : Bl);
            int row = ((tile < 2) ? bm : bn) * 128 + r;
            cp16(sbase + tile * 10240 + r * 80 + j * 16,
                 gp + (size_t)row * DM + kt + j * 8);
        }
    };

    float acc[4][4][4];
#pragma unroll
    for (int i = 0; i < 4; i++)
#pragma unroll
        for (int j = 0; j < 4; j++)
#pragma unroll
            for (int k = 0; k < 4; k++) acc[i][j][k] = 0.f;

    const int a_r  = (lane & 15), a_c = (lane >> 4) * 8;
    const int kn_r = (lane & 7) + ((lane >> 4) & 1) * 8;   // n-row within 16
    const int kn_c = ((lane >> 3) & 1) * 8;                // k-col half

    issue(0); CP_COMMIT();
    issue(1); CP_COMMIT();

    for (int kt = 0; kt < 32; kt++) {
        if (kt + 1 < 32) { CP_WAIT(1); } else { CP_WAIT(0); }
        __syncthreads();                     // stage kt visible; iter kt-1 readers done
        if (kt + 2 < 32) { issue(kt + 2); CP_COMMIT(); }

        const uint32_t st = uS + (kt % 3) * GSTAGE_B;
        const uint32_t uAh = st, uAl = st + 10240, uBh = st + 20480, uBl = st + 30720;

#pragma unroll
        for (int s = 0; s < 2; s++) {
            uint32_t ah[4][4], al[4][4], bh[4][2], bl[4][2];
#pragma unroll
            for (int i = 0; i < 4; i++) {
                uint32_t off = (uint32_t)(((wm * 64 + i * 16 + a_r) * GLD + s * 16 + a_c) * 2);
                ldsm_x4(ah[i], uAh + off);
                ldsm_x4(al[i], uAl + off);
            }
#pragma unroll
            for (int j2 = 0; j2 < 2; j2++) {   // x4: two n-fragments per ldsm
                uint32_t b4h[4], b4l[4];
                uint32_t off = (uint32_t)(((wn * 32 + j2 * 16 + kn_r) * GLD + s * 16 + kn_c) * 2);
                ldsm_x4(b4h, uBh + off);
                ldsm_x4(b4l, uBl + off);
                bh[2*j2][0] = b4h[0]; bh[2*j2][1] = b4h[1];
                bh[2*j2+1][0] = b4h[2]; bh[2*j2+1][1] = b4h[3];
                bl[2*j2][0] = b4l[0]; bl[2*j2][1] = b4l[1];
                bl[2*j2+1][0] = b4l[2]; bl[2*j2+1][1] = b4l[3];
            }
#pragma unroll
            for (int i = 0; i < 4; i++)
#pragma unroll
                for (int j = 0; j < 4; j++) {
                    mma_bf16(acc[i][j], ah[i], bh[j]);
                    mma_bf16(acc[i][j], ah[i], bl[j]);
                    mma_bf16(acc[i][j], al[i], bh[j]);
                }
        }
    }

    const int g = lane >> 2, t = lane & 3;
#pragma unroll
    for (int i = 0; i < 4; i++) {
        int row0 = bm * 128 + wm * 64 + i * 16 + g;
#pragma unroll
        for (int j = 0; j < 4; j++) {
            int col = bn * 128 + wn * 32 + j * 8 + 2 * t;
            if (SPLIT_OUT) {
                uint32_t hi, lo;
                split_pack2(acc[i][j][0] * oscale, acc[i][j][1] * oscale, hi, lo);
                *reinterpret_cast<uint32_t*>(Yh + (size_t)row0 * DM + col) = hi;
                *reinterpret_cast<uint32_t*>(Yl + (size_t)row0 * DM + col) = lo;
                split_pack2(acc[i][j][2] * oscale, acc[i][j][3] * oscale, hi, lo);
                *reinterpret_cast<uint32_t*>(Yh + (size_t)(row0 + 8) * DM + col) = hi;
                *reinterpret_cast<uint32_t*>(Yl + (size_t)(row0 + 8) * DM + col) = lo;
            } else {
                *reinterpret_cast<float2*>(Yf + (size_t)row0 * DM + col) =
                    make_float2(acc[i][j][0], acc[i][j][1]);
                *reinterpret_cast<float2*>(Yf + (size_t)(row0 + 8) * DM + col) =
                    make_float2(acc[i][j][2], acc[i][j][3]);
            }
        }
    }
}

struct QKVArgs {
    const bf16 *Ah[3], *Al[3], *Bh[3], *Bl[3];
    bf16 *Yh[3], *Yl[3];
    float sc[3];
};

__global__ __launch_bounds__(256) void gemm_qkv(QKVArgs a)
{
    extern __shared__ __align__(16) bf16 smg[];
    int z = blockIdx.z;
    gemm_body<true>(a.Ah[z], a.Al[z], a.Bh[z], a.Bl[z], nullptr, a.Yh[z], a.Yl[z], smg, a.sc[z]);
}

__global__ __launch_bounds__(256) void gemm_out(
    const bf16* __restrict__ Ah, const bf16* __restrict__ Al,
    const bf16* __restrict__ Bh, const bf16* __restrict__ Bl,
    float* __restrict__ Yf)
{
    extern __shared__ __align__(16) bf16 smg[];
    gemm_body<false>(Ah, Al, Bh, Bl, Yf, nullptr, nullptr, smg, 1.f);
}

// ---------------------------------------------------------------------------
// HMMA flash attention. Q fragments in registers; 3-stage KV pipeline with
// ONE __syncthreads per tile; K/V fragments via paired ldsm_x4.
// Scale 1/8 pre-folded into Q projection. 2 CTAs/SM.
// ---------------------------------------------------------------------------
#define FP 72            // pitch bf16 (144 B)
#define KV_STAGE 36864   // 4 arrays * 64 * FP * 2 B

__global__ __launch_bounds__(256, 2) void flash_mma(
    const bf16* __restrict__ Qh, const bf16* __restrict__ Ql,
    const bf16* __restrict__ Kh, const bf16* __restrict__ Kl,
    const bf16* __restrict__ Vh, const bf16* __restrict__ Vl,
    bf16* __restrict__ Oh, bf16* __restrict__ Ol)
{
    extern __shared__ __align__(16) bf16 sb[];
    const int tid  = threadIdx.x;
    const int lane = tid & 31;
    const int wid  = tid >> 5;
    const int g    = lane >> 2;
    const int t    = lane & 3;
    const int h    = blockIdx.x;
    const int qb   = blockIdx.y;
    const uint32_t uS = smem_u32(sb);

    const int a_r  = (lane & 15), a_c = (lane >> 4) * 8;
    const int kn_r = (lane & 7) + ((lane >> 4) & 1) * 8;   // K: n-row within 16
    const int kn_c = ((lane >> 3) & 1) * 8;                // K: k-col half
    const int vk_r = (lane & 7) + ((lane >> 3) & 1) * 8;   // V: k-row within 16
    const int vn_c = ((lane >> 4) & 1) * 8;                // V: n-col half

    // ---- stage Q into stage 0+1 space, load fragments to registers ----
#pragma unroll
    for (int it = 0; it < 8; it++) {
        int idx = tid + it * 256;               // 0..2047
        int arr = idx >> 10;                    // 0: Qh, 1: Ql
        int rem = idx & 1023;
        int r   = rem >> 3, j = rem & 7;
        const bf16* gp = arr ? Ql : Qh;
        cp16(uS + arr * 18432 + r * 144 + j * 16,
             gp + (size_t)(qb * 128 + r) * DM + h * DK + j * 8);
    }
    CP_COMMIT(); CP_WAIT(0);
    __syncthreads();

    uint32_t qfh[4][4], qfl[4][4];
#pragma unroll
    for (int kc = 0; kc < 4; kc++) {
        uint32_t aoff = (uint32_t)(((wid * 16 + a_r) * FP + kc * 16 + a_c) * 2);
        ldsm_x4(qfh[kc], uS + aoff);
        ldsm_x4(qfl[kc], uS + 18432 + aoff);
    }
    __syncthreads();   // Q reads done before KV overwrites

    auto issue_kv = [&](int kv) {
        const uint32_t base = uS + (kv % 3) * KV_STAGE;
#pragma unroll
        for (int it = 0; it < 8; it++) {
            int idx = tid + it * 256;
            int arr = idx >> 9;                 // Kh,Kl,Vh,Vl
            int rem = idx & 511;
            int r   = rem >> 3, j = rem & 7;
            const bf16* gp = (arr == 0 ? Kh : arr == 1 ? Kl : arr == 2 ? Vh : Vl);
            cp16(base + arr * 9216 + r * 144 + j * 16,
                 gp + (size_t)(kv * 64 + r) * DM + h * DK + j * 8);
        }
    };

    issue_kv(0); CP_COMMIT();
    issue_kv(1); CP_COMMIT();

    float o[8][4];
#pragma unroll
    for (int nf = 0; nf < 8; nf++)
#pragma unroll
        for (int k = 0; k < 4; k++) o[nf][k] = 0.f;
    float m0 = -1e30f, m1 = -1e30f, l0 = 0.f, l1 = 0.f;

    for (int kv = 0; kv < SEQ / 64; kv++) {
        if (kv + 1 < SEQ / 64) { CP_WAIT(1); } else { CP_WAIT(0); }
        __syncthreads();                        // stage kv ready; prev readers done
        if (kv + 2 < SEQ / 64) { issue_kv(kv + 2); CP_COMMIT(); }

        const uint32_t kb  = uS + (kv % 3) * KV_STAGE;
        const uint32_t uKh = kb, uKl = kb + 9216, uVh = kb + 18432, uVl = kb + 27648;

        // ---- S = Q @ K^T (3xBF16), paired x4 K loads ----
        float s[8][4];
#pragma unroll
        for (int nf = 0; nf < 8; nf++)
#pragma unroll
            for (int k = 0; k < 4; k++) s[nf][k] = 0.f;

#pragma unroll
        for (int kc = 0; kc < 4; kc++) {
#pragma unroll
            for (int nf2 = 0; nf2 < 4; nf2++) {
                uint32_t b4h[4], b4l[4];
                uint32_t boff = (uint32_t)(((nf2 * 16 + kn_r) * FP + kc * 16 + kn_c) * 2);
                ldsm_x4(b4h, uKh + boff);
                ldsm_x4(b4l, uKl + boff);
                mma_bf16(s[2*nf2],     qfh[kc], b4h);
                mma_bf16(s[2*nf2],     qfh[kc], b4l);
                mma_bf16(s[2*nf2],     qfl[kc], b4h);
                mma_bf16(s[2*nf2 + 1], qfh[kc], b4h + 2);
                mma_bf16(s[2*nf2 + 1], qfh[kc], b4l + 2);
                mma_bf16(s[2*nf2 + 1], qfl[kc], b4h + 2);
            }
        }

        // ---- online softmax (scale already folded into Q) ----
        float mx0 = -1e30f, mx1 = -1e30f;
#pragma unroll
        for (int nf = 0; nf < 8; nf++) {
            mx0 = fmaxf(mx0, fmaxf(s[nf][0], s[nf][1]));
            mx1 = fmaxf(mx1, fmaxf(s[nf][2], s[nf][3]));
        }
        mx0 = fmaxf(mx0, __shfl_xor_sync(0xffffffffu, mx0, 1));
        mx0 = fmaxf(mx0, __shfl_xor_sync(0xffffffffu, mx0, 2));
        mx1 = fmaxf(mx1, __shfl_xor_sync(0xffffffffu, mx1, 1));
        mx1 = fmaxf(mx1, __shfl_xor_sync(0xffffffffu, mx1, 2));

        float mn0 = fmaxf(m0, mx0), mn1 = fmaxf(m1, mx1);
        float c0 = __expf(m0 - mn0), c1 = __expf(m1 - mn1);
        float rs0 = 0.f, rs1 = 0.f;
#pragma unroll
        for (int nf = 0; nf < 8; nf++) {
            s[nf][0] = __expf(s[nf][0] - mn0);
            s[nf][1] = __expf(s[nf][1] - mn0);
            s[nf][2] = __expf(s[nf][2] - mn1);
            s[nf][3] = __expf(s[nf][3] - mn1);
            rs0 += s[nf][0] + s[nf][1];
            rs1 += s[nf][2] + s[nf][3];
        }
        rs0 += __shfl_xor_sync(0xffffffffu, rs0, 1);
        rs0 += __shfl_xor_sync(0xffffffffu, rs0, 2);
        rs1 += __shfl_xor_sync(0xffffffffu, rs1, 1);
        rs1 += __shfl_xor_sync(0xffffffffu, rs1, 2);
        l0 = l0 * c0 + rs0;
        l1 = l1 * c1 + rs1;
        m0 = mn0; m1 = mn1;
#pragma unroll
        for (int nf = 0; nf < 8; nf++) {
            o[nf][0] *= c0; o[nf][1] *= c0;
            o[nf][2] *= c1; o[nf][3] *= c1;
        }

        // ---- O += P @ V (3xBF16); paired x4 trans V loads ----
#pragma unroll
        for (int kc = 0; kc < 4; kc++) {
            uint32_t pah[4], pal[4];
            split_pack2(s[2 * kc][0],     s[2 * kc][1],     pah[0], pal[0]);
            split_pack2(s[2 * kc][2],     s[2 * kc][3],     pah[1], pal[1]);
            split_pack2(s[2 * kc + 1][0], s[2 * kc + 1][1], pah[2], pal[2]);
            split_pack2(s[2 * kc + 1][2], s[2 * kc + 1][3], pah[3], pal[3]);
#pragma unroll
            for (int nf2 = 0; nf2 < 4; nf2++) {
                uint32_t v4h[4], v4l[4];
                uint32_t voff = (uint32_t)(((kc * 16 + vk_r) * FP + nf2 * 16 + vn_c) * 2);
                ldsm_x4_trans(v4h, uVh + voff);
                ldsm_x4_trans(v4l, uVl + voff);
                mma_bf16(o[2*nf2],     pah, v4h);
                mma_bf16(o[2*nf2],     pah, v4l);
                mma_bf16(o[2*nf2],     pal, v4h);
                mma_bf16(o[2*nf2 + 1], pah, v4h + 2);
                mma_bf16(o[2*nf2 + 1], pah, v4l + 2);
                mma_bf16(o[2*nf2 + 1], pal, v4h + 2);
            }
        }
    }

    // ---- normalize + store as bf16 hi/lo ----
    float i0 = 1.f / l0, i1 = 1.f / l1;
    int row0 = qb * 128 + wid * 16 + g;
#pragma unroll
    for (int nf = 0; nf < 8; nf++) {
        int col = h * DK + nf * 8 + 2 * t;
        uint32_t hi, lo;
        split_pack2(o[nf][0] * i0, o[nf][1] * i0, hi, lo);
        *reinterpret_cast<uint32_t*>(Oh + (size_t)row0 * DM + col) = hi;
        *reinterpret_cast<uint32_t*>(Ol + (size_t)row0 * DM + col) = lo;
        split_pack2(o[nf][2] * i1, o[nf][3] * i1, hi, lo);
        *reinterpret_cast<uint32_t*>(Oh + (size_t)(row0 + 8) * DM + col) = hi;
        *reinterpret_cast<uint32_t*>(Ol + (size_t)(row0 + 8) * DM + col) = lo;
    }
}

// ---------------------------------------------------------------------------
extern "C" void kernel_launch(void* const* d_in, const int* in_sizes, int n_in,
                              void* d_out, int out_size)
{
    const float* query = (const float*)d_in[0];
    const float* key_t = (const float*)d_in[1];
    const float* value = (const float*)d_in[2];
    const float* w_q   = (const float*)d_in[3];
    const float* w_k   = (const float*)d_in[4];
    const float* w_v   = (const float*)d_in[5];
    const float* w_o   = (const float*)d_in[6];
    float* out = (float*)d_out;

    bf16 *xqh, *xql, *xkh, *xkl, *xvh, *xvl;
    bf16 *wqh, *wql, *wkh, *wkl, *wvh, *wvl, *woh, *wol;
    bf16 *Qh, *Ql, *Kh, *Kl, *Vh, *Vl, *oh, *ol;
    cudaGetSymbolAddress((void**)&xqh, g_xqh); cudaGetSymbolAddress((void**)&xql, g_xql);
    cudaGetSymbolAddress((void**)&xkh, g_xkh); cudaGetSymbolAddress((void**)&xkl, g_xkl);
    cudaGetSymbolAddress((void**)&xvh, g_xvh); cudaGetSymbolAddress((void**)&xvl, g_xvl);
    cudaGetSymbolAddress((void**)&wqh, g_wqh); cudaGetSymbolAddress((void**)&wql, g_wql);
    cudaGetSymbolAddress((void**)&wkh, g_wkh); cudaGetSymbolAddress((void**)&wkl, g_wkl);
    cudaGetSymbolAddress((void**)&wvh, g_wvh); cudaGetSymbolAddress((void**)&wvl, g_wvl);
    cudaGetSymbolAddress((void**)&woh, g_woh); cudaGetSymbolAddress((void**)&wol, g_wol);
    cudaGetSymbolAddress((void**)&Qh,  g_Qh);  cudaGetSymbolAddress((void**)&Ql,  g_Ql);
    cudaGetSymbolAddress((void**)&Kh,  g_Kh);  cudaGetSymbolAddress((void**)&Kl,  g_Kl);
    cudaGetSymbolAddress((void**)&Vh,  g_Vh);  cudaGetSymbolAddress((void**)&Vl,  g_Vl);
    cudaGetSymbolAddress((void**)&oh,  g_oh);  cudaGetSymbolAddress((void**)&ol,  g_ol);

    const int smem_gemm = 3 * GSTAGE_B;     // 122880 B
    const int smem_attn = 3 * KV_STAGE;     // 110592 B
    cudaFuncSetAttribute(gemm_qkv,  cudaFuncAttributeMaxDynamicSharedMemorySize, smem_gemm);
    cudaFuncSetAttribute(gemm_out,  cudaFuncAttributeMaxDynamicSharedMemorySize, smem_gemm);
    cudaFuncSetAttribute(flash_mma, cudaFuncAttributeMaxDynamicSharedMemorySize, smem_attn);

    const int nAct = SEQ * DM, nW = DM * DM;

    SplitArgs sa{};
    sa.x[0] = query; sa.h[0] = xqh; sa.l[0] = xql;
    sa.x[1] = key_t; sa.h[1] = xkh; sa.l[1] = xkl;
    sa.x[2] = value; sa.h[2] = xvh; sa.l[2] = xvl;
    split_multi<<<dim3(nAct / 1024, 3), 256>>>(sa, nAct);

    SplitArgs sw{};
    sw.x[0] = w_q; sw.h[0] = wqh; sw.l[0] = wql;
    sw.x[1] = w_k; sw.h[1] = wkh; sw.l[1] = wkl;
    sw.x[2] = w_v; sw.h[2] = wvh; sw.l[2] = wvl;
    sw.x[3] = w_o; sw.h[3] = woh; sw.l[3] = wol;
    split_multi<<<dim3(nW / 1024, 4), 256>>>(sw, nW);

    QKVArgs qa{};
    qa.Ah[0] = xqh; qa.Al[0] = xql; qa.Bh[0] = wqh; qa.Bl[0] = wql; qa.Yh[0] = Qh; qa.Yl[0] = Ql;
    qa.Ah[1] = xkh; qa.Al[1] = xkl; qa.Bh[1] = wkh; qa.Bl[1] = wkl; qa.Yh[1] = Kh; qa.Yl[1] = Kl;
    qa.Ah[2] = xvh; qa.Al[2] = xvl; qa.Bh[2] = wvh; qa.Bl[2] = wvl; qa.Yh[2] = Vh; qa.Yl[2] = Vl;
    qa.sc[0] = 0.125f; qa.sc[1] = 1.f; qa.sc[2] = 1.f;   // fold 1/sqrt(d_k) into Q
    gemm_qkv<<<dim3(DM / 128, SEQ / 128, 3), 256, smem_gemm>>>(qa);

    dim3 agrid(NH, SEQ / 128);   // (16, 32)
    flash_mma<<<agrid, 256, smem_attn>>>(Qh, Ql, Kh, Kl, Vh, Vl, oh, ol);

    gemm_out<<<dim3(DM / 128, SEQ / 128), 256, smem_gemm>>>(oh, ol, woh, wol, out);
}

// round 11
// speedup vs baseline: 1.0781x; 1.0781x over previous
#include <cuda_runtime.h>
#include <cuda_bf16.h>
#include <cstdint>
#include <math.h>

#define SEQ 4096
#define DM  1024
#define NH  16
#define DK  64

using bf16 = __nv_bfloat16;

// ---------------------------------------------------------------------------
// Scratch (__device__ globals: allocation-guard safe) — all bf16 hi/lo pairs
// ---------------------------------------------------------------------------
__device__ bf16 g_xqh[SEQ * DM], g_xql[SEQ * DM];
__device__ bf16 g_xkh[SEQ * DM], g_xkl[SEQ * DM];
__device__ bf16 g_xvh[SEQ * DM], g_xvl[SEQ * DM];
__device__ bf16 g_wqh[DM * DM],  g_wql[DM * DM];
__device__ bf16 g_wkh[DM * DM],  g_wkl[DM * DM];
__device__ bf16 g_wvh[DM * DM],  g_wvl[DM * DM];
__device__ bf16 g_woh[DM * DM],  g_wol[DM * DM];
__device__ bf16 g_Qh[SEQ * DM],  g_Ql[SEQ * DM];
__device__ bf16 g_Kh[SEQ * DM],  g_Kl[SEQ * DM];
__device__ bf16 g_Vh[SEQ * DM],  g_Vl[SEQ * DM];
__device__ bf16 g_oh[SEQ * DM],  g_ol[SEQ * DM];

// ---------------------------------------------------------------------------
// PTX helpers — valid at compute_103 (no tcgen05)
// ---------------------------------------------------------------------------
__device__ __forceinline__ uint32_t smem_u32(const void* p) {
    uint32_t a;
    asm("{ .reg .u64 t; cvta.to.shared.u64 t, %1; cvt.u32.u64 %0, t; }" : "=r"(a) : "l"(p));
    return a;
}
__device__ __forceinline__ void ldsm_x4(uint32_t* r, uint32_t addr) {
    asm volatile("ldmatrix.sync.aligned.m8n8.x4.shared.b16 {%0,%1,%2,%3}, [%4];"
                 : "=r"(r[0]), "=r"(r[1]), "=r"(r[2]), "=r"(r[3]) : "r"(addr));
}
__device__ __forceinline__ void ldsm_x4_trans(uint32_t* r, uint32_t addr) {
    asm volatile("ldmatrix.sync.aligned.m8n8.x4.trans.shared.b16 {%0,%1,%2,%3}, [%4];"
                 : "=r"(r[0]), "=r"(r[1]), "=r"(r[2]), "=r"(r[3]) : "r"(addr));
}
__device__ __forceinline__ void mma_bf16(float* c, const uint32_t* a, const uint32_t* b) {
    asm volatile(
        "mma.sync.aligned.m16n8k16.row.col.f32.bf16.bf16.f32 "
        "{%0,%1,%2,%3}, {%4,%5,%6,%7}, {%8,%9}, {%0,%1,%2,%3};"
        : "+f"(c[0]), "+f"(c[1]), "+f"(c[2]), "+f"(c[3])
        : "r"(a[0]), "r"(a[1]), "r"(a[2]), "r"(a[3]), "r"(b[0]), "r"(b[1]));
}
__device__ __forceinline__ void cp16(uint32_t s, const void* g) {
    asm volatile("cp.async.cg.shared.global [%0], [%1], 16;" :: "r"(s), "l"(g));
}
#define CP_COMMIT() asm volatile("cp.async.commit_group;" ::: "memory")
#define CP_WAIT(n)  asm volatile("cp.async.wait_group %0;" :: "n"(n) : "memory")

__device__ __forceinline__ void split_pack2(float x, float y, uint32_t& hi, uint32_t& lo) {
    __nv_bfloat162 h2 = __floats2bfloat162_rn(x, y);
    float rx = x - __bfloat162float(h2.x);
    float ry = y - __bfloat162float(h2.y);
    __nv_bfloat162 l2 = __floats2bfloat162_rn(rx, ry);
    hi = *reinterpret_cast<uint32_t*>(&h2);
    lo = *reinterpret_cast<uint32_t*>(&l2);
}

// ---------------------------------------------------------------------------
// Fused fp32 -> bf16 hi/lo split
// ---------------------------------------------------------------------------
struct SplitArgs {
    const float* x[4];
    bf16* h[4];
    bf16* l[4];
};

__global__ __launch_bounds__(256) void split_multi(SplitArgs a, int n)
{
    int z = blockIdx.y;
    const float* x = a.x[z];
    bf16 *h = a.h[z], *l = a.l[z];
    int i = (blockIdx.x * 256 + threadIdx.x) * 4;
    if (i >= n) return;
    float4 v = *reinterpret_cast<const float4*>(x + i);
    uint32_t h01, l01, h23, l23;
    split_pack2(v.x, v.y, h01, l01);
    split_pack2(v.z, v.w, h23, l23);
    *reinterpret_cast<uint32_t*>(h + i)     = h01;
    *reinterpret_cast<uint32_t*>(h + i + 2) = h23;
    *reinterpret_cast<uint32_t*>(l + i)     = l01;
    *reinterpret_cast<uint32_t*>(l + i + 2) = l23;
}

// ---------------------------------------------------------------------------
// HMMA GEMM body: Y = A @ B^T, 3xBF16 split. 2-stage cp.async pipeline,
// ONE __syncthreads per K tile, 2 CTAs/SM. CTA 128x128, BK=32.
// ---------------------------------------------------------------------------
#define GLD 40
#define GSTAGE_B 40960   // 4 tiles * 128 * GLD * 2 bytes

template<bool SPLIT_OUT>
__device__ __forceinline__ void gemm_body(
    const bf16* __restrict__ Ah, const bf16* __restrict__ Al,
    const bf16* __restrict__ Bh, const bf16* __restrict__ Bl,
    float* __restrict__ Yf, bf16* __restrict__ Yh, bf16* __restrict__ Yl,
    bf16* smg, float oscale)
{
    const int tid  = threadIdx.x;
    const int lane = tid & 31;
    const int wid  = tid >> 5;
    const int wm   = wid >> 2;
    const int wn   = wid & 3;
    const int bm   = blockIdx.y, bn = blockIdx.x;
    const uint32_t uS = smem_u32(smg);

    auto issue = [&](int ktile) {
        const int kt = ktile * 32;
        const uint32_t sbase = uS + (ktile & 1) * GSTAGE_B;
#pragma unroll
        for (int it = 0; it < 8; it++) {
            int idx  = tid + it * 256;
            int tile = idx >> 9;
            int rem  = idx & 511;
            int r    = rem >> 2, j = rem & 3;
            const bf16* gp = (tile == 0 ? Ah : tile == 1 ? Al : tile == 2 ? Bh : Bl);
            int row = ((tile < 2) ? bm : bn) * 128 + r;
            cp16(sbase + tile * 10240 + r * 80 + j * 16,
                 gp + (size_t)row * DM + kt + j * 8);
        }
    };

    float acc[4][4][4];
#pragma unroll
    for (int i = 0; i < 4; i++)
#pragma unroll
        for (int j = 0; j < 4; j++)
#pragma unroll
            for (int k = 0; k < 4; k++) acc[i][j][k] = 0.f;

    const int a_r  = (lane & 15), a_c = (lane >> 4) * 8;
    const int kn_r = (lane & 7) + ((lane >> 4) & 1) * 8;
    const int kn_c = ((lane >> 3) & 1) * 8;

    issue(0); CP_COMMIT();

    for (int kt = 0; kt < 32; kt++) {
        CP_WAIT(0);              // stage kt resident (only group in flight)
        __syncthreads();         // visible to all; prev-iter readers of other stage done
        if (kt + 1 < 32) { issue(kt + 1); CP_COMMIT(); }   // overlaps compute below

        const uint32_t st = uS + (kt & 1) * GSTAGE_B;
        const uint32_t uAh = st, uAl = st + 10240, uBh = st + 20480, uBl = st + 30720;

#pragma unroll
        for (int s = 0; s < 2; s++) {
            uint32_t ah[4][4], al[4][4], bh[4][2], bl[4][2];
#pragma unroll
            for (int i = 0; i < 4; i++) {
                uint32_t off = (uint32_t)(((wm * 64 + i * 16 + a_r) * GLD + s * 16 + a_c) * 2);
                ldsm_x4(ah[i], uAh + off);
                ldsm_x4(al[i], uAl + off);
            }
#pragma unroll
            for (int j2 = 0; j2 < 2; j2++) {
                uint32_t b4h[4], b4l[4];
                uint32_t off = (uint32_t)(((wn * 32 + j2 * 16 + kn_r) * GLD + s * 16 + kn_c) * 2);
                ldsm_x4(b4h, uBh + off);
                ldsm_x4(b4l, uBl + off);
                bh[2*j2][0] = b4h[0]; bh[2*j2][1] = b4h[1];
                bh[2*j2+1][0] = b4h[2]; bh[2*j2+1][1] = b4h[3];
                bl[2*j2][0] = b4l[0]; bl[2*j2][1] = b4l[1];
                bl[2*j2+1][0] = b4l[2]; bl[2*j2+1][1] = b4l[3];
            }
#pragma unroll
            for (int i = 0; i < 4; i++)
#pragma unroll
                for (int j = 0; j < 4; j++) {
                    mma_bf16(acc[i][j], ah[i], bh[j]);
                    mma_bf16(acc[i][j], ah[i], bl[j]);
                    mma_bf16(acc[i][j], al[i], bh[j]);
                }
        }
        __syncthreads();         // readers done before next iter's issue overwrites
    }

    const int g = lane >> 2, t = lane & 3;
#pragma unroll
    for (int i = 0; i < 4; i++) {
        int row0 = bm * 128 + wm * 64 + i * 16 + g;
#pragma unroll
        for (int j = 0; j < 4; j++) {
            int col = bn * 128 + wn * 32 + j * 8 + 2 * t;
            if (SPLIT_OUT) {
                uint32_t hi, lo;
                split_pack2(acc[i][j][0] * oscale, acc[i][j][1] * oscale, hi, lo);
                *reinterpret_cast<uint32_t*>(Yh + (size_t)row0 * DM + col) = hi;
                *reinterpret_cast<uint32_t*>(Yl + (size_t)row0 * DM + col) = lo;
                split_pack2(acc[i][j][2] * oscale, acc[i][j][3] * oscale, hi, lo);
                *reinterpret_cast<uint32_t*>(Yh + (size_t)(row0 + 8) * DM + col) = hi;
                *reinterpret_cast<uint32_t*>(Yl + (size_t)(row0 + 8) * DM + col) = lo;
            } else {
                *reinterpret_cast<float2*>(Yf + (size_t)row0 * DM + col) =
                    make_float2(acc[i][j][0], acc[i][j][1]);
                *reinterpret_cast<float2*>(Yf + (size_t)(row0 + 8) * DM + col) =
                    make_float2(acc[i][j][2], acc[i][j][3]);
            }
        }
    }
}

struct QKVArgs {
    const bf16 *Ah[3], *Al[3], *Bh[3], *Bl[3];
    bf16 *Yh[3], *Yl[3];
    float sc[3];
};

__global__ __launch_bounds__(256) void gemm_qkv(QKVArgs a)
{
    extern __shared__ __align__(16) bf16 smg[];
    int z = blockIdx.z;
    gemm_body<true>(a.Ah[z], a.Al[z], a.Bh[z], a.Bl[z], nullptr, a.Yh[z], a.Yl[z], smg, a.sc[z]);
}

__global__ __launch_bounds__(256) void gemm_out(
    const bf16* __restrict__ Ah, const bf16* __restrict__ Al,
    const bf16* __restrict__ Bh, const bf16* __restrict__ Bl,
    float* __restrict__ Yf)
{
    extern __shared__ __align__(16) bf16 smg[];
    gemm_body<false>(Ah, Al, Bh, Bl, Yf, nullptr, nullptr, smg, 1.f);
}

// ---------------------------------------------------------------------------
// HMMA flash attention. Q frags in registers; 3-stage KV pipeline.
// Softmax restructured: max-reduce up front, exp/pack INTERLEAVED with PV
// MMAs (row-sum deferred). exp2-domain: Q scale carries 0.125*log2(e).
// ---------------------------------------------------------------------------
#define FP 72            // pitch bf16 (144 B)
#define KV_STAGE 36864   // 4 arrays * 64 * FP * 2 B

__global__ __launch_bounds__(256, 2) void flash_mma(
    const bf16* __restrict__ Qh, const bf16* __restrict__ Ql,
    const bf16* __restrict__ Kh, const bf16* __restrict__ Kl,
    const bf16* __restrict__ Vh, const bf16* __restrict__ Vl,
    bf16* __restrict__ Oh, bf16* __restrict__ Ol)
{
    extern __shared__ __align__(16) bf16 sb[];
    const int tid  = threadIdx.x;
    const int lane = tid & 31;
    const int wid  = tid >> 5;
    const int g    = lane >> 2;
    const int t    = lane & 3;
    const int h    = blockIdx.x;
    const int qb   = blockIdx.y;
    const uint32_t uS = smem_u32(sb);

    const int a_r  = (lane & 15), a_c = (lane >> 4) * 8;
    const int kn_r = (lane & 7) + ((lane >> 4) & 1) * 8;
    const int kn_c = ((lane >> 3) & 1) * 8;
    const int vk_r = (lane & 7) + ((lane >> 3) & 1) * 8;
    const int vn_c = ((lane >> 4) & 1) * 8;

    // ---- stage Q, load fragments to registers ----
#pragma unroll
    for (int it = 0; it < 8; it++) {
        int idx = tid + it * 256;
        int arr = idx >> 10;
        int rem = idx & 1023;
        int r   = rem >> 3, j = rem & 7;
        const bf16* gp = arr ? Ql : Qh;
        cp16(uS + arr * 18432 + r * 144 + j * 16,
             gp + (size_t)(qb * 128 + r) * DM + h * DK + j * 8);
    }
    CP_COMMIT(); CP_WAIT(0);
    __syncthreads();

    uint32_t qfh[4][4], qfl[4][4];
#pragma unroll
    for (int kc = 0; kc < 4; kc++) {
        uint32_t aoff = (uint32_t)(((wid * 16 + a_r) * FP + kc * 16 + a_c) * 2);
        ldsm_x4(qfh[kc], uS + aoff);
        ldsm_x4(qfl[kc], uS + 18432 + aoff);
    }
    __syncthreads();

    auto issue_kv = [&](int kv) {
        const uint32_t base = uS + (kv % 3) * KV_STAGE;
#pragma unroll
        for (int it = 0; it < 8; it++) {
            int idx = tid + it * 256;
            int arr = idx >> 9;
            int rem = idx & 511;
            int r   = rem >> 3, j = rem & 7;
            const bf16* gp = (arr == 0 ? Kh : arr == 1 ? Kl : arr == 2 ? Vh : Vl);
            cp16(base + arr * 9216 + r * 144 + j * 16,
                 gp + (size_t)(kv * 64 + r) * DM + h * DK + j * 8);
        }
    };

    issue_kv(0); CP_COMMIT();
    issue_kv(1); CP_COMMIT();

    float o[8][4];
#pragma unroll
    for (int nf = 0; nf < 8; nf++)
#pragma unroll
        for (int k = 0; k < 4; k++) o[nf][k] = 0.f;
    float m0 = -1e30f, m1 = -1e30f, l0 = 0.f, l1 = 0.f;

    for (int kv = 0; kv < SEQ / 64; kv++) {
        if (kv + 1 < SEQ / 64) { CP_WAIT(1); } else { CP_WAIT(0); }
        __syncthreads();
        if (kv + 2 < SEQ / 64) { issue_kv(kv + 2); CP_COMMIT(); }

        const uint32_t kb  = uS + (kv % 3) * KV_STAGE;
        const uint32_t uKh = kb, uKl = kb + 9216, uVh = kb + 18432, uVl = kb + 27648;

        // ---- S = Q @ K^T (3xBF16), log2-domain scores ----
        float s[8][4];
#pragma unroll
        for (int nf = 0; nf < 8; nf++)
#pragma unroll
            for (int k = 0; k < 4; k++) s[nf][k] = 0.f;

#pragma unroll
        for (int kc = 0; kc < 4; kc++) {
#pragma unroll
            for (int nf2 = 0; nf2 < 4; nf2++) {
                uint32_t b4h[4], b4l[4];
                uint32_t boff = (uint32_t)(((nf2 * 16 + kn_r) * FP + kc * 16 + kn_c) * 2);
                ldsm_x4(b4h, uKh + boff);
                ldsm_x4(b4l, uKl + boff);
                mma_bf16(s[2*nf2],     qfh[kc], b4h);
                mma_bf16(s[2*nf2],     qfh[kc], b4l);
                mma_bf16(s[2*nf2],     qfl[kc], b4h);
                mma_bf16(s[2*nf2 + 1], qfh[kc], b4h + 2);
                mma_bf16(s[2*nf2 + 1], qfh[kc], b4l + 2);
                mma_bf16(s[2*nf2 + 1], qfl[kc], b4h + 2);
            }
        }

        // ---- max reduction only (short serial part) ----
        float mx0 = -1e30f, mx1 = -1e30f;
#pragma unroll
        for (int nf = 0; nf < 8; nf++) {
            mx0 = fmaxf(mx0, fmaxf(s[nf][0], s[nf][1]));
            mx1 = fmaxf(mx1, fmaxf(s[nf][2], s[nf][3]));
        }
        mx0 = fmaxf(mx0, __shfl_xor_sync(0xffffffffu, mx0, 1));
        mx0 = fmaxf(mx0, __shfl_xor_sync(0xffffffffu, mx0, 2));
        mx1 = fmaxf(mx1, __shfl_xor_sync(0xffffffffu, mx1, 1));
        mx1 = fmaxf(mx1, __shfl_xor_sync(0xffffffffu, mx1, 2));

        float mn0 = fmaxf(m0, mx0), mn1 = fmaxf(m1, mx1);
        float c0 = exp2f(m0 - mn0), c1 = exp2f(m1 - mn1);
        m0 = mn0; m1 = mn1;
#pragma unroll
        for (int nf = 0; nf < 8; nf++) {
            o[nf][0] *= c0; o[nf][1] *= c0;
            o[nf][2] *= c1; o[nf][3] *= c1;
        }
        float rs0 = 0.f, rs1 = 0.f;

        // ---- exp + pack + PV MMAs interleaved (MUFU overlaps tensor) ----
#pragma unroll
        for (int kc = 0; kc < 4; kc++) {
            float e00 = exp2f(s[2*kc][0]     - mn0);
            float e01 = exp2f(s[2*kc][1]     - mn0);
            float e02 = exp2f(s[2*kc][2]     - mn1);
            float e03 = exp2f(s[2*kc][3]     - mn1);
            float e10 = exp2f(s[2*kc + 1][0] - mn0);
            float e11 = exp2f(s[2*kc + 1][1] - mn0);
            float e12 = exp2f(s[2*kc + 1][2] - mn1);
            float e13 = exp2f(s[2*kc + 1][3] - mn1);
            rs0 += (e00 + e01) + (e10 + e11);
            rs1 += (e02 + e03) + (e12 + e13);

            uint32_t pah[4], pal[4];
            split_pack2(e00, e01, pah[0], pal[0]);
            split_pack2(e02, e03, pah[1], pal[1]);
            split_pack2(e10, e11, pah[2], pal[2]);
            split_pack2(e12, e13, pah[3], pal[3]);
#pragma unroll
            for (int nf2 = 0; nf2 < 4; nf2++) {
                uint32_t v4h[4], v4l[4];
                uint32_t voff = (uint32_t)(((kc * 16 + vk_r) * FP + nf2 * 16 + vn_c) * 2);
                ldsm_x4_trans(v4h, uVh + voff);
                ldsm_x4_trans(v4l, uVl + voff);
                mma_bf16(o[2*nf2],     pah, v4h);
                mma_bf16(o[2*nf2],     pah, v4l);
                mma_bf16(o[2*nf2],     pal, v4h);
                mma_bf16(o[2*nf2 + 1], pah, v4h + 2);
                mma_bf16(o[2*nf2 + 1], pah, v4l + 2);
                mma_bf16(o[2*nf2 + 1], pal, v4h + 2);
            }
        }
        rs0 += __shfl_xor_sync(0xffffffffu, rs0, 1);
        rs0 += __shfl_xor_sync(0xffffffffu, rs0, 2);
        rs1 += __shfl_xor_sync(0xffffffffu, rs1, 1);
        rs1 += __shfl_xor_sync(0xffffffffu, rs1, 2);
        l0 = l0 * c0 + rs0;
        l1 = l1 * c1 + rs1;
    }

    // ---- normalize + store as bf16 hi/lo ----
    float i0 = 1.f / l0, i1 = 1.f / l1;
    int row0 = qb * 128 + wid * 16 + g;
#pragma unroll
    for (int nf = 0; nf < 8; nf++) {
        int col = h * DK + nf * 8 + 2 * t;
        uint32_t hi, lo;
        split_pack2(o[nf][0] * i0, o[nf][1] * i0, hi, lo);
        *reinterpret_cast<uint32_t*>(Oh + (size_t)row0 * DM + col) = hi;
        *reinterpret_cast<uint32_t*>(Ol + (size_t)row0 * DM + col) = lo;
        split_pack2(o[nf][2] * i1, o[nf][3] * i1, hi, lo);
        *reinterpret_cast<uint32_t*>(Oh + (size_t)(row0 + 8) * DM + col) = hi;
        *reinterpret_cast<uint32_t*>(Ol + (size_t)(row0 + 8) * DM + col) = lo;
    }
}

// ---------------------------------------------------------------------------
extern "C" void kernel_launch(void* const* d_in, const int* in_sizes, int n_in,
                              void* d_out, int out_size)
{
    const float* query = (const float*)d_in[0];
    const float* key_t = (const float*)d_in[1];
    const float* value = (const float*)d_in[2];
    const float* w_q   = (const float*)d_in[3];
    const float* w_k   = (const float*)d_in[4];
    const float* w_v   = (const float*)d_in[5];
    const float* w_o   = (const float*)d_in[6];
    float* out = (float*)d_out;

    bf16 *xqh, *xql, *xkh, *xkl, *xvh, *xvl;
    bf16 *wqh, *wql, *wkh, *wkl, *wvh, *wvl, *woh, *wol;
    bf16 *Qh, *Ql, *Kh, *Kl, *Vh, *Vl, *oh, *ol;
    cudaGetSymbolAddress((void**)&xqh, g_xqh); cudaGetSymbolAddress((void**)&xql, g_xql);
    cudaGetSymbolAddress((void**)&xkh, g_xkh); cudaGetSymbolAddress((void**)&xkl, g_xkl);
    cudaGetSymbolAddress((void**)&xvh, g_xvh); cudaGetSymbolAddress((void**)&xvl, g_xvl);
    cudaGetSymbolAddress((void**)&wqh, g_wqh); cudaGetSymbolAddress((void**)&wql, g_wql);
    cudaGetSymbolAddress((void**)&wkh, g_wkh); cudaGetSymbolAddress((void**)&wkl, g_wkl);
    cudaGetSymbolAddress((void**)&wvh, g_wvh); cudaGetSymbolAddress((void**)&wvl, g_wvl);
    cudaGetSymbolAddress((void**)&woh, g_woh); cudaGetSymbolAddress((void**)&wol, g_wol);
    cudaGetSymbolAddress((void**)&Qh,  g_Qh);  cudaGetSymbolAddress((void**)&Ql,  g_Ql);
    cudaGetSymbolAddress((void**)&Kh,  g_Kh);  cudaGetSymbolAddress((void**)&Kl,  g_Kl);
    cudaGetSymbolAddress((void**)&Vh,  g_Vh);  cudaGetSymbolAddress((void**)&Vl,  g_Vl);
    cudaGetSymbolAddress((void**)&oh,  g_oh);  cudaGetSymbolAddress((void**)&ol,  g_ol);

    const int smem_gemm = 2 * GSTAGE_B;     // 81920 B  -> 2 CTAs/SM
    const int smem_attn = 3 * KV_STAGE;     // 110592 B -> 2 CTAs/SM
    cudaFuncSetAttribute(gemm_qkv,  cudaFuncAttributeMaxDynamicSharedMemorySize, smem_gemm);
    cudaFuncSetAttribute(gemm_out,  cudaFuncAttributeMaxDynamicSharedMemorySize, smem_gemm);
    cudaFuncSetAttribute(flash_mma, cudaFuncAttributeMaxDynamicSharedMemorySize, smem_attn);

    const int nAct = SEQ * DM, nW = DM * DM;

    SplitArgs sa{};
    sa.x[0] = query; sa.h[0] = xqh; sa.l[0] = xql;
    sa.x[1] = key_t; sa.h[1] = xkh; sa.l[1] = xkl;
    sa.x[2] = value; sa.h[2] = xvh; sa.l[2] = xvl;
    split_multi<<<dim3(nAct / 1024, 3), 256>>>(sa, nAct);

    SplitArgs sw{};
    sw.x[0] = w_q; sw.h[0] = wqh; sw.l[0] = wql;
    sw.x[1] = w_k; sw.h[1] = wkh; sw.l[1] = wkl;
    sw.x[2] = w_v; sw.h[2] = wvh; sw.l[2] = wvl;
    sw.x[3] = w_o; sw.h[3] = woh; sw.l[3] = wol;
    split_multi<<<dim3(nW / 1024, 4), 256>>>(sw, nW);

    QKVArgs qa{};
    qa.Ah[0] = xqh; qa.Al[0] = xql; qa.Bh[0] = wqh; qa.Bl[0] = wql; qa.Yh[0] = Qh; qa.Yl[0] = Ql;
    qa.Ah[1] = xkh; qa.Al[1] = xkl; qa.Bh[1] = wkh; qa.Bl[1] = wkl; qa.Yh[1] = Kh; qa.Yl[1] = Kl;
    qa.Ah[2] = xvh; qa.Al[2] = xvl; qa.Bh[2] = wvh; qa.Bl[2] = wvl; qa.Yh[2] = Vh; qa.Yl[2] = Vl;
    qa.sc[0] = 0.125f * 1.4426950408889634f;   // 1/sqrt(d_k) * log2(e) -> exp2 domain
    qa.sc[1] = 1.f; qa.sc[2] = 1.f;
    gemm_qkv<<<dim3(DM / 128, SEQ / 128, 3), 256, smem_gemm>>>(qa);

    dim3 agrid(NH, SEQ / 128);   // (16, 32)
    flash_mma<<<agrid, 256, smem_attn>>>(Qh, Ql, Kh, Kl, Vh, Vl, oh, ol);

    gemm_out<<<dim3(DM / 128, SEQ / 128), 256, smem_gemm>>>(oh, ol, woh, wol, out);
}

// round 12
// speedup vs baseline: 1.0844x; 1.0059x over previous
#include <cuda_runtime.h>
#include <cuda_bf16.h>
#include <cstdint>
#include <math.h>

#define SEQ 4096
#define DM  1024
#define NH  16
#define DK  64

using bf16 = __nv_bfloat16;

// ---------------------------------------------------------------------------
// Scratch (__device__ globals: allocation-guard safe) — all bf16 hi/lo pairs
// ---------------------------------------------------------------------------
__device__ bf16 g_xqh[SEQ * DM], g_xql[SEQ * DM];
__device__ bf16 g_xkh[SEQ * DM], g_xkl[SEQ * DM];
__device__ bf16 g_xvh[SEQ * DM], g_xvl[SEQ * DM];
__device__ bf16 g_wqh[DM * DM],  g_wql[DM * DM];
__device__ bf16 g_wkh[DM * DM],  g_wkl[DM * DM];
__device__ bf16 g_wvh[DM * DM],  g_wvl[DM * DM];
__device__ bf16 g_woh[DM * DM],  g_wol[DM * DM];
__device__ bf16 g_Qh[SEQ * DM],  g_Ql[SEQ * DM];
__device__ bf16 g_Kh[SEQ * DM],  g_Kl[SEQ * DM];
__device__ bf16 g_Vh[SEQ * DM],  g_Vl[SEQ * DM];
__device__ bf16 g_oh[SEQ * DM],  g_ol[SEQ * DM];

// ---------------------------------------------------------------------------
// PTX helpers — valid at compute_103 (no tcgen05)
// ---------------------------------------------------------------------------
__device__ __forceinline__ uint32_t smem_u32(const void* p) {
    uint32_t a;
    asm("{ .reg .u64 t; cvta.to.shared.u64 t, %1; cvt.u32.u64 %0, t; }" : "=r"(a) : "l"(p));
    return a;
}
__device__ __forceinline__ void ldsm_x4(uint32_t* r, uint32_t addr) {
    asm volatile("ldmatrix.sync.aligned.m8n8.x4.shared.b16 {%0,%1,%2,%3}, [%4];"
                 : "=r"(r[0]), "=r"(r[1]), "=r"(r[2]), "=r"(r[3]) : "r"(addr));
}
__device__ __forceinline__ void ldsm_x4_trans(uint32_t* r, uint32_t addr) {
    asm volatile("ldmatrix.sync.aligned.m8n8.x4.trans.shared.b16 {%0,%1,%2,%3}, [%4];"
                 : "=r"(r[0]), "=r"(r[1]), "=r"(r[2]), "=r"(r[3]) : "r"(addr));
}
__device__ __forceinline__ void mma_bf16(float* c, const uint32_t* a, const uint32_t* b) {
    asm volatile(
        "mma.sync.aligned.m16n8k16.row.col.f32.bf16.bf16.f32 "
        "{%0,%1,%2,%3}, {%4,%5,%6,%7}, {%8,%9}, {%0,%1,%2,%3};"
        : "+f"(c[0]), "+f"(c[1]), "+f"(c[2]), "+f"(c[3])
        : "r"(a[0]), "r"(a[1]), "r"(a[2]), "r"(a[3]), "r"(b[0]), "r"(b[1]));
}
__device__ __forceinline__ void cp16(uint32_t s, const void* g) {
    asm volatile("cp.async.cg.shared.global [%0], [%1], 16;" :: "r"(s), "l"(g));
}
#define CP_COMMIT() asm volatile("cp.async.commit_group;" ::: "memory")
#define CP_WAIT(n)  asm volatile("cp.async.wait_group %0;" :: "n"(n) : "memory")

__device__ __forceinline__ void split_pack2(float x, float y, uint32_t& hi, uint32_t& lo) {
    __nv_bfloat162 h2 = __floats2bfloat162_rn(x, y);
    float rx = x - __bfloat162float(h2.x);
    float ry = y - __bfloat162float(h2.y);
    __nv_bfloat162 l2 = __floats2bfloat162_rn(rx, ry);
    hi = *reinterpret_cast<uint32_t*>(&h2);
    lo = *reinterpret_cast<uint32_t*>(&l2);
}

// ---------------------------------------------------------------------------
// Fused fp32 -> bf16 hi/lo split
// ---------------------------------------------------------------------------
struct SplitArgs {
    const float* x[4];
    bf16* h[4];
    bf16* l[4];
};

__global__ __launch_bounds__(256) void split_multi(SplitArgs a, int n)
{
    int z = blockIdx.y;
    const float* x = a.x[z];
    bf16 *h = a.h[z], *l = a.l[z];
    int i = (blockIdx.x * 256 + threadIdx.x) * 4;
    if (i >= n) return;
    float4 v = *reinterpret_cast<const float4*>(x + i);
    uint32_t h01, l01, h23, l23;
    split_pack2(v.x, v.y, h01, l01);
    split_pack2(v.z, v.w, h23, l23);
    *reinterpret_cast<uint32_t*>(h + i)     = h01;
    *reinterpret_cast<uint32_t*>(h + i + 2) = h23;
    *reinterpret_cast<uint32_t*>(l + i)     = l01;
    *reinterpret_cast<uint32_t*>(l + i + 2) = l23;
}

// ---------------------------------------------------------------------------
// HMMA GEMM body: Y = A @ B^T, 3xBF16 split. 2-stage cp.async pipeline,
// ONE __syncthreads per K tile, forced 2 CTAs/SM. CTA 128x128, BK=32.
// ---------------------------------------------------------------------------
#define GLD 40
#define GSTAGE_B 40960   // 4 tiles * 128 * GLD * 2 bytes

template<bool SPLIT_OUT>
__device__ __forceinline__ void gemm_body(
    const bf16* __restrict__ Ah, const bf16* __restrict__ Al,
    const bf16* __restrict__ Bh, const bf16* __restrict__ Bl,
    float* __restrict__ Yf, bf16* __restrict__ Yh, bf16* __restrict__ Yl,
    bf16* smg, float oscale)
{
    const int tid  = threadIdx.x;
    const int lane = tid & 31;
    const int wid  = tid >> 5;
    const int wm   = wid >> 2;
    const int wn   = wid & 3;
    const int bm   = blockIdx.y, bn = blockIdx.x;
    const uint32_t uS = smem_u32(smg);

    auto issue = [&](int ktile) {
        const int kt = ktile * 32;
        const uint32_t sbase = uS + (ktile & 1) * GSTAGE_B;
#pragma unroll
        for (int it = 0; it < 8; it++) {
            int idx  = tid + it * 256;
            int tile = idx >> 9;
            int rem  = idx & 511;
            int r    = rem >> 2, j = rem & 3;
            const bf16* gp = (tile == 0 ? Ah : tile == 1 ? Al : tile == 2 ? Bh : Bl);
            int row = ((tile < 2) ? bm : bn) * 128 + r;
            cp16(sbase + tile * 10240 + r * 80 + j * 16,
                 gp + (size_t)row * DM + kt + j * 8);
        }
    };

    float acc[4][4][4];
#pragma unroll
    for (int i = 0; i < 4; i++)
#pragma unroll
        for (int j = 0; j < 4; j++)
#pragma unroll
            for (int k = 0; k < 4; k++) acc[i][j][k] = 0.f;

    const int a_r  = (lane & 15), a_c = (lane >> 4) * 8;
    const int kn_r = (lane & 7) + ((lane >> 4) & 1) * 8;
    const int kn_c = ((lane >> 3) & 1) * 8;

    issue(0); CP_COMMIT();

    for (int kt = 0; kt < 32; kt++) {
        CP_WAIT(0);              // stage kt resident
        __syncthreads();         // all warps past iter kt-1 compute -> safe to overwrite
        if (kt + 1 < 32) { issue(kt + 1); CP_COMMIT(); }   // overlaps compute below

        const uint32_t st = uS + (kt & 1) * GSTAGE_B;
        const uint32_t uAh = st, uAl = st + 10240, uBh = st + 20480, uBl = st + 30720;

#pragma unroll
        for (int s = 0; s < 2; s++) {
            uint32_t ah[4][4], al[4][4], bh[4][2], bl[4][2];
#pragma unroll
            for (int i = 0; i < 4; i++) {
                uint32_t off = (uint32_t)(((wm * 64 + i * 16 + a_r) * GLD + s * 16 + a_c) * 2);
                ldsm_x4(ah[i], uAh + off);
                ldsm_x4(al[i], uAl + off);
            }
#pragma unroll
            for (int j2 = 0; j2 < 2; j2++) {
                uint32_t b4h[4], b4l[4];
                uint32_t off = (uint32_t)(((wn * 32 + j2 * 16 + kn_r) * GLD + s * 16 + kn_c) * 2);
                ldsm_x4(b4h, uBh + off);
                ldsm_x4(b4l, uBl + off);
                bh[2*j2][0] = b4h[0]; bh[2*j2][1] = b4h[1];
                bh[2*j2+1][0] = b4h[2]; bh[2*j2+1][1] = b4h[3];
                bl[2*j2][0] = b4l[0]; bl[2*j2][1] = b4l[1];
                bl[2*j2+1][0] = b4l[2]; bl[2*j2+1][1] = b4l[3];
            }
#pragma unroll
            for (int i = 0; i < 4; i++)
#pragma unroll
                for (int j = 0; j < 4; j++) {
                    mma_bf16(acc[i][j], ah[i], bh[j]);
                    mma_bf16(acc[i][j], ah[i], bl[j]);
                    mma_bf16(acc[i][j], al[i], bh[j]);
                }
        }
    }

    const int g = lane >> 2, t = lane & 3;
#pragma unroll
    for (int i = 0; i < 4; i++) {
        int row0 = bm * 128 + wm * 64 + i * 16 + g;
#pragma unroll
        for (int j = 0; j < 4; j++) {
            int col = bn * 128 + wn * 32 + j * 8 + 2 * t;
            if (SPLIT_OUT) {
                uint32_t hi, lo;
                split_pack2(acc[i][j][0] * oscale, acc[i][j][1] * oscale, hi, lo);
                *reinterpret_cast<uint32_t*>(Yh + (size_t)row0 * DM + col) = hi;
                *reinterpret_cast<uint32_t*>(Yl + (size_t)row0 * DM + col) = lo;
                split_pack2(acc[i][j][2] * oscale, acc[i][j][3] * oscale, hi, lo);
                *reinterpret_cast<uint32_t*>(Yh + (size_t)(row0 + 8) * DM + col) = hi;
                *reinterpret_cast<uint32_t*>(Yl + (size_t)(row0 + 8) * DM + col) = lo;
            } else {
                *reinterpret_cast<float2*>(Yf + (size_t)row0 * DM + col) =
                    make_float2(acc[i][j][0], acc[i][j][1]);
                *reinterpret_cast<float2*>(Yf + (size_t)(row0 + 8) * DM + col) =
                    make_float2(acc[i][j][2], acc[i][j][3]);
            }
        }
    }
}

struct QKVArgs {
    const bf16 *Ah[3], *Al[3], *Bh[3], *Bl[3];
    bf16 *Yh[3], *Yl[3];
    float sc[3];
};

__global__ __launch_bounds__(256, 2) void gemm_qkv(QKVArgs a)
{
    extern __shared__ __align__(16) bf16 smg[];
    int z = blockIdx.z;
    gemm_body<true>(a.Ah[z], a.Al[z], a.Bh[z], a.Bl[z], nullptr, a.Yh[z], a.Yl[z], smg, a.sc[z]);
}

__global__ __launch_bounds__(256, 2) void gemm_out(
    const bf16* __restrict__ Ah, const bf16* __restrict__ Al,
    const bf16* __restrict__ Bh, const bf16* __restrict__ Bl,
    float* __restrict__ Yf)
{
    extern __shared__ __align__(16) bf16 smg[];
    gemm_body<false>(Ah, Al, Bh, Bl, Yf, nullptr, nullptr, smg, 1.f);
}

// ---------------------------------------------------------------------------
// HMMA flash attention. Q frags in registers; 3-stage KV pipeline.
// Max-reduce up front; exp/pack interleaved with PV MMAs. exp2 domain
// (Q projection carries 0.125*log2(e)). 2 CTAs/SM.
// ---------------------------------------------------------------------------
#define FP 72            // pitch bf16 (144 B)
#define KV_STAGE 36864   // 4 arrays * 64 * FP * 2 B

__global__ __launch_bounds__(256, 2) void flash_mma(
    const bf16* __restrict__ Qh, const bf16* __restrict__ Ql,
    const bf16* __restrict__ Kh, const bf16* __restrict__ Kl,
    const bf16* __restrict__ Vh, const bf16* __restrict__ Vl,
    bf16* __restrict__ Oh, bf16* __restrict__ Ol)
{
    extern __shared__ __align__(16) bf16 sb[];
    const int tid  = threadIdx.x;
    const int lane = tid & 31;
    const int wid  = tid >> 5;
    const int g    = lane >> 2;
    const int t    = lane & 3;
    const int h    = blockIdx.x;
    const int qb   = blockIdx.y;
    const uint32_t uS = smem_u32(sb);

    const int a_r  = (lane & 15), a_c = (lane >> 4) * 8;
    const int kn_r = (lane & 7) + ((lane >> 4) & 1) * 8;
    const int kn_c = ((lane >> 3) & 1) * 8;
    const int vk_r = (lane & 7) + ((lane >> 3) & 1) * 8;
    const int vn_c = ((lane >> 4) & 1) * 8;

    // ---- stage Q, load fragments to registers ----
#pragma unroll
    for (int it = 0; it < 8; it++) {
        int idx = tid + it * 256;
        int arr = idx >> 10;
        int rem = idx & 1023;
        int r   = rem >> 3, j = rem & 7;
        const bf16* gp = arr ? Ql : Qh;
        cp16(uS + arr * 18432 + r * 144 + j * 16,
             gp + (size_t)(qb * 128 + r) * DM + h * DK + j * 8);
    }
    CP_COMMIT(); CP_WAIT(0);
    __syncthreads();

    uint32_t qfh[4][4], qfl[4][4];
#pragma unroll
    for (int kc = 0; kc < 4; kc++) {
        uint32_t aoff = (uint32_t)(((wid * 16 + a_r) * FP + kc * 16 + a_c) * 2);
        ldsm_x4(qfh[kc], uS + aoff);
        ldsm_x4(qfl[kc], uS + 18432 + aoff);
    }
    __syncthreads();

    auto issue_kv = [&](int kv) {
        const uint32_t base = uS + (kv % 3) * KV_STAGE;
#pragma unroll
        for (int it = 0; it < 8; it++) {
            int idx = tid + it * 256;
            int arr = idx >> 9;
            int rem = idx & 511;
            int r   = rem >> 3, j = rem & 7;
            const bf16* gp = (arr == 0 ? Kh : arr == 1 ? Kl : arr == 2 ? Vh : Vl);
            cp16(base + arr * 9216 + r * 144 + j * 16,
                 gp + (size_t)(kv * 64 + r) * DM + h * DK + j * 8);
        }
    };

    issue_kv(0); CP_COMMIT();
    issue_kv(1); CP_COMMIT();

    float o[8][4];
#pragma unroll
    for (int nf = 0; nf < 8; nf++)
#pragma unroll
        for (int k = 0; k < 4; k++) o[nf][k] = 0.f;
    float m0 = -1e30f, m1 = -1e30f, l0 = 0.f, l1 = 0.f;

    for (int kv = 0; kv < SEQ / 64; kv++) {
        if (kv + 1 < SEQ / 64) { CP_WAIT(1); } else { CP_WAIT(0); }
        __syncthreads();
        if (kv + 2 < SEQ / 64) { issue_kv(kv + 2); CP_COMMIT(); }

        const uint32_t kb  = uS + (kv % 3) * KV_STAGE;
        const uint32_t uKh = kb, uKl = kb + 9216, uVh = kb + 18432, uVl = kb + 27648;

        // ---- S = Q @ K^T (3xBF16), log2-domain scores ----
        float s[8][4];
#pragma unroll
        for (int nf = 0; nf < 8; nf++)
#pragma unroll
            for (int k = 0; k < 4; k++) s[nf][k] = 0.f;

#pragma unroll
        for (int kc = 0; kc < 4; kc++) {
#pragma unroll
            for (int nf2 = 0; nf2 < 4; nf2++) {
                uint32_t b4h[4], b4l[4];
                uint32_t boff = (uint32_t)(((nf2 * 16 + kn_r) * FP + kc * 16 + kn_c) * 2);
                ldsm_x4(b4h, uKh + boff);
                ldsm_x4(b4l, uKl + boff);
                mma_bf16(s[2*nf2],     qfh[kc], b4h);
                mma_bf16(s[2*nf2],     qfh[kc], b4l);
                mma_bf16(s[2*nf2],     qfl[kc], b4h);
                mma_bf16(s[2*nf2 + 1], qfh[kc], b4h + 2);
                mma_bf16(s[2*nf2 + 1], qfh[kc], b4l + 2);
                mma_bf16(s[2*nf2 + 1], qfl[kc], b4h + 2);
            }
        }

        // ---- max reduction only ----
        float mx0 = -1e30f, mx1 = -1e30f;
#pragma unroll
        for (int nf = 0; nf < 8; nf++) {
            mx0 = fmaxf(mx0, fmaxf(s[nf][0], s[nf][1]));
            mx1 = fmaxf(mx1, fmaxf(s[nf][2], s[nf][3]));
        }
        mx0 = fmaxf(mx0, __shfl_xor_sync(0xffffffffu, mx0, 1));
        mx0 = fmaxf(mx0, __shfl_xor_sync(0xffffffffu, mx0, 2));
        mx1 = fmaxf(mx1, __shfl_xor_sync(0xffffffffu, mx1, 1));
        mx1 = fmaxf(mx1, __shfl_xor_sync(0xffffffffu, mx1, 2));

        float mn0 = fmaxf(m0, mx0), mn1 = fmaxf(m1, mx1);
        float c0 = exp2f(m0 - mn0), c1 = exp2f(m1 - mn1);
        m0 = mn0; m1 = mn1;
#pragma unroll
        for (int nf = 0; nf < 8; nf++) {
            o[nf][0] *= c0; o[nf][1] *= c0;
            o[nf][2] *= c1; o[nf][3] *= c1;
        }
        float rs0 = 0.f, rs1 = 0.f;

        // ---- exp + pack + PV MMAs interleaved ----
#pragma unroll
        for (int kc = 0; kc < 4; kc++) {
            float e00 = exp2f(s[2*kc][0]     - mn0);
            float e01 = exp2f(s[2*kc][1]     - mn0);
            float e02 = exp2f(s[2*kc][2]     - mn1);
            float e03 = exp2f(s[2*kc][3]     - mn1);
            float e10 = exp2f(s[2*kc + 1][0] - mn0);
            float e11 = exp2f(s[2*kc + 1][1] - mn0);
            float e12 = exp2f(s[2*kc + 1][2] - mn1);
            float e13 = exp2f(s[2*kc + 1][3] - mn1);
            rs0 += (e00 + e01) + (e10 + e11);
            rs1 += (e02 + e03) + (e12 + e13);

            uint32_t pah[4], pal[4];
            split_pack2(e00, e01, pah[0], pal[0]);
            split_pack2(e02, e03, pah[1], pal[1]);
            split_pack2(e10, e11, pah[2], pal[2]);
            split_pack2(e12, e13, pah[3], pal[3]);
#pragma unroll
            for (int nf2 = 0; nf2 < 4; nf2++) {
                uint32_t v4h[4], v4l[4];
                uint32_t voff = (uint32_t)(((kc * 16 + vk_r) * FP + nf2 * 16 + vn_c) * 2);
                ldsm_x4_trans(v4h, uVh + voff);
                ldsm_x4_trans(v4l, uVl + voff);
                mma_bf16(o[2*nf2],     pah, v4h);
                mma_bf16(o[2*nf2],     pah, v4l);
                mma_bf16(o[2*nf2],     pal, v4h);
                mma_bf16(o[2*nf2 + 1], pah, v4h + 2);
                mma_bf16(o[2*nf2 + 1], pah, v4l + 2);
                mma_bf16(o[2*nf2 + 1], pal, v4h + 2);
            }
        }
        rs0 += __shfl_xor_sync(0xffffffffu, rs0, 1);
        rs0 += __shfl_xor_sync(0xffffffffu, rs0, 2);
        rs1 += __shfl_xor_sync(0xffffffffu, rs1, 1);
        rs1 += __shfl_xor_sync(0xffffffffu, rs1, 2);
        l0 = l0 * c0 + rs0;
        l1 = l1 * c1 + rs1;
    }

    // ---- normalize + store as bf16 hi/lo ----
    float i0 = 1.f / l0, i1 = 1.f / l1;
    int row0 = qb * 128 + wid * 16 + g;
#pragma unroll
    for (int nf = 0; nf < 8; nf++) {
        int col = h * DK + nf * 8 + 2 * t;
        uint32_t hi, lo;
        split_pack2(o[nf][0] * i0, o[nf][1] * i0, hi, lo);
        *reinterpret_cast<uint32_t*>(Oh + (size_t)row0 * DM + col) = hi;
        *reinterpret_cast<uint32_t*>(Ol + (size_t)row0 * DM + col) = lo;
        split_pack2(o[nf][2] * i1, o[nf][3] * i1, hi, lo);
        *reinterpret_cast<uint32_t*>(Oh + (size_t)(row0 + 8) * DM + col) = hi;
        *reinterpret_cast<uint32_t*>(Ol + (size_t)(row0 + 8) * DM + col) = lo;
    }
}

// ---------------------------------------------------------------------------
extern "C" void kernel_launch(void* const* d_in, const int* in_sizes, int n_in,
                              void* d_out, int out_size)
{
    const float* query = (const float*)d_in[0];
    const float* key_t = (const float*)d_in[1];
    const float* value = (const float*)d_in[2];
    const float* w_q   = (const float*)d_in[3];
    const float* w_k   = (const float*)d_in[4];
    const float* w_v   = (const float*)d_in[5];
    const float* w_o   = (const float*)d_in[6];
    float* out = (float*)d_out;

    bf16 *xqh, *xql, *xkh, *xkl, *xvh, *xvl;
    bf16 *wqh, *wql, *wkh, *wkl, *wvh, *wvl, *woh, *wol;
    bf16 *Qh, *Ql, *Kh, *Kl, *Vh, *Vl, *oh, *ol;
    cudaGetSymbolAddress((void**)&xqh, g_xqh); cudaGetSymbolAddress((void**)&xql, g_xql);
    cudaGetSymbolAddress((void**)&xkh, g_xkh); cudaGetSymbolAddress((void**)&xkl, g_xkl);
    cudaGetSymbolAddress((void**)&xvh, g_xvh); cudaGetSymbolAddress((void**)&xvl, g_xvl);
    cudaGetSymbolAddress((void**)&wqh, g_wqh); cudaGetSymbolAddress((void**)&wql, g_wql);
    cudaGetSymbolAddress((void**)&wkh, g_wkh); cudaGetSymbolAddress((void**)&wkl, g_wkl);
    cudaGetSymbolAddress((void**)&wvh, g_wvh); cudaGetSymbolAddress((void**)&wvl, g_wvl);
    cudaGetSymbolAddress((void**)&woh, g_woh); cudaGetSymbolAddress((void**)&wol, g_wol);
    cudaGetSymbolAddress((void**)&Qh,  g_Qh);  cudaGetSymbolAddress((void**)&Ql,  g_Ql);
    cudaGetSymbolAddress((void**)&Kh,  g_Kh);  cudaGetSymbolAddress((void**)&Kl,  g_Kl);
    cudaGetSymbolAddress((void**)&Vh,  g_Vh);  cudaGetSymbolAddress((void**)&Vl,  g_Vl);
    cudaGetSymbolAddress((void**)&oh,  g_oh);  cudaGetSymbolAddress((void**)&ol,  g_ol);

    const int smem_gemm = 2 * GSTAGE_B;     // 81920 B  -> 2 CTAs/SM
    const int smem_attn = 3 * KV_STAGE;     // 110592 B -> 2 CTAs/SM
    cudaFuncSetAttribute(gemm_qkv,  cudaFuncAttributeMaxDynamicSharedMemorySize, smem_gemm);
    cudaFuncSetAttribute(gemm_out,  cudaFuncAttributeMaxDynamicSharedMemorySize, smem_gemm);
    cudaFuncSetAttribute(flash_mma, cudaFuncAttributeMaxDynamicSharedMemorySize, smem_attn);

    const int nAct = SEQ * DM, nW = DM * DM;

    SplitArgs sa{};
    sa.x[0] = query; sa.h[0] = xqh; sa.l[0] = xql;
    sa.x[1] = key_t; sa.h[1] = xkh; sa.l[1] = xkl;
    sa.x[2] = value; sa.h[2] = xvh; sa.l[2] = xvl;
    split_multi<<<dim3(nAct / 1024, 3), 256>>>(sa, nAct);

    SplitArgs sw{};
    sw.x[0] = w_q; sw.h[0] = wqh; sw.l[0] = wql;
    sw.x[1] = w_k; sw.h[1] = wkh; sw.l[1] = wkl;
    sw.x[2] = w_v; sw.h[2] = wvh; sw.l[2] = wvl;
    sw.x[3] = w_o; sw.h[3] = woh; sw.l[3] = wol;
    split_multi<<<dim3(nW / 1024, 4), 256>>>(sw, nW);

    QKVArgs qa{};
    qa.Ah[0] = xqh; qa.Al[0] = xql; qa.Bh[0] = wqh; qa.Bl[0] = wql; qa.Yh[0] = Qh; qa.Yl[0] = Ql;
    qa.Ah[1] = xkh; qa.Al[1] = xkl; qa.Bh[1] = wkh; qa.Bl[1] = wkl; qa.Yh[1] = Kh; qa.Yl[1] = Kl;
    qa.Ah[2] = xvh; qa.Al[2] = xvl; qa.Bh[2] = wvh; qa.Bl[2] = wvl; qa.Yh[2] = Vh; qa.Yl[2] = Vl;
    qa.sc[0] = 0.125f * 1.4426950408889634f;   // 1/sqrt(d_k) * log2(e) -> exp2 domain
    qa.sc[1] = 1.f; qa.sc[2] = 1.f;
    gemm_qkv<<<dim3(DM / 128, SEQ / 128, 3), 256, smem_gemm>>>(qa);

    dim3 agrid(NH, SEQ / 128);   // (16, 32)
    flash_mma<<<agrid, 256, smem_attn>>>(Qh, Ql, Kh, Kl, Vh, Vl, oh, ol);

    gemm_out<<<dim3(DM / 128, SEQ / 128), 256, smem_gemm>>>(oh, ol, woh, wol, out);
}

// round 13
// speedup vs baseline: 1.1970x; 1.1038x over previous
#include <cuda_runtime.h>
#include <cuda_fp16.h>
#include <cstdint>
#include <math.h>

#define SEQ 4096
#define DM  1024
#define NH  16
#define DK  64

using f16 = __half;

// ---------------------------------------------------------------------------
// Scratch (__device__ globals: allocation-guard safe) — fp16 hi/lo pairs
// ---------------------------------------------------------------------------
__device__ f16 g_xqh[SEQ * DM], g_xql[SEQ * DM];
__device__ f16 g_xkh[SEQ * DM], g_xkl[SEQ * DM];
__device__ f16 g_xvh[SEQ * DM], g_xvl[SEQ * DM];
__device__ f16 g_wqh[DM * DM],  g_wql[DM * DM];
__device__ f16 g_wkh[DM * DM],  g_wkl[DM * DM];
__device__ f16 g_wvh[DM * DM],  g_wvl[DM * DM];
__device__ f16 g_woh[DM * DM],  g_wol[DM * DM];
__device__ f16 g_Qh[SEQ * DM],  g_Ql[SEQ * DM];
__device__ f16 g_Kh[SEQ * DM],  g_Kl[SEQ * DM];
__device__ f16 g_Vh[SEQ * DM],  g_Vl[SEQ * DM];
__device__ f16 g_oh[SEQ * DM],  g_ol[SEQ * DM];

// ---------------------------------------------------------------------------
// PTX helpers — valid at compute_103 (no tcgen05)
// ---------------------------------------------------------------------------
__device__ __forceinline__ uint32_t smem_u32(const void* p) {
    uint32_t a;
    asm("{ .reg .u64 t; cvta.to.shared.u64 t, %1; cvt.u32.u64 %0, t; }" : "=r"(a) : "l"(p));
    return a;
}
__device__ __forceinline__ void ldsm_x4(uint32_t* r, uint32_t addr) {
    asm volatile("ldmatrix.sync.aligned.m8n8.x4.shared.b16 {%0,%1,%2,%3}, [%4];"
                 : "=r"(r[0]), "=r"(r[1]), "=r"(r[2]), "=r"(r[3]) : "r"(addr));
}
__device__ __forceinline__ void ldsm_x4_trans(uint32_t* r, uint32_t addr) {
    asm volatile("ldmatrix.sync.aligned.m8n8.x4.trans.shared.b16 {%0,%1,%2,%3}, [%4];"
                 : "=r"(r[0]), "=r"(r[1]), "=r"(r[2]), "=r"(r[3]) : "r"(addr));
}
__device__ __forceinline__ void mma_f16(float* c, const uint32_t* a, const uint32_t* b) {
    asm volatile(
        "mma.sync.aligned.m16n8k16.row.col.f32.f16.f16.f32 "
        "{%0,%1,%2,%3}, {%4,%5,%6,%7}, {%8,%9}, {%0,%1,%2,%3};"
        : "+f"(c[0]), "+f"(c[1]), "+f"(c[2]), "+f"(c[3])
        : "r"(a[0]), "r"(a[1]), "r"(a[2]), "r"(a[3]), "r"(b[0]), "r"(b[1]));
}
__device__ __forceinline__ void cp16(uint32_t s, const void* g) {
    asm volatile("cp.async.cg.shared.global [%0], [%1], 16;" :: "r"(s), "l"(g));
}
#define CP_COMMIT() asm volatile("cp.async.commit_group;" ::: "memory")
#define CP_WAIT(n)  asm volatile("cp.async.wait_group %0;" :: "n"(n) : "memory")

// fp16 hi/lo split of two fp32 values (residual captures down to 2^-22)
__device__ __forceinline__ void split_pack2(float x, float y, uint32_t& hi, uint32_t& lo) {
    __half2 h2 = __floats2half2_rn(x, y);
    float rx = x - __half2float(__low2half(h2));
    float ry = y - __half2float(__high2half(h2));
    __half2 l2 = __floats2half2_rn(rx, ry);
    hi = *reinterpret_cast<uint32_t*>(&h2);
    lo = *reinterpret_cast<uint32_t*>(&l2);
}
__device__ __forceinline__ uint32_t pack_f16x2(float x, float y) {
    __half2 h2 = __floats2half2_rn(x, y);
    return *reinterpret_cast<uint32_t*>(&h2);
}

// ---------------------------------------------------------------------------
// Fused fp32 -> fp16 hi/lo split
// ---------------------------------------------------------------------------
struct SplitArgs {
    const float* x[4];
    f16* h[4];
    f16* l[4];
};

__global__ __launch_bounds__(256) void split_multi(SplitArgs a, int n)
{
    int z = blockIdx.y;
    const float* x = a.x[z];
    f16 *h = a.h[z], *l = a.l[z];
    int i = (blockIdx.x * 256 + threadIdx.x) * 4;
    if (i >= n) return;
    float4 v = *reinterpret_cast<const float4*>(x + i);
    uint32_t h01, l01, h23, l23;
    split_pack2(v.x, v.y, h01, l01);
    split_pack2(v.z, v.w, h23, l23);
    *reinterpret_cast<uint32_t*>(h + i)     = h01;
    *reinterpret_cast<uint32_t*>(h + i + 2) = h23;
    *reinterpret_cast<uint32_t*>(l + i)     = l01;
    *reinterpret_cast<uint32_t*>(l + i + 2) = l23;
}

// ---------------------------------------------------------------------------
// HMMA GEMM body: Y = A @ B^T, 3xFP16 split. 2-stage cp.async pipeline,
// ONE __syncthreads per K tile, forced 2 CTAs/SM. CTA 128x128, BK=32.
// ---------------------------------------------------------------------------
#define GLD 40
#define GSTAGE_B 40960   // 4 tiles * 128 * GLD * 2 bytes

template<bool SPLIT_OUT>
__device__ __forceinline__ void gemm_body(
    const f16* __restrict__ Ah, const f16* __restrict__ Al,
    const f16* __restrict__ Bh, const f16* __restrict__ Bl,
    float* __restrict__ Yf, f16* __restrict__ Yh, f16* __restrict__ Yl,
    f16* smg, float oscale)
{
    const int tid  = threadIdx.x;
    const int lane = tid & 31;
    const int wid  = tid >> 5;
    const int wm   = wid >> 2;
    const int wn   = wid & 3;
    const int bm   = blockIdx.y, bn = blockIdx.x;
    const uint32_t uS = smem_u32(smg);

    auto issue = [&](int ktile) {
        const int kt = ktile * 32;
        const uint32_t sbase = uS + (ktile & 1) * GSTAGE_B;
#pragma unroll
        for (int it = 0; it < 8; it++) {
            int idx  = tid + it * 256;
            int tile = idx >> 9;
            int rem  = idx & 511;
            int r    = rem >> 2, j = rem & 3;
            const f16* gp = (tile == 0 ? Ah : tile == 1 ? Al : tile == 2 ? Bh : Bl);
            int row = ((tile < 2) ? bm : bn) * 128 + r;
            cp16(sbase + tile * 10240 + r * 80 + j * 16,
                 gp + (size_t)row * DM + kt + j * 8);
        }
    };

    float acc[4][4][4];
#pragma unroll
    for (int i = 0; i < 4; i++)
#pragma unroll
        for (int j = 0; j < 4; j++)
#pragma unroll
            for (int k = 0; k < 4; k++) acc[i][j][k] = 0.f;

    const int a_r  = (lane & 15), a_c = (lane >> 4) * 8;
    const int kn_r = (lane & 7) + ((lane >> 4) & 1) * 8;
    const int kn_c = ((lane >> 3) & 1) * 8;

    issue(0); CP_COMMIT();

    for (int kt = 0; kt < 32; kt++) {
        CP_WAIT(0);
        __syncthreads();
        if (kt + 1 < 32) { issue(kt + 1); CP_COMMIT(); }

        const uint32_t st = uS + (kt & 1) * GSTAGE_B;
        const uint32_t uAh = st, uAl = st + 10240, uBh = st + 20480, uBl = st + 30720;

#pragma unroll
        for (int s = 0; s < 2; s++) {
            uint32_t ah[4][4], al[4][4], bh[4][2], bl[4][2];
#pragma unroll
            for (int i = 0; i < 4; i++) {
                uint32_t off = (uint32_t)(((wm * 64 + i * 16 + a_r) * GLD + s * 16 + a_c) * 2);
                ldsm_x4(ah[i], uAh + off);
                ldsm_x4(al[i], uAl + off);
            }
#pragma unroll
            for (int j2 = 0; j2 < 2; j2++) {
                uint32_t b4h[4], b4l[4];
                uint32_t off = (uint32_t)(((wn * 32 + j2 * 16 + kn_r) * GLD + s * 16 + kn_c) * 2);
                ldsm_x4(b4h, uBh + off);
                ldsm_x4(b4l, uBl + off);
                bh[2*j2][0] = b4h[0]; bh[2*j2][1] = b4h[1];
                bh[2*j2+1][0] = b4h[2]; bh[2*j2+1][1] = b4h[3];
                bl[2*j2][0] = b4l[0]; bl[2*j2][1] = b4l[1];
                bl[2*j2+1][0] = b4l[2]; bl[2*j2+1][1] = b4l[3];
            }
#pragma unroll
            for (int i = 0; i < 4; i++)
#pragma unroll
                for (int j = 0; j < 4; j++) {
                    mma_f16(acc[i][j], ah[i], bh[j]);
                    mma_f16(acc[i][j], ah[i], bl[j]);
                    mma_f16(acc[i][j], al[i], bh[j]);
                }
        }
    }

    const int g = lane >> 2, t = lane & 3;
#pragma unroll
    for (int i = 0; i < 4; i++) {
        int row0 = bm * 128 + wm * 64 + i * 16 + g;
#pragma unroll
        for (int j = 0; j < 4; j++) {
            int col = bn * 128 + wn * 32 + j * 8 + 2 * t;
            if (SPLIT_OUT) {
                uint32_t hi, lo;
                split_pack2(acc[i][j][0] * oscale, acc[i][j][1] * oscale, hi, lo);
                *reinterpret_cast<uint32_t*>(Yh + (size_t)row0 * DM + col) = hi;
                *reinterpret_cast<uint32_t*>(Yl + (size_t)row0 * DM + col) = lo;
                split_pack2(acc[i][j][2] * oscale, acc[i][j][3] * oscale, hi, lo);
                *reinterpret_cast<uint32_t*>(Yh + (size_t)(row0 + 8) * DM + col) = hi;
                *reinterpret_cast<uint32_t*>(Yl + (size_t)(row0 + 8) * DM + col) = lo;
            } else {
                *reinterpret_cast<float2*>(Yf + (size_t)row0 * DM + col) =
                    make_float2(acc[i][j][0], acc[i][j][1]);
                *reinterpret_cast<float2*>(Yf + (size_t)(row0 + 8) * DM + col) =
                    make_float2(acc[i][j][2], acc[i][j][3]);
            }
        }
    }
}

struct QKVArgs {
    const f16 *Ah[3], *Al[3], *Bh[3], *Bl[3];
    f16 *Yh[3], *Yl[3];
    float sc[3];
};

__global__ __launch_bounds__(256, 2) void gemm_qkv(QKVArgs a)
{
    extern __shared__ __align__(16) f16 smg[];
    int z = blockIdx.z;
    gemm_body<true>(a.Ah[z], a.Al[z], a.Bh[z], a.Bl[z], nullptr, a.Yh[z], a.Yl[z], smg, a.sc[z]);
}

__global__ __launch_bounds__(256, 2) void gemm_out(
    const f16* __restrict__ Ah, const f16* __restrict__ Al,
    const f16* __restrict__ Bh, const f16* __restrict__ Bl,
    float* __restrict__ Yf)
{
    extern __shared__ __align__(16) f16 smg[];
    gemm_body<false>(Ah, Al, Bh, Bl, Yf, nullptr, nullptr, smg, 1.f);
}

// ---------------------------------------------------------------------------
// HMMA flash attention, fp16. QK^T = 3 fp16 MMA terms (error ~2^-22);
// PV = 2 terms with UNSPLIT fp16 P (Ph*Vh + Ph*Vl, P rounding 2^-11).
// Q frags in registers; 3-stage KV pipeline; exp2 domain. 2 CTAs/SM.
// ---------------------------------------------------------------------------
#define FP 72            // pitch f16 (144 B)
#define KV_STAGE 36864   // 4 arrays * 64 * FP * 2 B

__global__ __launch_bounds__(256, 2) void flash_mma(
    const f16* __restrict__ Qh, const f16* __restrict__ Ql,
    const f16* __restrict__ Kh, const f16* __restrict__ Kl,
    const f16* __restrict__ Vh, const f16* __restrict__ Vl,
    f16* __restrict__ Oh, f16* __restrict__ Ol)
{
    extern __shared__ __align__(16) f16 sb[];
    const int tid  = threadIdx.x;
    const int lane = tid & 31;
    const int wid  = tid >> 5;
    const int g    = lane >> 2;
    const int t    = lane & 3;
    const int h    = blockIdx.x;
    const int qb   = blockIdx.y;
    const uint32_t uS = smem_u32(sb);

    const int a_r  = (lane & 15), a_c = (lane >> 4) * 8;
    const int kn_r = (lane & 7) + ((lane >> 4) & 1) * 8;
    const int kn_c = ((lane >> 3) & 1) * 8;
    const int vk_r = (lane & 7) + ((lane >> 3) & 1) * 8;
    const int vn_c = ((lane >> 4) & 1) * 8;

    // ---- stage Q, load fragments to registers ----
#pragma unroll
    for (int it = 0; it < 8; it++) {
        int idx = tid + it * 256;
        int arr = idx >> 10;
        int rem = idx & 1023;
        int r   = rem >> 3, j = rem & 7;
        const f16* gp = arr ? Ql : Qh;
        cp16(uS + arr * 18432 + r * 144 + j * 16,
             gp + (size_t)(qb * 128 + r) * DM + h * DK + j * 8);
    }
    CP_COMMIT(); CP_WAIT(0);
    __syncthreads();

    uint32_t qfh[4][4], qfl[4][4];
#pragma unroll
    for (int kc = 0; kc < 4; kc++) {
        uint32_t aoff = (uint32_t)(((wid * 16 + a_r) * FP + kc * 16 + a_c) * 2);
        ldsm_x4(qfh[kc], uS + aoff);
        ldsm_x4(qfl[kc], uS + 18432 + aoff);
    }
    __syncthreads();

    auto issue_kv = [&](int kv) {
        const uint32_t base = uS + (kv % 3) * KV_STAGE;
#pragma unroll
        for (int it = 0; it < 8; it++) {
            int idx = tid + it * 256;
            int arr = idx >> 9;
            int rem = idx & 511;
            int r   = rem >> 3, j = rem & 7;
            const f16* gp = (arr == 0 ? Kh : arr == 1 ? Kl : arr == 2 ? Vh : Vl);
            cp16(base + arr * 9216 + r * 144 + j * 16,
                 gp + (size_t)(kv * 64 + r) * DM + h * DK + j * 8);
        }
    };

    issue_kv(0); CP_COMMIT();
    issue_kv(1); CP_COMMIT();

    float o[8][4];
#pragma unroll
    for (int nf = 0; nf < 8; nf++)
#pragma unroll
        for (int k = 0; k < 4; k++) o[nf][k] = 0.f;
    float m0 = -1e30f, m1 = -1e30f, l0 = 0.f, l1 = 0.f;

    for (int kv = 0; kv < SEQ / 64; kv++) {
        if (kv + 1 < SEQ / 64) { CP_WAIT(1); } else { CP_WAIT(0); }
        __syncthreads();
        if (kv + 2 < SEQ / 64) { issue_kv(kv + 2); CP_COMMIT(); }

        const uint32_t kb  = uS + (kv % 3) * KV_STAGE;
        const uint32_t uKh = kb, uKl = kb + 9216, uVh = kb + 18432, uVl = kb + 27648;

        // ---- S = Q @ K^T (3xFP16), log2-domain scores ----
        float s[8][4];
#pragma unroll
        for (int nf = 0; nf < 8; nf++)
#pragma unroll
            for (int k = 0; k < 4; k++) s[nf][k] = 0.f;

#pragma unroll
        for (int kc = 0; kc < 4; kc++) {
#pragma unroll
            for (int nf2 = 0; nf2 < 4; nf2++) {
                uint32_t b4h[4], b4l[4];
                uint32_t boff = (uint32_t)(((nf2 * 16 + kn_r) * FP + kc * 16 + kn_c) * 2);
                ldsm_x4(b4h, uKh + boff);
                ldsm_x4(b4l, uKl + boff);
                mma_f16(s[2*nf2],     qfh[kc], b4h);
                mma_f16(s[2*nf2],     qfh[kc], b4l);
                mma_f16(s[2*nf2],     qfl[kc], b4h);
                mma_f16(s[2*nf2 + 1], qfh[kc], b4h + 2);
                mma_f16(s[2*nf2 + 1], qfh[kc], b4l + 2);
                mma_f16(s[2*nf2 + 1], qfl[kc], b4h + 2);
            }
        }

        // ---- max reduction ----
        float mx0 = -1e30f, mx1 = -1e30f;
#pragma unroll
        for (int nf = 0; nf < 8; nf++) {
            mx0 = fmaxf(mx0, fmaxf(s[nf][0], s[nf][1]));
            mx1 = fmaxf(mx1, fmaxf(s[nf][2], s[nf][3]));
        }
        mx0 = fmaxf(mx0, __shfl_xor_sync(0xffffffffu, mx0, 1));
        mx0 = fmaxf(mx0, __shfl_xor_sync(0xffffffffu, mx0, 2));
        mx1 = fmaxf(mx1, __shfl_xor_sync(0xffffffffu, mx1, 1));
        mx1 = fmaxf(mx1, __shfl_xor_sync(0xffffffffu, mx1, 2));

        float mn0 = fmaxf(m0, mx0), mn1 = fmaxf(m1, mx1);
        float c0 = exp2f(m0 - mn0), c1 = exp2f(m1 - mn1);
        m0 = mn0; m1 = mn1;
#pragma unroll
        for (int nf = 0; nf < 8; nf++) {
            o[nf][0] *= c0; o[nf][1] *= c0;
            o[nf][2] *= c1; o[nf][3] *= c1;
        }
        float rs0 = 0.f, rs1 = 0.f;

        // ---- exp + cheap fp16 pack + PV MMAs interleaved (2 terms) ----
#pragma unroll
        for (int kc = 0; kc < 4; kc++) {
            float e00 = exp2f(s[2*kc][0]     - mn0);
            float e01 = exp2f(s[2*kc][1]     - mn0);
            float e02 = exp2f(s[2*kc][2]     - mn1);
            float e03 = exp2f(s[2*kc][3]     - mn1);
            float e10 = exp2f(s[2*kc + 1][0] - mn0);
            float e11 = exp2f(s[2*kc + 1][1] - mn0);
            float e12 = exp2f(s[2*kc + 1][2] - mn1);
            float e13 = exp2f(s[2*kc + 1][3] - mn1);
            rs0 += (e00 + e01) + (e10 + e11);
            rs1 += (e02 + e03) + (e12 + e13);

            uint32_t pa[4];
            pa[0] = pack_f16x2(e00, e01);
            pa[1] = pack_f16x2(e02, e03);
            pa[2] = pack_f16x2(e10, e11);
            pa[3] = pack_f16x2(e12, e13);
#pragma unroll
            for (int nf2 = 0; nf2 < 4; nf2++) {
                uint32_t v4h[4], v4l[4];
                uint32_t voff = (uint32_t)(((kc * 16 + vk_r) * FP + nf2 * 16 + vn_c) * 2);
                ldsm_x4_trans(v4h, uVh + voff);
                ldsm_x4_trans(v4l, uVl + voff);
                mma_f16(o[2*nf2],     pa, v4h);
                mma_f16(o[2*nf2],     pa, v4l);
                mma_f16(o[2*nf2 + 1], pa, v4h + 2);
                mma_f16(o[2*nf2 + 1], pa, v4l + 2);
            }
        }
        rs0 += __shfl_xor_sync(0xffffffffu, rs0, 1);
        rs0 += __shfl_xor_sync(0xffffffffu, rs0, 2);
        rs1 += __shfl_xor_sync(0xffffffffu, rs1, 1);
        rs1 += __shfl_xor_sync(0xffffffffu, rs1, 2);
        l0 = l0 * c0 + rs0;
        l1 = l1 * c1 + rs1;
    }

    // ---- normalize + store as fp16 hi/lo ----
    float i0 = 1.f / l0, i1 = 1.f / l1;
    int row0 = qb * 128 + wid * 16 + g;
#pragma unroll
    for (int nf = 0; nf < 8; nf++) {
        int col = h * DK + nf * 8 + 2 * t;
        uint32_t hi, lo;
        split_pack2(o[nf][0] * i0, o[nf][1] * i0, hi, lo);
        *reinterpret_cast<uint32_t*>(Oh + (size_t)row0 * DM + col) = hi;
        *reinterpret_cast<uint32_t*>(Ol + (size_t)row0 * DM + col) = lo;
        split_pack2(o[nf][2] * i1, o[nf][3] * i1, hi, lo);
        *reinterpret_cast<uint32_t*>(Oh + (size_t)(row0 + 8) * DM + col) = hi;
        *reinterpret_cast<uint32_t*>(Ol + (size_t)(row0 + 8) * DM + col) = lo;
    }
}

// ---------------------------------------------------------------------------
extern "C" void kernel_launch(void* const* d_in, const int* in_sizes, int n_in,
                              void* d_out, int out_size)
{
    const float* query = (const float*)d_in[0];
    const float* key_t = (const float*)d_in[1];
    const float* value = (const float*)d_in[2];
    const float* w_q   = (const float*)d_in[3];
    const float* w_k   = (const float*)d_in[4];
    const float* w_v   = (const float*)d_in[5];
    const float* w_o   = (const float*)d_in[6];
    float* out = (float*)d_out;

    f16 *xqh, *xql, *xkh, *xkl, *xvh, *xvl;
    f16 *wqh, *wql, *wkh, *wkl, *wvh, *wvl, *woh, *wol;
    f16 *Qh, *Ql, *Kh, *Kl, *Vh, *Vl, *oh, *ol;
    cudaGetSymbolAddress((void**)&xqh, g_xqh); cudaGetSymbolAddress((void**)&xql, g_xql);
    cudaGetSymbolAddress((void**)&xkh, g_xkh); cudaGetSymbolAddress((void**)&xkl, g_xkl);
    cudaGetSymbolAddress((void**)&xvh, g_xvh); cudaGetSymbolAddress((void**)&xvl, g_xvl);
    cudaGetSymbolAddress((void**)&wqh, g_wqh); cudaGetSymbolAddress((void**)&wql, g_wql);
    cudaGetSymbolAddress((void**)&wkh, g_wkh); cudaGetSymbolAddress((void**)&wkl, g_wkl);
    cudaGetSymbolAddress((void**)&wvh, g_wvh); cudaGetSymbolAddress((void**)&wvl, g_wvl);
    cudaGetSymbolAddress((void**)&woh, g_woh); cudaGetSymbolAddress((void**)&wol, g_wol);
    cudaGetSymbolAddress((void**)&Qh,  g_Qh);  cudaGetSymbolAddress((void**)&Ql,  g_Ql);
    cudaGetSymbolAddress((void**)&Kh,  g_Kh);  cudaGetSymbolAddress((void**)&Kl,  g_Kl);
    cudaGetSymbolAddress((void**)&Vh,  g_Vh);  cudaGetSymbolAddress((void**)&Vl,  g_Vl);
    cudaGetSymbolAddress((void**)&oh,  g_oh);  cudaGetSymbolAddress((void**)&ol,  g_ol);

    const int smem_gemm = 2 * GSTAGE_B;     // 81920 B
    const int smem_attn = 3 * KV_STAGE;     // 110592 B
    cudaFuncSetAttribute(gemm_qkv,  cudaFuncAttributeMaxDynamicSharedMemorySize, smem_gemm);
    cudaFuncSetAttribute(gemm_out,  cudaFuncAttributeMaxDynamicSharedMemorySize, smem_gemm);
    cudaFuncSetAttribute(flash_mma, cudaFuncAttributeMaxDynamicSharedMemorySize, smem_attn);

    const int nAct = SEQ * DM, nW = DM * DM;

    SplitArgs sa{};
    sa.x[0] = query; sa.h[0] = xqh; sa.l[0] = xql;
    sa.x[1] = key_t; sa.h[1] = xkh; sa.l[1] = xkl;
    sa.x[2] = value; sa.h[2] = xvh; sa.l[2] = xvl;
    split_multi<<<dim3(nAct / 1024, 3), 256>>>(sa, nAct);

    SplitArgs sw{};
    sw.x[0] = w_q; sw.h[0] = wqh; sw.l[0] = wql;
    sw.x[1] = w_k; sw.h[1] = wkh; sw.l[1] = wkl;
    sw.x[2] = w_v; sw.h[2] = wvh; sw.l[2] = wvl;
    sw.x[3] = w_o; sw.h[3] = woh; sw.l[3] = wol;
    split_multi<<<dim3(nW / 1024, 4), 256>>>(sw, nW);

    QKVArgs qa{};
    qa.Ah[0] = xqh; qa.Al[0] = xql; qa.Bh[0] = wqh; qa.Bl[0] = wql; qa.Yh[0] = Qh; qa.Yl[0] = Ql;
    qa.Ah[1] = xkh; qa.Al[1] = xkl; qa.Bh[1] = wkh; qa.Bl[1] = wkl; qa.Yh[1] = Kh; qa.Yl[1] = Kl;
    qa.Ah[2] = xvh; qa.Al[2] = xvl; qa.Bh[2] = wvh; qa.Bl[2] = wvl; qa.Yh[2] = Vh; qa.Yl[2] = Vl;
    qa.sc[0] = 0.125f * 1.4426950408889634f;   // 1/sqrt(d_k) * log2(e) -> exp2 domain
    qa.sc[1] = 1.f; qa.sc[2] = 1.f;
    gemm_qkv<<<dim3(DM / 128, SEQ / 128, 3), 256, smem_gemm>>>(qa);

    dim3 agrid(NH, SEQ / 128);   // (16, 32)
    flash_mma<<<agrid, 256, smem_attn>>>(Qh, Ql, Kh, Kl, Vh, Vl, oh, ol);

    gemm_out<<<dim3(DM / 128, SEQ / 128), 256, smem_gemm>>>(oh, ol, woh, wol, out);
}

// round 14
// speedup vs baseline: 1.3227x; 1.1051x over previous
#include <cuda_runtime.h>
#include <cuda_fp16.h>
#include <cstdint>
#include <math.h>

#define SEQ 4096
#define DM  1024
#define NH  16
#define DK  64

using f16 = __half;

// ---------------------------------------------------------------------------
// Scratch (__device__ globals: allocation-guard safe) — fp16 hi/lo pairs
// ---------------------------------------------------------------------------
__device__ f16 g_xqh[SEQ * DM], g_xql[SEQ * DM];
__device__ f16 g_xkh[SEQ * DM], g_xkl[SEQ * DM];
__device__ f16 g_xvh[SEQ * DM], g_xvl[SEQ * DM];
__device__ f16 g_wqh[DM * DM],  g_wql[DM * DM];
__device__ f16 g_wkh[DM * DM],  g_wkl[DM * DM];
__device__ f16 g_wvh[DM * DM],  g_wvl[DM * DM];
__device__ f16 g_woh[DM * DM],  g_wol[DM * DM];
__device__ f16 g_Qh[SEQ * DM],  g_Ql[SEQ * DM];
__device__ f16 g_Kh[SEQ * DM],  g_Kl[SEQ * DM];
__device__ f16 g_Vh[SEQ * DM],  g_Vl[SEQ * DM];
__device__ f16 g_oh[SEQ * DM],  g_ol[SEQ * DM];

// ---------------------------------------------------------------------------
// PTX helpers — valid at compute_103 (no tcgen05)
// ---------------------------------------------------------------------------
__device__ __forceinline__ uint32_t smem_u32(const void* p) {
    uint32_t a;
    asm("{ .reg .u64 t; cvta.to.shared.u64 t, %1; cvt.u32.u64 %0, t; }" : "=r"(a) : "l"(p));
    return a;
}
__device__ __forceinline__ void ldsm_x4(uint32_t* r, uint32_t addr) {
    asm volatile("ldmatrix.sync.aligned.m8n8.x4.shared.b16 {%0,%1,%2,%3}, [%4];"
                 : "=r"(r[0]), "=r"(r[1]), "=r"(r[2]), "=r"(r[3]) : "r"(addr));
}
__device__ __forceinline__ void ldsm_x4_trans(uint32_t* r, uint32_t addr) {
    asm volatile("ldmatrix.sync.aligned.m8n8.x4.trans.shared.b16 {%0,%1,%2,%3}, [%4];"
                 : "=r"(r[0]), "=r"(r[1]), "=r"(r[2]), "=r"(r[3]) : "r"(addr));
}
__device__ __forceinline__ void mma_f16(float* c, const uint32_t* a, const uint32_t* b) {
    asm volatile(
        "mma.sync.aligned.m16n8k16.row.col.f32.f16.f16.f32 "
        "{%0,%1,%2,%3}, {%4,%5,%6,%7}, {%8,%9}, {%0,%1,%2,%3};"
        : "+f"(c[0]), "+f"(c[1]), "+f"(c[2]), "+f"(c[3])
        : "r"(a[0]), "r"(a[1]), "r"(a[2]), "r"(a[3]), "r"(b[0]), "r"(b[1]));
}
__device__ __forceinline__ void cp16(uint32_t s, const void* g) {
    asm volatile("cp.async.cg.shared.global [%0], [%1], 16;" :: "r"(s), "l"(g));
}
#define CP_COMMIT() asm volatile("cp.async.commit_group;" ::: "memory")
#define CP_WAIT(n)  asm volatile("cp.async.wait_group %0;" :: "n"(n) : "memory")

// fp16 hi/lo split of two fp32 values (residual captures down to 2^-22)
__device__ __forceinline__ void split_pack2(float x, float y, uint32_t& hi, uint32_t& lo) {
    __half2 h2 = __floats2half2_rn(x, y);
    float rx = x - __half2float(__low2half(h2));
    float ry = y - __half2float(__high2half(h2));
    __half2 l2 = __floats2half2_rn(rx, ry);
    hi = *reinterpret_cast<uint32_t*>(&h2);
    lo = *reinterpret_cast<uint32_t*>(&l2);
}
__device__ __forceinline__ uint32_t pack_f16x2(float x, float y) {
    __half2 h2 = __floats2half2_rn(x, y);
    return *reinterpret_cast<uint32_t*>(&h2);
}

// ---------------------------------------------------------------------------
// Fused fp32 -> fp16 hi/lo split
// ---------------------------------------------------------------------------
struct SplitArgs {
    const float* x[4];
    f16* h[4];
    f16* l[4];
};

__global__ __launch_bounds__(256) void split_multi(SplitArgs a, int n)
{
    int z = blockIdx.y;
    const float* x = a.x[z];
    f16 *h = a.h[z], *l = a.l[z];
    int i = (blockIdx.x * 256 + threadIdx.x) * 4;
    if (i >= n) return;
    float4 v = *reinterpret_cast<const float4*>(x + i);
    uint32_t h01, l01, h23, l23;
    split_pack2(v.x, v.y, h01, l01);
    split_pack2(v.z, v.w, h23, l23);
    *reinterpret_cast<uint32_t*>(h + i)     = h01;
    *reinterpret_cast<uint32_t*>(h + i + 2) = h23;
    *reinterpret_cast<uint32_t*>(l + i)     = l01;
    *reinterpret_cast<uint32_t*>(l + i + 2) = l23;
}

// ---------------------------------------------------------------------------
// HMMA GEMM body: Y = A @ B^T, 3xFP16 split. 2-stage cp.async pipeline,
// ONE __syncthreads per K tile, forced 2 CTAs/SM. CTA 128x128, BK=32.
// ---------------------------------------------------------------------------
#define GLD 40
#define GSTAGE_B 40960   // 4 tiles * 128 * GLD * 2 bytes

template<bool SPLIT_OUT>
__device__ __forceinline__ void gemm_body(
    const f16* __restrict__ Ah, const f16* __restrict__ Al,
    const f16* __restrict__ Bh, const f16* __restrict__ Bl,
    float* __restrict__ Yf, f16* __restrict__ Yh, f16* __restrict__ Yl,
    f16* smg, float oscale)
{
    const int tid  = threadIdx.x;
    const int lane = tid & 31;
    const int wid  = tid >> 5;
    const int wm   = wid >> 2;
    const int wn   = wid & 3;
    const int bm   = blockIdx.y, bn = blockIdx.x;
    const uint32_t uS = smem_u32(smg);

    auto issue = [&](int ktile) {
        const int kt = ktile * 32;
        const uint32_t sbase = uS + (ktile & 1) * GSTAGE_B;
#pragma unroll
        for (int it = 0; it < 8; it++) {
            int idx  = tid + it * 256;
            int tile = idx >> 9;
            int rem  = idx & 511;
            int r    = rem >> 2, j = rem & 3;
            const f16* gp = (tile == 0 ? Ah : tile == 1 ? Al : tile == 2 ? Bh : Bl);
            int row = ((tile < 2) ? bm : bn) * 128 + r;
            cp16(sbase + tile * 10240 + r * 80 + j * 16,
                 gp + (size_t)row * DM + kt + j * 8);
        }
    };

    float acc[4][4][4];
#pragma unroll
    for (int i = 0; i < 4; i++)
#pragma unroll
        for (int j = 0; j < 4; j++)
#pragma unroll
            for (int k = 0; k < 4; k++) acc[i][j][k] = 0.f;

    const int a_r  = (lane & 15), a_c = (lane >> 4) * 8;
    const int kn_r = (lane & 7) + ((lane >> 4) & 1) * 8;
    const int kn_c = ((lane >> 3) & 1) * 8;

    issue(0); CP_COMMIT();

    for (int kt = 0; kt < 32; kt++) {
        CP_WAIT(0);
        __syncthreads();
        if (kt + 1 < 32) { issue(kt + 1); CP_COMMIT(); }

        const uint32_t st = uS + (kt & 1) * GSTAGE_B;
        const uint32_t uAh = st, uAl = st + 10240, uBh = st + 20480, uBl = st + 30720;

#pragma unroll
        for (int s = 0; s < 2; s++) {
            uint32_t ah[4][4], al[4][4], bh[4][2], bl[4][2];
#pragma unroll
            for (int i = 0; i < 4; i++) {
                uint32_t off = (uint32_t)(((wm * 64 + i * 16 + a_r) * GLD + s * 16 + a_c) * 2);
                ldsm_x4(ah[i], uAh + off);
                ldsm_x4(al[i], uAl + off);
            }
#pragma unroll
            for (int j2 = 0; j2 < 2; j2++) {
                uint32_t b4h[4], b4l[4];
                uint32_t off = (uint32_t)(((wn * 32 + j2 * 16 + kn_r) * GLD + s * 16 + kn_c) * 2);
                ldsm_x4(b4h, uBh + off);
                ldsm_x4(b4l, uBl + off);
                bh[2*j2][0] = b4h[0]; bh[2*j2][1] = b4h[1];
                bh[2*j2+1][0] = b4h[2]; bh[2*j2+1][1] = b4h[3];
                bl[2*j2][0] = b4l[0]; bl[2*j2][1] = b4l[1];
                bl[2*j2+1][0] = b4l[2]; bl[2*j2+1][1] = b4l[3];
            }
#pragma unroll
            for (int i = 0; i < 4; i++)
#pragma unroll
                for (int j = 0; j < 4; j++) {
                    mma_f16(acc[i][j], ah[i], bh[j]);
                    mma_f16(acc[i][j], ah[i], bl[j]);
                    mma_f16(acc[i][j], al[i], bh[j]);
                }
        }
    }

    const int g = lane >> 2, t = lane & 3;
#pragma unroll
    for (int i = 0; i < 4; i++) {
        int row0 = bm * 128 + wm * 64 + i * 16 + g;
#pragma unroll
        for (int j = 0; j < 4; j++) {
            int col = bn * 128 + wn * 32 + j * 8 + 2 * t;
            if (SPLIT_OUT) {
                uint32_t hi, lo;
                split_pack2(acc[i][j][0] * oscale, acc[i][j][1] * oscale, hi, lo);
                *reinterpret_cast<uint32_t*>(Yh + (size_t)row0 * DM + col) = hi;
                *reinterpret_cast<uint32_t*>(Yl + (size_t)row0 * DM + col) = lo;
                split_pack2(acc[i][j][2] * oscale, acc[i][j][3] * oscale, hi, lo);
                *reinterpret_cast<uint32_t*>(Yh + (size_t)(row0 + 8) * DM + col) = hi;
                *reinterpret_cast<uint32_t*>(Yl + (size_t)(row0 + 8) * DM + col) = lo;
            } else {
                *reinterpret_cast<float2*>(Yf + (size_t)row0 * DM + col) =
                    make_float2(acc[i][j][0], acc[i][j][1]);
                *reinterpret_cast<float2*>(Yf + (size_t)(row0 + 8) * DM + col) =
                    make_float2(acc[i][j][2], acc[i][j][3]);
            }
        }
    }
}

struct QKVArgs {
    const f16 *Ah[3], *Al[3], *Bh[3], *Bl[3];
    f16 *Yh[3], *Yl[3];
    float sc[3];
};

__global__ __launch_bounds__(256, 2) void gemm_qkv(QKVArgs a)
{
    extern __shared__ __align__(16) f16 smg[];
    int z = blockIdx.z;
    gemm_body<true>(a.Ah[z], a.Al[z], a.Bh[z], a.Bl[z], nullptr, a.Yh[z], a.Yl[z], smg, a.sc[z]);
}

__global__ __launch_bounds__(256, 2) void gemm_out(
    const f16* __restrict__ Ah, const f16* __restrict__ Al,
    const f16* __restrict__ Bh, const f16* __restrict__ Bl,
    float* __restrict__ Yf)
{
    extern __shared__ __align__(16) f16 smg[];
    gemm_body<false>(Ah, Al, Bh, Bl, Yf, nullptr, nullptr, smg, 1.f);
}

// ---------------------------------------------------------------------------
// HMMA flash attention, fp16.
// QK^T = 2 MMA terms: (Qh + Ql) @ Kh  — K unsplit (rounding ~2^-11 on S).
// PV   = 2 MMA terms: P @ (Vh + Vl)   — P unsplit fp16.
// KV stage = 3 arrays (Kh, Vh, Vl) = 27.6 KB; 3-stage pipeline; 2 CTAs/SM.
// ---------------------------------------------------------------------------
#define FP 72            // pitch f16 (144 B)
#define KV_STAGE 27648   // 3 arrays * 64 * FP * 2 B

__global__ __launch_bounds__(256, 2) void flash_mma(
    const f16* __restrict__ Qh, const f16* __restrict__ Ql,
    const f16* __restrict__ Kh,
    const f16* __restrict__ Vh, const f16* __restrict__ Vl,
    f16* __restrict__ Oh, f16* __restrict__ Ol)
{
    extern __shared__ __align__(16) f16 sb[];
    const int tid  = threadIdx.x;
    const int lane = tid & 31;
    const int wid  = tid >> 5;
    const int g    = lane >> 2;
    const int t    = lane & 3;
    const int h    = blockIdx.x;
    const int qb   = blockIdx.y;
    const uint32_t uS = smem_u32(sb);

    const int a_r  = (lane & 15), a_c = (lane >> 4) * 8;
    const int kn_r = (lane & 7) + ((lane >> 4) & 1) * 8;
    const int kn_c = ((lane >> 3) & 1) * 8;
    const int vk_r = (lane & 7) + ((lane >> 3) & 1) * 8;
    const int vn_c = ((lane >> 4) & 1) * 8;

    // ---- stage Q (hi/lo) into start of smem, load fragments to registers ----
#pragma unroll
    for (int it = 0; it < 8; it++) {
        int idx = tid + it * 256;
        int arr = idx >> 10;
        int rem = idx & 1023;
        int r   = rem >> 3, j = rem & 7;
        const f16* gp = arr ? Ql : Qh;
        cp16(uS + arr * 18432 + r * 144 + j * 16,
             gp + (size_t)(qb * 128 + r) * DM + h * DK + j * 8);
    }
    CP_COMMIT(); CP_WAIT(0);
    __syncthreads();

    uint32_t qfh[4][4], qfl[4][4];
#pragma unroll
    for (int kc = 0; kc < 4; kc++) {
        uint32_t aoff = (uint32_t)(((wid * 16 + a_r) * FP + kc * 16 + a_c) * 2);
        ldsm_x4(qfh[kc], uS + aoff);
        ldsm_x4(qfl[kc], uS + 18432 + aoff);
    }
    __syncthreads();   // Q reads done before KV stage 0/1 overwrite

    auto issue_kv = [&](int kv) {
        const uint32_t base = uS + (kv % 3) * KV_STAGE;
#pragma unroll
        for (int it = 0; it < 6; it++) {
            int idx = tid + it * 256;           // 0..1535
            int arr = idx >> 9;                 // 0:Kh 1:Vh 2:Vl
            int rem = idx & 511;
            int r   = rem >> 3, j = rem & 7;
            const f16* gp = (arr == 0 ? Kh : arr == 1 ? Vh : Vl);
            cp16(base + arr * 9216 + r * 144 + j * 16,
                 gp + (size_t)(kv * 64 + r) * DM + h * DK + j * 8);
        }
    };

    issue_kv(0); CP_COMMIT();
    issue_kv(1); CP_COMMIT();

    float o[8][4];
#pragma unroll
    for (int nf = 0; nf < 8; nf++)
#pragma unroll
        for (int k = 0; k < 4; k++) o[nf][k] = 0.f;
    float m0 = -1e30f, m1 = -1e30f, l0 = 0.f, l1 = 0.f;

    for (int kv = 0; kv < SEQ / 64; kv++) {
        if (kv + 1 < SEQ / 64) { CP_WAIT(1); } else { CP_WAIT(0); }
        __syncthreads();
        if (kv + 2 < SEQ / 64) { issue_kv(kv + 2); CP_COMMIT(); }

        const uint32_t kb  = uS + (kv % 3) * KV_STAGE;
        const uint32_t uKh = kb, uVh = kb + 9216, uVl = kb + 18432;

        // ---- S = (Qh + Ql) @ Kh^T (2 terms), log2-domain scores ----
        float s[8][4];
#pragma unroll
        for (int nf = 0; nf < 8; nf++)
#pragma unroll
            for (int k = 0; k < 4; k++) s[nf][k] = 0.f;

#pragma unroll
        for (int kc = 0; kc < 4; kc++) {
#pragma unroll
            for (int nf2 = 0; nf2 < 4; nf2++) {
                uint32_t b4h[4];
                uint32_t boff = (uint32_t)(((nf2 * 16 + kn_r) * FP + kc * 16 + kn_c) * 2);
                ldsm_x4(b4h, uKh + boff);
                mma_f16(s[2*nf2],     qfh[kc], b4h);
                mma_f16(s[2*nf2],     qfl[kc], b4h);
                mma_f16(s[2*nf2 + 1], qfh[kc], b4h + 2);
                mma_f16(s[2*nf2 + 1], qfl[kc], b4h + 2);
            }
        }

        // ---- max reduction ----
        float mx0 = -1e30f, mx1 = -1e30f;
#pragma unroll
        for (int nf = 0; nf < 8; nf++) {
            mx0 = fmaxf(mx0, fmaxf(s[nf][0], s[nf][1]));
            mx1 = fmaxf(mx1, fmaxf(s[nf][2], s[nf][3]));
        }
        mx0 = fmaxf(mx0, __shfl_xor_sync(0xffffffffu, mx0, 1));
        mx0 = fmaxf(mx0, __shfl_xor_sync(0xffffffffu, mx0, 2));
        mx1 = fmaxf(mx1, __shfl_xor_sync(0xffffffffu, mx1, 1));
        mx1 = fmaxf(mx1, __shfl_xor_sync(0xffffffffu, mx1, 2));

        float mn0 = fmaxf(m0, mx0), mn1 = fmaxf(m1, mx1);
        float c0 = exp2f(m0 - mn0), c1 = exp2f(m1 - mn1);
        m0 = mn0; m1 = mn1;
#pragma unroll
        for (int nf = 0; nf < 8; nf++) {
            o[nf][0] *= c0; o[nf][1] *= c0;
            o[nf][2] *= c1; o[nf][3] *= c1;
        }
        float rs0 = 0.f, rs1 = 0.f;

        // ---- exp + fp16 pack + PV MMAs interleaved (2 terms) ----
#pragma unroll
        for (int kc = 0; kc < 4; kc++) {
            float e00 = exp2f(s[2*kc][0]     - mn0);
            float e01 = exp2f(s[2*kc][1]     - mn0);
            float e02 = exp2f(s[2*kc][2]     - mn1);
            float e03 = exp2f(s[2*kc][3]     - mn1);
            float e10 = exp2f(s[2*kc + 1][0] - mn0);
            float e11 = exp2f(s[2*kc + 1][1] - mn0);
            float e12 = exp2f(s[2*kc + 1][2] - mn1);
            float e13 = exp2f(s[2*kc + 1][3] - mn1);
            rs0 += (e00 + e01) + (e10 + e11);
            rs1 += (e02 + e03) + (e12 + e13);

            uint32_t pa[4];
            pa[0] = pack_f16x2(e00, e01);
            pa[1] = pack_f16x2(e02, e03);
            pa[2] = pack_f16x2(e10, e11);
            pa[3] = pack_f16x2(e12, e13);
#pragma unroll
            for (int nf2 = 0; nf2 < 4; nf2++) {
                uint32_t v4h[4], v4l[4];
                uint32_t voff = (uint32_t)(((kc * 16 + vk_r) * FP + nf2 * 16 + vn_c) * 2);
                ldsm_x4_trans(v4h, uVh + voff);
                ldsm_x4_trans(v4l, uVl + voff);
                mma_f16(o[2*nf2],     pa, v4h);
                mma_f16(o[2*nf2],     pa, v4l);
                mma_f16(o[2*nf2 + 1], pa, v4h + 2);
                mma_f16(o[2*nf2 + 1], pa, v4l + 2);
            }
        }
        rs0 += __shfl_xor_sync(0xffffffffu, rs0, 1);
        rs0 += __shfl_xor_sync(0xffffffffu, rs0, 2);
        rs1 += __shfl_xor_sync(0xffffffffu, rs1, 1);
        rs1 += __shfl_xor_sync(0xffffffffu, rs1, 2);
        l0 = l0 * c0 + rs0;
        l1 = l1 * c1 + rs1;
    }

    // ---- normalize + store as fp16 hi/lo ----
    float i0 = 1.f / l0, i1 = 1.f / l1;
    int row0 = qb * 128 + wid * 16 + g;
#pragma unroll
    for (int nf = 0; nf < 8; nf++) {
        int col = h * DK + nf * 8 + 2 * t;
        uint32_t hi, lo;
        split_pack2(o[nf][0] * i0, o[nf][1] * i0, hi, lo);
        *reinterpret_cast<uint32_t*>(Oh + (size_t)row0 * DM + col) = hi;
        *reinterpret_cast<uint32_t*>(Ol + (size_t)row0 * DM + col) = lo;
        split_pack2(o[nf][2] * i1, o[nf][3] * i1, hi, lo);
        *reinterpret_cast<uint32_t*>(Oh + (size_t)(row0 + 8) * DM + col) = hi;
        *reinterpret_cast<uint32_t*>(Ol + (size_t)(row0 + 8) * DM + col) = lo;
    }
}

// ---------------------------------------------------------------------------
extern "C" void kernel_launch(void* const* d_in, const int* in_sizes, int n_in,
                              void* d_out, int out_size)
{
    const float* query = (const float*)d_in[0];
    const float* key_t = (const float*)d_in[1];
    const float* value = (const float*)d_in[2];
    const float* w_q   = (const float*)d_in[3];
    const float* w_k   = (const float*)d_in[4];
    const float* w_v   = (const float*)d_in[5];
    const float* w_o   = (const float*)d_in[6];
    float* out = (float*)d_out;

    f16 *xqh, *xql, *xkh, *xkl, *xvh, *xvl;
    f16 *wqh, *wql, *wkh, *wkl, *wvh, *wvl, *woh, *wol;
    f16 *Qh, *Ql, *Kh, *Kl, *Vh, *Vl, *oh, *ol;
    cudaGetSymbolAddress((void**)&xqh, g_xqh); cudaGetSymbolAddress((void**)&xql, g_xql);
    cudaGetSymbolAddress((void**)&xkh, g_xkh); cudaGetSymbolAddress((void**)&xkl, g_xkl);
    cudaGetSymbolAddress((void**)&xvh, g_xvh); cudaGetSymbolAddress((void**)&xvl, g_xvl);
    cudaGetSymbolAddress((void**)&wqh, g_wqh); cudaGetSymbolAddress((void**)&wql, g_wql);
    cudaGetSymbolAddress((void**)&wkh, g_wkh); cudaGetSymbolAddress((void**)&wkl, g_wkl);
    cudaGetSymbolAddress((void**)&wvh, g_wvh); cudaGetSymbolAddress((void**)&wvl, g_wvl);
    cudaGetSymbolAddress((void**)&woh, g_woh); cudaGetSymbolAddress((void**)&wol, g_wol);
    cudaGetSymbolAddress((void**)&Qh,  g_Qh);  cudaGetSymbolAddress((void**)&Ql,  g_Ql);
    cudaGetSymbolAddress((void**)&Kh,  g_Kh);  cudaGetSymbolAddress((void**)&Kl,  g_Kl);
    cudaGetSymbolAddress((void**)&Vh,  g_Vh);  cudaGetSymbolAddress((void**)&Vl,  g_Vl);
    cudaGetSymbolAddress((void**)&oh,  g_oh);  cudaGetSymbolAddress((void**)&ol,  g_ol);

    const int smem_gemm = 2 * GSTAGE_B;     // 81920 B
    const int smem_attn = 3 * KV_STAGE;     // 82944 B
    cudaFuncSetAttribute(gemm_qkv,  cudaFuncAttributeMaxDynamicSharedMemorySize, smem_gemm);
    cudaFuncSetAttribute(gemm_out,  cudaFuncAttributeMaxDynamicSharedMemorySize, smem_gemm);
    cudaFuncSetAttribute(flash_mma, cudaFuncAttributeMaxDynamicSharedMemorySize, smem_attn);

    const int nAct = SEQ * DM, nW = DM * DM;

    SplitArgs sa{};
    sa.x[0] = query; sa.h[0] = xqh; sa.l[0] = xql;
    sa.x[1] = key_t; sa.h[1] = xkh; sa.l[1] = xkl;
    sa.x[2] = value; sa.h[2] = xvh; sa.l[2] = xvl;
    split_multi<<<dim3(nAct / 1024, 3), 256>>>(sa, nAct);

    SplitArgs sw{};
    sw.x[0] = w_q; sw.h[0] = wqh; sw.l[0] = wql;
    sw.x[1] = w_k; sw.h[1] = wkh; sw.l[1] = wkl;
    sw.x[2] = w_v; sw.h[2] = wvh; sw.l[2] = wvl;
    sw.x[3] = w_o; sw.h[3] = woh; sw.l[3] = wol;
    split_multi<<<dim3(nW / 1024, 4), 256>>>(sw, nW);

    QKVArgs qa{};
    qa.Ah[0] = xqh; qa.Al[0] = xql; qa.Bh[0] = wqh; qa.Bl[0] = wql; qa.Yh[0] = Qh; qa.Yl[0] = Ql;
    qa.Ah[1] = xkh; qa.Al[1] = xkl; qa.Bh[1] = wkh; qa.Bl[1] = wkl; qa.Yh[1] = Kh; qa.Yl[1] = Kl;
    qa.Ah[2] = xvh; qa.Al[2] = xvl; qa.Bh[2] = wvh; qa.Bl[2] = wvl; qa.Yh[2] = Vh; qa.Yl[2] = Vl;
    qa.sc[0] = 0.125f * 1.4426950408889634f;   // 1/sqrt(d_k) * log2(e) -> exp2 domain
    qa.sc[1] = 1.f; qa.sc[2] = 1.f;
    gemm_qkv<<<dim3(DM / 128, SEQ / 128, 3), 256, smem_gemm>>>(qa);

    dim3 agrid(NH, SEQ / 128);   // (16, 32)
    flash_mma<<<agrid, 256, smem_attn>>>(Qh, Ql, Kh, Vh, Vl, oh, ol);

    gemm_out<<<dim3(DM / 128, SEQ / 128), 256, smem_gemm>>>(oh, ol, woh, wol, out);
}

// round 15
// speedup vs baseline: 1.3330x; 1.0078x over previous
#include <cuda_runtime.h>
#include <cuda_fp16.h>
#include <cstdint>
#include <math.h>

#define SEQ 4096
#define DM  1024
#define NH  16
#define DK  64

using f16 = __half;

// ---------------------------------------------------------------------------
// Scratch (__device__ globals: allocation-guard safe) — fp16 hi/lo pairs
// ---------------------------------------------------------------------------
__device__ f16 g_xqh[SEQ * DM], g_xql[SEQ * DM];
__device__ f16 g_xkh[SEQ * DM], g_xkl[SEQ * DM];
__device__ f16 g_xvh[SEQ * DM], g_xvl[SEQ * DM];
__device__ f16 g_wqh[DM * DM],  g_wql[DM * DM];
__device__ f16 g_wkh[DM * DM],  g_wkl[DM * DM];
__device__ f16 g_wvh[DM * DM],  g_wvl[DM * DM];
__device__ f16 g_woh[DM * DM],  g_wol[DM * DM];
__device__ f16 g_Qh[SEQ * DM],  g_Ql[SEQ * DM];
__device__ f16 g_Kh[SEQ * DM],  g_Kl[SEQ * DM];
__device__ f16 g_Vh[SEQ * DM],  g_Vl[SEQ * DM];
__device__ f16 g_oh[SEQ * DM],  g_ol[SEQ * DM];

// ---------------------------------------------------------------------------
// PTX helpers — valid at compute_103 (no tcgen05)
// ---------------------------------------------------------------------------
__device__ __forceinline__ uint32_t smem_u32(const void* p) {
    uint32_t a;
    asm("{ .reg .u64 t; cvta.to.shared.u64 t, %1; cvt.u32.u64 %0, t; }" : "=r"(a) : "l"(p));
    return a;
}
__device__ __forceinline__ void ldsm_x4(uint32_t* r, uint32_t addr) {
    asm volatile("ldmatrix.sync.aligned.m8n8.x4.shared.b16 {%0,%1,%2,%3}, [%4];"
                 : "=r"(r[0]), "=r"(r[1]), "=r"(r[2]), "=r"(r[3]) : "r"(addr));
}
__device__ __forceinline__ void ldsm_x4_trans(uint32_t* r, uint32_t addr) {
    asm volatile("ldmatrix.sync.aligned.m8n8.x4.trans.shared.b16 {%0,%1,%2,%3}, [%4];"
                 : "=r"(r[0]), "=r"(r[1]), "=r"(r[2]), "=r"(r[3]) : "r"(addr));
}
__device__ __forceinline__ void mma_f16(float* c, const uint32_t* a, const uint32_t* b) {
    asm volatile(
        "mma.sync.aligned.m16n8k16.row.col.f32.f16.f16.f32 "
        "{%0,%1,%2,%3}, {%4,%5,%6,%7}, {%8,%9}, {%0,%1,%2,%3};"
        : "+f"(c[0]), "+f"(c[1]), "+f"(c[2]), "+f"(c[3])
        : "r"(a[0]), "r"(a[1]), "r"(a[2]), "r"(a[3]), "r"(b[0]), "r"(b[1]));
}
__device__ __forceinline__ void cp16(uint32_t s, const void* g) {
    asm volatile("cp.async.cg.shared.global [%0], [%1], 16;" :: "r"(s), "l"(g));
}
#define CP_COMMIT() asm volatile("cp.async.commit_group;" ::: "memory")
#define CP_WAIT(n)  asm volatile("cp.async.wait_group %0;" :: "n"(n) : "memory")

// fp16 hi/lo split of two fp32 values (residual captures down to 2^-22)
__device__ __forceinline__ void split_pack2(float x, float y, uint32_t& hi, uint32_t& lo) {
    __half2 h2 = __floats2half2_rn(x, y);
    float rx = x - __half2float(__low2half(h2));
    float ry = y - __half2float(__high2half(h2));
    __half2 l2 = __floats2half2_rn(rx, ry);
    hi = *reinterpret_cast<uint32_t*>(&h2);
    lo = *reinterpret_cast<uint32_t*>(&l2);
}
__device__ __forceinline__ uint32_t pack_f16x2(float x, float y) {
    __half2 h2 = __floats2half2_rn(x, y);
    return *reinterpret_cast<uint32_t*>(&h2);
}

// ---------------------------------------------------------------------------
// Fused fp32 -> fp16 hi/lo split
// ---------------------------------------------------------------------------
struct SplitArgs {
    const float* x[4];
    f16* h[4];
    f16* l[4];
};

__global__ __launch_bounds__(256) void split_multi(SplitArgs a, int n)
{
    int z = blockIdx.y;
    const float* x = a.x[z];
    f16 *h = a.h[z], *l = a.l[z];
    int i = (blockIdx.x * 256 + threadIdx.x) * 4;
    if (i >= n) return;
    float4 v = *reinterpret_cast<const float4*>(x + i);
    uint32_t h01, l01, h23, l23;
    split_pack2(v.x, v.y, h01, l01);
    split_pack2(v.z, v.w, h23, l23);
    *reinterpret_cast<uint32_t*>(h + i)     = h01;
    *reinterpret_cast<uint32_t*>(h + i + 2) = h23;
    *reinterpret_cast<uint32_t*>(l + i)     = l01;
    *reinterpret_cast<uint32_t*>(l + i + 2) = l23;
}

// ---------------------------------------------------------------------------
// HMMA GEMM body: Y = A @ B^T, 3xFP16 split. 2-stage cp.async pipeline,
// term-major MMA ordering (RAW revisit distance 16). CTA 128x128, BK=32.
// ---------------------------------------------------------------------------
#define GLD 40
#define GSTAGE_B 40960   // 4 tiles * 128 * GLD * 2 bytes

template<bool SPLIT_OUT>
__device__ __forceinline__ void gemm_body(
    const f16* __restrict__ Ah, const f16* __restrict__ Al,
    const f16* __restrict__ Bh, const f16* __restrict__ Bl,
    float* __restrict__ Yf, f16* __restrict__ Yh, f16* __restrict__ Yl,
    f16* smg, float oscale)
{
    const int tid  = threadIdx.x;
    const int lane = tid & 31;
    const int wid  = tid >> 5;
    const int wm   = wid >> 2;
    const int wn   = wid & 3;
    const int bm   = blockIdx.y, bn = blockIdx.x;
    const uint32_t uS = smem_u32(smg);

    auto issue = [&](int ktile) {
        const int kt = ktile * 32;
        const uint32_t sbase = uS + (ktile & 1) * GSTAGE_B;
#pragma unroll
        for (int it = 0; it < 8; it++) {
            int idx  = tid + it * 256;
            int tile = idx >> 9;
            int rem  = idx & 511;
            int r    = rem >> 2, j = rem & 3;
            const f16* gp = (tile == 0 ? Ah : tile == 1 ? Al : tile == 2 ? Bh : Bl);
            int row = ((tile < 2) ? bm : bn) * 128 + r;
            cp16(sbase + tile * 10240 + r * 80 + j * 16,
                 gp + (size_t)row * DM + kt + j * 8);
        }
    };

    float acc[4][4][4];
#pragma unroll
    for (int i = 0; i < 4; i++)
#pragma unroll
        for (int j = 0; j < 4; j++)
#pragma unroll
            for (int k = 0; k < 4; k++) acc[i][j][k] = 0.f;

    const int a_r  = (lane & 15), a_c = (lane >> 4) * 8;
    const int kn_r = (lane & 7) + ((lane >> 4) & 1) * 8;
    const int kn_c = ((lane >> 3) & 1) * 8;

    issue(0); CP_COMMIT();

    for (int kt = 0; kt < 32; kt++) {
        CP_WAIT(0);
        __syncthreads();
        if (kt + 1 < 32) { issue(kt + 1); CP_COMMIT(); }

        const uint32_t st = uS + (kt & 1) * GSTAGE_B;
        const uint32_t uAh = st, uAl = st + 10240, uBh = st + 20480, uBl = st + 30720;

#pragma unroll
        for (int s = 0; s < 2; s++) {
            uint32_t ah[4][4], al[4][4], bh[4][2], bl[4][2];
#pragma unroll
            for (int i = 0; i < 4; i++) {
                uint32_t off = (uint32_t)(((wm * 64 + i * 16 + a_r) * GLD + s * 16 + a_c) * 2);
                ldsm_x4(ah[i], uAh + off);
                ldsm_x4(al[i], uAl + off);
            }
#pragma unroll
            for (int j2 = 0; j2 < 2; j2++) {
                uint32_t b4h[4], b4l[4];
                uint32_t off = (uint32_t)(((wn * 32 + j2 * 16 + kn_r) * GLD + s * 16 + kn_c) * 2);
                ldsm_x4(b4h, uBh + off);
                ldsm_x4(b4l, uBl + off);
                bh[2*j2][0] = b4h[0]; bh[2*j2][1] = b4h[1];
                bh[2*j2+1][0] = b4h[2]; bh[2*j2+1][1] = b4h[3];
                bl[2*j2][0] = b4l[0]; bl[2*j2][1] = b4l[1];
                bl[2*j2+1][0] = b4l[2]; bl[2*j2+1][1] = b4l[3];
            }
            // term-major: each acc[i][j] revisited at distance 16 (RAW relief);
            // per-accumulator term order (hh, hl, lh) unchanged -> bit-identical
#pragma unroll
            for (int i = 0; i < 4; i++)
#pragma unroll
                for (int j = 0; j < 4; j++)
                    mma_f16(acc[i][j], ah[i], bh[j]);
#pragma unroll
            for (int i = 0; i < 4; i++)
#pragma unroll
                for (int j = 0; j < 4; j++)
                    mma_f16(acc[i][j], ah[i], bl[j]);
#pragma unroll
            for (int i = 0; i < 4; i++)
#pragma unroll
                for (int j = 0; j < 4; j++)
                    mma_f16(acc[i][j], al[i], bh[j]);
        }
    }

    const int g = lane >> 2, t = lane & 3;
#pragma unroll
    for (int i = 0; i < 4; i++) {
        int row0 = bm * 128 + wm * 64 + i * 16 + g;
#pragma unroll
        for (int j = 0; j < 4; j++) {
            int col = bn * 128 + wn * 32 + j * 8 + 2 * t;
            if (SPLIT_OUT) {
                uint32_t hi, lo;
                split_pack2(acc[i][j][0] * oscale, acc[i][j][1] * oscale, hi, lo);
                *reinterpret_cast<uint32_t*>(Yh + (size_t)row0 * DM + col) = hi;
                *reinterpret_cast<uint32_t*>(Yl + (size_t)row0 * DM + col) = lo;
                split_pack2(acc[i][j][2] * oscale, acc[i][j][3] * oscale, hi, lo);
                *reinterpret_cast<uint32_t*>(Yh + (size_t)(row0 + 8) * DM + col) = hi;
                *reinterpret_cast<uint32_t*>(Yl + (size_t)(row0 + 8) * DM + col) = lo;
            } else {
                *reinterpret_cast<float2*>(Yf + (size_t)row0 * DM + col) =
                    make_float2(acc[i][j][0], acc[i][j][1]);
                *reinterpret_cast<float2*>(Yf + (size_t)(row0 + 8) * DM + col) =
                    make_float2(acc[i][j][2], acc[i][j][3]);
            }
        }
    }
}

struct QKVArgs {
    const f16 *Ah[3], *Al[3], *Bh[3], *Bl[3];
    f16 *Yh[3], *Yl[3];
    float sc[3];
};

__global__ __launch_bounds__(256, 2) void gemm_qkv(QKVArgs a)
{
    extern __shared__ __align__(16) f16 smg[];
    int z = blockIdx.z;
    gemm_body<true>(a.Ah[z], a.Al[z], a.Bh[z], a.Bl[z], nullptr, a.Yh[z], a.Yl[z], smg, a.sc[z]);
}

__global__ __launch_bounds__(256, 2) void gemm_out(
    const f16* __restrict__ Ah, const f16* __restrict__ Al,
    const f16* __restrict__ Bh, const f16* __restrict__ Bl,
    float* __restrict__ Yf)
{
    extern __shared__ __align__(16) f16 smg[];
    gemm_body<false>(Ah, Al, Bh, Bl, Yf, nullptr, nullptr, smg, 1.f);
}

// ---------------------------------------------------------------------------
// HMMA flash attention, fp16.
// QK^T = (Qh + Ql) @ Kh: K-frags preloaded, hi-pass then lo-pass over all 8
// accumulators (RAW revisit distance 8). PV = P @ (Vh + Vl): V-hi pass then
// V-lo pass. 3-stage KV pipeline (Kh,Vh,Vl); 2 CTAs/SM; exp2 domain.
// ---------------------------------------------------------------------------
#define FP 72            // pitch f16 (144 B)
#define KV_STAGE 27648   // 3 arrays * 64 * FP * 2 B

__global__ __launch_bounds__(256, 2) void flash_mma(
    const f16* __restrict__ Qh, const f16* __restrict__ Ql,
    const f16* __restrict__ Kh,
    const f16* __restrict__ Vh, const f16* __restrict__ Vl,
    f16* __restrict__ Oh, f16* __restrict__ Ol)
{
    extern __shared__ __align__(16) f16 sb[];
    const int tid  = threadIdx.x;
    const int lane = tid & 31;
    const int wid  = tid >> 5;
    const int g    = lane >> 2;
    const int t    = lane & 3;
    const int h    = blockIdx.x;
    const int qb   = blockIdx.y;
    const uint32_t uS = smem_u32(sb);

    const int a_r  = (lane & 15), a_c = (lane >> 4) * 8;
    const int kn_r = (lane & 7) + ((lane >> 4) & 1) * 8;
    const int kn_c = ((lane >> 3) & 1) * 8;
    const int vk_r = (lane & 7) + ((lane >> 3) & 1) * 8;
    const int vn_c = ((lane >> 4) & 1) * 8;

    // ---- stage Q (hi/lo), load fragments to registers ----
#pragma unroll
    for (int it = 0; it < 8; it++) {
        int idx = tid + it * 256;
        int arr = idx >> 10;
        int rem = idx & 1023;
        int r   = rem >> 3, j = rem & 7;
        const f16* gp = arr ? Ql : Qh;
        cp16(uS + arr * 18432 + r * 144 + j * 16,
             gp + (size_t)(qb * 128 + r) * DM + h * DK + j * 8);
    }
    CP_COMMIT(); CP_WAIT(0);
    __syncthreads();

    uint32_t qfh[4][4], qfl[4][4];
#pragma unroll
    for (int kc = 0; kc < 4; kc++) {
        uint32_t aoff = (uint32_t)(((wid * 16 + a_r) * FP + kc * 16 + a_c) * 2);
        ldsm_x4(qfh[kc], uS + aoff);
        ldsm_x4(qfl[kc], uS + 18432 + aoff);
    }
    __syncthreads();   // Q reads done before KV stage 0/1 overwrite

    auto issue_kv = [&](int kv) {
        const uint32_t base = uS + (kv % 3) * KV_STAGE;
#pragma unroll
        for (int it = 0; it < 6; it++) {
            int idx = tid + it * 256;           // 0..1535
            int arr = idx >> 9;                 // 0:Kh 1:Vh 2:Vl
            int rem = idx & 511;
            int r   = rem >> 3, j = rem & 7;
            const f16* gp = (arr == 0 ? Kh : arr == 1 ? Vh : Vl);
            cp16(base + arr * 9216 + r * 144 + j * 16,
                 gp + (size_t)(kv * 64 + r) * DM + h * DK + j * 8);
        }
    };

    issue_kv(0); CP_COMMIT();
    issue_kv(1); CP_COMMIT();

    float o[8][4];
#pragma unroll
    for (int nf = 0; nf < 8; nf++)
#pragma unroll
        for (int k = 0; k < 4; k++) o[nf][k] = 0.f;
    float m0 = -1e30f, m1 = -1e30f, l0 = 0.f, l1 = 0.f;

    for (int kv = 0; kv < SEQ / 64; kv++) {
        if (kv + 1 < SEQ / 64) { CP_WAIT(1); } else { CP_WAIT(0); }
        __syncthreads();
        if (kv + 2 < SEQ / 64) { issue_kv(kv + 2); CP_COMMIT(); }

        const uint32_t kb  = uS + (kv % 3) * KV_STAGE;
        const uint32_t uKh = kb, uVh = kb + 9216, uVl = kb + 18432;

        // ---- S = (Qh + Ql) @ Kh^T, pass-split for RAW distance 8 ----
        float s[8][4];
#pragma unroll
        for (int nf = 0; nf < 8; nf++)
#pragma unroll
            for (int k = 0; k < 4; k++) s[nf][k] = 0.f;

#pragma unroll
        for (int kc = 0; kc < 4; kc++) {
            uint32_t b4[4][4];
#pragma unroll
            for (int nf2 = 0; nf2 < 4; nf2++) {
                uint32_t boff = (uint32_t)(((nf2 * 16 + kn_r) * FP + kc * 16 + kn_c) * 2);
                ldsm_x4(b4[nf2], uKh + boff);
            }
#pragma unroll
            for (int nf2 = 0; nf2 < 4; nf2++) {        // hi pass: 8 indep MMAs
                mma_f16(s[2*nf2],     qfh[kc], b4[nf2]);
                mma_f16(s[2*nf2 + 1], qfh[kc], b4[nf2] + 2);
            }
#pragma unroll
            for (int nf2 = 0; nf2 < 4; nf2++) {        // lo pass: revisit dist 8
                mma_f16(s[2*nf2],     qfl[kc], b4[nf2]);
                mma_f16(s[2*nf2 + 1], qfl[kc], b4[nf2] + 2);
            }
        }

        // ---- max reduction ----
        float mx0 = -1e30f, mx1 = -1e30f;
#pragma unroll
        for (int nf = 0; nf < 8; nf++) {
            mx0 = fmaxf(mx0, fmaxf(s[nf][0], s[nf][1]));
            mx1 = fmaxf(mx1, fmaxf(s[nf][2], s[nf][3]));
        }
        mx0 = fmaxf(mx0, __shfl_xor_sync(0xffffffffu, mx0, 1));
        mx0 = fmaxf(mx0, __shfl_xor_sync(0xffffffffu, mx0, 2));
        mx1 = fmaxf(mx1, __shfl_xor_sync(0xffffffffu, mx1, 1));
        mx1 = fmaxf(mx1, __shfl_xor_sync(0xffffffffu, mx1, 2));

        float mn0 = fmaxf(m0, mx0), mn1 = fmaxf(m1, mx1);
        float c0 = exp2f(m0 - mn0), c1 = exp2f(m1 - mn1);
        m0 = mn0; m1 = mn1;
#pragma unroll
        for (int nf = 0; nf < 8; nf++) {
            o[nf][0] *= c0; o[nf][1] *= c0;
            o[nf][2] *= c1; o[nf][3] *= c1;
        }
        float rs0 = 0.f, rs1 = 0.f;

        // ---- exp + fp16 pack + PV MMAs (hi pass then lo pass per kc) ----
#pragma unroll
        for (int kc = 0; kc < 4; kc++) {
            float e00 = exp2f(s[2*kc][0]     - mn0);
            float e01 = exp2f(s[2*kc][1]     - mn0);
            float e02 = exp2f(s[2*kc][2]     - mn1);
            float e03 = exp2f(s[2*kc][3]     - mn1);
            float e10 = exp2f(s[2*kc + 1][0] - mn0);
            float e11 = exp2f(s[2*kc + 1][1] - mn0);
            float e12 = exp2f(s[2*kc + 1][2] - mn1);
            float e13 = exp2f(s[2*kc + 1][3] - mn1);
            rs0 += (e00 + e01) + (e10 + e11);
            rs1 += (e02 + e03) + (e12 + e13);

            uint32_t pa[4];
            pa[0] = pack_f16x2(e00, e01);
            pa[1] = pack_f16x2(e02, e03);
            pa[2] = pack_f16x2(e10, e11);
            pa[3] = pack_f16x2(e12, e13);

            uint32_t v4[4][4];
#pragma unroll
            for (int nf2 = 0; nf2 < 4; nf2++) {
                uint32_t voff = (uint32_t)(((kc * 16 + vk_r) * FP + nf2 * 16 + vn_c) * 2);
                ldsm_x4_trans(v4[nf2], uVh + voff);
            }
#pragma unroll
            for (int nf2 = 0; nf2 < 4; nf2++) {        // V-hi pass: 8 indep MMAs
                mma_f16(o[2*nf2],     pa, v4[nf2]);
                mma_f16(o[2*nf2 + 1], pa, v4[nf2] + 2);
            }
#pragma unroll
            for (int nf2 = 0; nf2 < 4; nf2++) {
                uint32_t voff = (uint32_t)(((kc * 16 + vk_r) * FP + nf2 * 16 + vn_c) * 2);
                ldsm_x4_trans(v4[nf2], uVl + voff);
            }
#pragma unroll
            for (int nf2 = 0; nf2 < 4; nf2++) {        // V-lo pass: revisit dist 8
                mma_f16(o[2*nf2],     pa, v4[nf2]);
                mma_f16(o[2*nf2 + 1], pa, v4[nf2] + 2);
            }
        }
        rs0 += __shfl_xor_sync(0xffffffffu, rs0, 1);
        rs0 += __shfl_xor_sync(0xffffffffu, rs0, 2);
        rs1 += __shfl_xor_sync(0xffffffffu, rs1, 1);
        rs1 += __shfl_xor_sync(0xffffffffu, rs1, 2);
        l0 = l0 * c0 + rs0;
        l1 = l1 * c1 + rs1;
    }

    // ---- normalize + store as fp16 hi/lo ----
    float i0 = 1.f / l0, i1 = 1.f / l1;
    int row0 = qb * 128 + wid * 16 + g;
#pragma unroll
    for (int nf = 0; nf < 8; nf++) {
        int col = h * DK + nf * 8 + 2 * t;
        uint32_t hi, lo;
        split_pack2(o[nf][0] * i0, o[nf][1] * i0, hi, lo);
        *reinterpret_cast<uint32_t*>(Oh + (size_t)row0 * DM + col) = hi;
        *reinterpret_cast<uint32_t*>(Ol + (size_t)row0 * DM + col) = lo;
        split_pack2(o[nf][2] * i1, o[nf][3] * i1, hi, lo);
        *reinterpret_cast<uint32_t*>(Oh + (size_t)(row0 + 8) * DM + col) = hi;
        *reinterpret_cast<uint32_t*>(Ol + (size_t)(row0 + 8) * DM + col) = lo;
    }
}

// ---------------------------------------------------------------------------
extern "C" void kernel_launch(void* const* d_in, const int* in_sizes, int n_in,
                              void* d_out, int out_size)
{
    const float* query = (const float*)d_in[0];
    const float* key_t = (const float*)d_in[1];
    const float* value = (const float*)d_in[2];
    const float* w_q   = (const float*)d_in[3];
    const float* w_k   = (const float*)d_in[4];
    const float* w_v   = (const float*)d_in[5];
    const float* w_o   = (const float*)d_in[6];
    float* out = (float*)d_out;

    f16 *xqh, *xql, *xkh, *xkl, *xvh, *xvl;
    f16 *wqh, *wql, *wkh, *wkl, *wvh, *wvl, *woh, *wol;
    f16 *Qh, *Ql, *Kh, *Kl, *Vh, *Vl, *oh, *ol;
    cudaGetSymbolAddress((void**)&xqh, g_xqh); cudaGetSymbolAddress((void**)&xql, g_xql);
    cudaGetSymbolAddress((void**)&xkh, g_xkh); cudaGetSymbolAddress((void**)&xkl, g_xkl);
    cudaGetSymbolAddress((void**)&xvh, g_xvh); cudaGetSymbolAddress((void**)&xvl, g_xvl);
    cudaGetSymbolAddress((void**)&wqh, g_wqh); cudaGetSymbolAddress((void**)&wql, g_wql);
    cudaGetSymbolAddress((void**)&wkh, g_wkh); cudaGetSymbolAddress((void**)&wkl, g_wkl);
    cudaGetSymbolAddress((void**)&wvh, g_wvh); cudaGetSymbolAddress((void**)&wvl, g_wvl);
    cudaGetSymbolAddress((void**)&woh, g_woh); cudaGetSymbolAddress((void**)&wol, g_wol);
    cudaGetSymbolAddress((void**)&Qh,  g_Qh);  cudaGetSymbolAddress((void**)&Ql,  g_Ql);
    cudaGetSymbolAddress((void**)&Kh,  g_Kh);  cudaGetSymbolAddress((void**)&Kl,  g_Kl);
    cudaGetSymbolAddress((void**)&Vh,  g_Vh);  cudaGetSymbolAddress((void**)&Vl,  g_Vl);
    cudaGetSymbolAddress((void**)&oh,  g_oh);  cudaGetSymbolAddress((void**)&ol,  g_ol);

    const int smem_gemm = 2 * GSTAGE_B;     // 81920 B
    const int smem_attn = 3 * KV_STAGE;     // 82944 B
    cudaFuncSetAttribute(gemm_qkv,  cudaFuncAttributeMaxDynamicSharedMemorySize, smem_gemm);
    cudaFuncSetAttribute(gemm_out,  cudaFuncAttributeMaxDynamicSharedMemorySize, smem_gemm);
    cudaFuncSetAttribute(flash_mma, cudaFuncAttributeMaxDynamicSharedMemorySize, smem_attn);

    const int nAct = SEQ * DM, nW = DM * DM;

    SplitArgs sa{};
    sa.x[0] = query; sa.h[0] = xqh; sa.l[0] = xql;
    sa.x[1] = key_t; sa.h[1] = xkh; sa.l[1] = xkl;
    sa.x[2] = value; sa.h[2] = xvh; sa.l[2] = xvl;
    split_multi<<<dim3(nAct / 1024, 3), 256>>>(sa, nAct);

    SplitArgs sw{};
    sw.x[0] = w_q; sw.h[0] = wqh; sw.l[0] = wql;
    sw.x[1] = w_k; sw.h[1] = wkh; sw.l[1] = wkl;
    sw.x[2] = w_v; sw.h[2] = wvh; sw.l[2] = wvl;
    sw.x[3] = w_o; sw.h[3] = woh; sw.l[3] = wol;
    split_multi<<<dim3(nW / 1024, 4), 256>>>(sw, nW);

    QKVArgs qa{};
    qa.Ah[0] = xqh; qa.Al[0] = xql; qa.Bh[0] = wqh; qa.Bl[0] = wql; qa.Yh[0] = Qh; qa.Yl[0] = Ql;
    qa.Ah[1] = xkh; qa.Al[1] = xkl; qa.Bh[1] = wkh; qa.Bl[1] = wkl; qa.Yh[1] = Kh; qa.Yl[1] = Kl;
    qa.Ah[2] = xvh; qa.Al[2] = xvl; qa.Bh[2] = wvh; qa.Bl[2] = wvl; qa.Yh[2] = Vh; qa.Yl[2] = Vl;
    qa.sc[0] = 0.125f * 1.4426950408889634f;   // 1/sqrt(d_k) * log2(e) -> exp2 domain
    qa.sc[1] = 1.f; qa.sc[2] = 1.f;
    gemm_qkv<<<dim3(DM / 128, SEQ / 128, 3), 256, smem_gemm>>>(qa);

    dim3 agrid(NH, SEQ / 128);   // (16, 32)
    flash_mma<<<agrid, 256, smem_attn>>>(Qh, Ql, Kh, Vh, Vl, oh, ol);

    gemm_out<<<dim3(DM / 128, SEQ / 128), 256, smem_gemm>>>(oh, ol, woh, wol, out);
}

// round 16
// speedup vs baseline: 1.4938x; 1.1206x over previous
#include <cuda_runtime.h>
#include <cuda_fp16.h>
#include <cstdint>
#include <math.h>

#define SEQ 4096
#define DM  1024
#define NH  16
#define DK  64

using f16 = __half;

// ---------------------------------------------------------------------------
// Scratch (__device__ globals: allocation-guard safe) — fp16 hi/lo pairs
// ---------------------------------------------------------------------------
__device__ f16 g_xqh[SEQ * DM], g_xql[SEQ * DM];
__device__ f16 g_xkh[SEQ * DM], g_xkl[SEQ * DM];
__device__ f16 g_xvh[SEQ * DM], g_xvl[SEQ * DM];
__device__ f16 g_wqh[DM * DM],  g_wql[DM * DM];
__device__ f16 g_wkh[DM * DM],  g_wkl[DM * DM];
__device__ f16 g_wvh[DM * DM],  g_wvl[DM * DM];
__device__ f16 g_woh[DM * DM],  g_wol[DM * DM];
__device__ f16 g_Qh[SEQ * DM],  g_Ql[SEQ * DM];
__device__ f16 g_Kh[SEQ * DM],  g_Kl[SEQ * DM];
__device__ f16 g_Vh[SEQ * DM],  g_Vl[SEQ * DM];
__device__ f16 g_oh[SEQ * DM],  g_ol[SEQ * DM];

// ---------------------------------------------------------------------------
// PTX helpers — valid at compute_103 (no tcgen05)
// ---------------------------------------------------------------------------
__device__ __forceinline__ uint32_t smem_u32(const void* p) {
    uint32_t a;
    asm("{ .reg .u64 t; cvta.to.shared.u64 t, %1; cvt.u32.u64 %0, t; }" : "=r"(a) : "l"(p));
    return a;
}
__device__ __forceinline__ void ldsm_x4(uint32_t* r, uint32_t addr) {
    asm volatile("ldmatrix.sync.aligned.m8n8.x4.shared.b16 {%0,%1,%2,%3}, [%4];"
                 : "=r"(r[0]), "=r"(r[1]), "=r"(r[2]), "=r"(r[3]) : "r"(addr));
}
__device__ __forceinline__ void ldsm_x4_trans(uint32_t* r, uint32_t addr) {
    asm volatile("ldmatrix.sync.aligned.m8n8.x4.trans.shared.b16 {%0,%1,%2,%3}, [%4];"
                 : "=r"(r[0]), "=r"(r[1]), "=r"(r[2]), "=r"(r[3]) : "r"(addr));
}
__device__ __forceinline__ void mma_f16(float* c, const uint32_t* a, const uint32_t* b) {
    asm volatile(
        "mma.sync.aligned.m16n8k16.row.col.f32.f16.f16.f32 "
        "{%0,%1,%2,%3}, {%4,%5,%6,%7}, {%8,%9}, {%0,%1,%2,%3};"
        : "+f"(c[0]), "+f"(c[1]), "+f"(c[2]), "+f"(c[3])
        : "r"(a[0]), "r"(a[1]), "r"(a[2]), "r"(a[3]), "r"(b[0]), "r"(b[1]));
}
__device__ __forceinline__ void cp16(uint32_t s, const void* g) {
    asm volatile("cp.async.cg.shared.global [%0], [%1], 16;" :: "r"(s), "l"(g));
}
#define CP_COMMIT() asm volatile("cp.async.commit_group;" ::: "memory")
#define CP_WAIT(n)  asm volatile("cp.async.wait_group %0;" :: "n"(n) : "memory")

// fp16 hi/lo split of two fp32 values (residual captures down to 2^-22)
__device__ __forceinline__ void split_pack2(float x, float y, uint32_t& hi, uint32_t& lo) {
    __half2 h2 = __floats2half2_rn(x, y);
    float rx = x - __half2float(__low2half(h2));
    float ry = y - __half2float(__high2half(h2));
    __half2 l2 = __floats2half2_rn(rx, ry);
    hi = *reinterpret_cast<uint32_t*>(&h2);
    lo = *reinterpret_cast<uint32_t*>(&l2);
}
__device__ __forceinline__ uint32_t pack_f16x2(float x, float y) {
    __half2 h2 = __floats2half2_rn(x, y);
    return *reinterpret_cast<uint32_t*>(&h2);
}

// ---------------------------------------------------------------------------
// Fused fp32 -> fp16 hi/lo split
// ---------------------------------------------------------------------------
struct SplitArgs {
    const float* x[4];
    f16* h[4];
    f16* l[4];
};

__global__ __launch_bounds__(256) void split_multi(SplitArgs a, int n)
{
    int z = blockIdx.y;
    const float* x = a.x[z];
    f16 *h = a.h[z], *l = a.l[z];
    int i = (blockIdx.x * 256 + threadIdx.x) * 4;
    if (i >= n) return;
    float4 v = *reinterpret_cast<const float4*>(x + i);
    uint32_t h01, l01, h23, l23;
    split_pack2(v.x, v.y, h01, l01);
    split_pack2(v.z, v.w, h23, l23);
    *reinterpret_cast<uint32_t*>(h + i)     = h01;
    *reinterpret_cast<uint32_t*>(h + i + 2) = h23;
    *reinterpret_cast<uint32_t*>(l + i)     = l01;
    *reinterpret_cast<uint32_t*>(l + i + 2) = l23;
}

// ---------------------------------------------------------------------------
// HMMA GEMM body: Y = A @ B^T, 3xFP16 split. 2-stage cp.async pipeline,
// term-major MMA ordering. CTA 128x128, BK=32, 2 CTAs/SM.
// ---------------------------------------------------------------------------
#define GLD 40
#define GSTAGE_B 40960   // 4 tiles * 128 * GLD * 2 bytes

template<bool SPLIT_OUT>
__device__ __forceinline__ void gemm_body(
    const f16* __restrict__ Ah, const f16* __restrict__ Al,
    const f16* __restrict__ Bh, const f16* __restrict__ Bl,
    float* __restrict__ Yf, f16* __restrict__ Yh, f16* __restrict__ Yl,
    f16* smg, float oscale)
{
    const int tid  = threadIdx.x;
    const int lane = tid & 31;
    const int wid  = tid >> 5;
    const int wm   = wid >> 2;
    const int wn   = wid & 3;
    const int bm   = blockIdx.y, bn = blockIdx.x;
    const uint32_t uS = smem_u32(smg);

    auto issue = [&](int ktile) {
        const int kt = ktile * 32;
        const uint32_t sbase = uS + (ktile & 1) * GSTAGE_B;
#pragma unroll
        for (int it = 0; it < 8; it++) {
            int idx  = tid + it * 256;
            int tile = idx >> 9;
            int rem  = idx & 511;
            int r    = rem >> 2, j = rem & 3;
            const f16* gp = (tile == 0 ? Ah : tile == 1 ? Al : tile == 2 ? Bh : Bl);
            int row = ((tile < 2) ? bm : bn) * 128 + r;
            cp16(sbase + tile * 10240 + r * 80 + j * 16,
                 gp + (size_t)row * DM + kt + j * 8);
        }
    };

    float acc[4][4][4];
#pragma unroll
    for (int i = 0; i < 4; i++)
#pragma unroll
        for (int j = 0; j < 4; j++)
#pragma unroll
            for (int k = 0; k < 4; k++) acc[i][j][k] = 0.f;

    const int a_r  = (lane & 15), a_c = (lane >> 4) * 8;
    const int kn_r = (lane & 7) + ((lane >> 4) & 1) * 8;
    const int kn_c = ((lane >> 3) & 1) * 8;

    issue(0); CP_COMMIT();

    for (int kt = 0; kt < 32; kt++) {
        CP_WAIT(0);
        __syncthreads();
        if (kt + 1 < 32) { issue(kt + 1); CP_COMMIT(); }

        const uint32_t st = uS + (kt & 1) * GSTAGE_B;
        const uint32_t uAh = st, uAl = st + 10240, uBh = st + 20480, uBl = st + 30720;

#pragma unroll
        for (int s = 0; s < 2; s++) {
            uint32_t ah[4][4], al[4][4], bh[4][2], bl[4][2];
#pragma unroll
            for (int i = 0; i < 4; i++) {
                uint32_t off = (uint32_t)(((wm * 64 + i * 16 + a_r) * GLD + s * 16 + a_c) * 2);
                ldsm_x4(ah[i], uAh + off);
                ldsm_x4(al[i], uAl + off);
            }
#pragma unroll
            for (int j2 = 0; j2 < 2; j2++) {
                uint32_t b4h[4], b4l[4];
                uint32_t off = (uint32_t)(((wn * 32 + j2 * 16 + kn_r) * GLD + s * 16 + kn_c) * 2);
                ldsm_x4(b4h, uBh + off);
                ldsm_x4(b4l, uBl + off);
                bh[2*j2][0] = b4h[0]; bh[2*j2][1] = b4h[1];
                bh[2*j2+1][0] = b4h[2]; bh[2*j2+1][1] = b4h[3];
                bl[2*j2][0] = b4l[0]; bl[2*j2][1] = b4l[1];
                bl[2*j2+1][0] = b4l[2]; bl[2*j2+1][1] = b4l[3];
            }
#pragma unroll
            for (int i = 0; i < 4; i++)
#pragma unroll
                for (int j = 0; j < 4; j++)
                    mma_f16(acc[i][j], ah[i], bh[j]);
#pragma unroll
            for (int i = 0; i < 4; i++)
#pragma unroll
                for (int j = 0; j < 4; j++)
                    mma_f16(acc[i][j], ah[i], bl[j]);
#pragma unroll
            for (int i = 0; i < 4; i++)
#pragma unroll
                for (int j = 0; j < 4; j++)
                    mma_f16(acc[i][j], al[i], bh[j]);
        }
    }

    const int g = lane >> 2, t = lane & 3;
#pragma unroll
    for (int i = 0; i < 4; i++) {
        int row0 = bm * 128 + wm * 64 + i * 16 + g;
#pragma unroll
        for (int j = 0; j < 4; j++) {
            int col = bn * 128 + wn * 32 + j * 8 + 2 * t;
            if (SPLIT_OUT) {
                uint32_t hi, lo;
                split_pack2(acc[i][j][0] * oscale, acc[i][j][1] * oscale, hi, lo);
                *reinterpret_cast<uint32_t*>(Yh + (size_t)row0 * DM + col) = hi;
                *reinterpret_cast<uint32_t*>(Yl + (size_t)row0 * DM + col) = lo;
                split_pack2(acc[i][j][2] * oscale, acc[i][j][3] * oscale, hi, lo);
                *reinterpret_cast<uint32_t*>(Yh + (size_t)(row0 + 8) * DM + col) = hi;
                *reinterpret_cast<uint32_t*>(Yl + (size_t)(row0 + 8) * DM + col) = lo;
            } else {
                *reinterpret_cast<float2*>(Yf + (size_t)row0 * DM + col) =
                    make_float2(acc[i][j][0], acc[i][j][1]);
                *reinterpret_cast<float2*>(Yf + (size_t)(row0 + 8) * DM + col) =
                    make_float2(acc[i][j][2], acc[i][j][3]);
            }
        }
    }
}

struct QKVArgs {
    const f16 *Ah[3], *Al[3], *Bh[3], *Bl[3];
    f16 *Yh[3], *Yl[3];
    float sc[3];
};

__global__ __launch_bounds__(256, 2) void gemm_qkv(QKVArgs a)
{
    extern __shared__ __align__(16) f16 smg[];
    int z = blockIdx.z;
    gemm_body<true>(a.Ah[z], a.Al[z], a.Bh[z], a.Bl[z], nullptr, a.Yh[z], a.Yl[z], smg, a.sc[z]);
}

__global__ __launch_bounds__(256, 2) void gemm_out(
    const f16* __restrict__ Ah, const f16* __restrict__ Al,
    const f16* __restrict__ Bh, const f16* __restrict__ Bl,
    float* __restrict__ Yf)
{
    extern __shared__ __align__(16) f16 smg[];
    gemm_body<false>(Ah, Al, Bh, Bl, Yf, nullptr, nullptr, smg, 1.f);
}

// ---------------------------------------------------------------------------
// HMMA flash attention, fp16, minimal-MMA variant:
// QK^T = (Qh + Ql) @ Kh   (2 terms, K unsplit)
// PV   = P @ Vh           (1 term, P and V unsplit fp16)
// KV stage = 2 arrays (Kh, Vh) = 18.4 KB; 4-stage cp.async pipeline;
// 2 CTAs/SM; exp2 domain (scale pre-folded into Q projection).
// ---------------------------------------------------------------------------
#define FP 72            // pitch f16 (144 B)
#define KV_STAGE 18432   // 2 arrays * 64 * FP * 2 B
#define NKV (SEQ / 64)

__global__ __launch_bounds__(256, 2) void flash_mma(
    const f16* __restrict__ Qh, const f16* __restrict__ Ql,
    const f16* __restrict__ Kh, const f16* __restrict__ Vh,
    f16* __restrict__ Oh, f16* __restrict__ Ol)
{
    extern __shared__ __align__(16) f16 sb[];
    const int tid  = threadIdx.x;
    const int lane = tid & 31;
    const int wid  = tid >> 5;
    const int g    = lane >> 2;
    const int t    = lane & 3;
    const int h    = blockIdx.x;
    const int qb   = blockIdx.y;
    const uint32_t uS = smem_u32(sb);

    const int a_r  = (lane & 15), a_c = (lane >> 4) * 8;
    const int kn_r = (lane & 7) + ((lane >> 4) & 1) * 8;
    const int kn_c = ((lane >> 3) & 1) * 8;
    const int vk_r = (lane & 7) + ((lane >> 3) & 1) * 8;
    const int vn_c = ((lane >> 4) & 1) * 8;

    // ---- stage Q (hi/lo), load fragments to registers ----
#pragma unroll
    for (int it = 0; it < 8; it++) {
        int idx = tid + it * 256;
        int arr = idx >> 10;
        int rem = idx & 1023;
        int r   = rem >> 3, j = rem & 7;
        const f16* gp = arr ? Ql : Qh;
        cp16(uS + arr * 18432 + r * 144 + j * 16,
             gp + (size_t)(qb * 128 + r) * DM + h * DK + j * 8);
    }
    CP_COMMIT(); CP_WAIT(0);
    __syncthreads();

    uint32_t qfh[4][4], qfl[4][4];
#pragma unroll
    for (int kc = 0; kc < 4; kc++) {
        uint32_t aoff = (uint32_t)(((wid * 16 + a_r) * FP + kc * 16 + a_c) * 2);
        ldsm_x4(qfh[kc], uS + aoff);
        ldsm_x4(qfl[kc], uS + 18432 + aoff);
    }
    __syncthreads();   // Q reads done before KV stages overwrite

    auto issue_kv = [&](int kv) {
        const uint32_t base = uS + (kv & 3) * KV_STAGE;
#pragma unroll
        for (int it = 0; it < 4; it++) {
            int idx = tid + it * 256;           // 0..1023
            int arr = idx >> 9;                 // 0:Kh 1:Vh
            int rem = idx & 511;
            int r   = rem >> 3, j = rem & 7;
            const f16* gp = (arr == 0 ? Kh : Vh);
            cp16(base + arr * 9216 + r * 144 + j * 16,
                 gp + (size_t)(kv * 64 + r) * DM + h * DK + j * 8);
        }
    };

    issue_kv(0); CP_COMMIT();
    issue_kv(1); CP_COMMIT();
    issue_kv(2); CP_COMMIT();

    float o[8][4];
#pragma unroll
    for (int nf = 0; nf < 8; nf++)
#pragma unroll
        for (int k = 0; k < 4; k++) o[nf][k] = 0.f;
    float m0 = -1e30f, m1 = -1e30f, l0 = 0.f, l1 = 0.f;

    for (int kv = 0; kv < NKV; kv++) {
        if (kv < NKV - 2)      { CP_WAIT(2); }
        else if (kv == NKV - 2){ CP_WAIT(1); }
        else                   { CP_WAIT(0); }
        __syncthreads();
        if (kv + 3 < NKV) { issue_kv(kv + 3); CP_COMMIT(); }

        const uint32_t kb  = uS + (kv & 3) * KV_STAGE;
        const uint32_t uKh = kb, uVh = kb + 9216;

        // ---- S = (Qh + Ql) @ Kh^T ----
        float s[8][4];
#pragma unroll
        for (int nf = 0; nf < 8; nf++)
#pragma unroll
            for (int k = 0; k < 4; k++) s[nf][k] = 0.f;

#pragma unroll
        for (int kc = 0; kc < 4; kc++) {
            uint32_t b4[4][4];
#pragma unroll
            for (int nf2 = 0; nf2 < 4; nf2++) {
                uint32_t boff = (uint32_t)(((nf2 * 16 + kn_r) * FP + kc * 16 + kn_c) * 2);
                ldsm_x4(b4[nf2], uKh + boff);
            }
#pragma unroll
            for (int nf2 = 0; nf2 < 4; nf2++) {
                mma_f16(s[2*nf2],     qfh[kc], b4[nf2]);
                mma_f16(s[2*nf2 + 1], qfh[kc], b4[nf2] + 2);
            }
#pragma unroll
            for (int nf2 = 0; nf2 < 4; nf2++) {
                mma_f16(s[2*nf2],     qfl[kc], b4[nf2]);
                mma_f16(s[2*nf2 + 1], qfl[kc], b4[nf2] + 2);
            }
        }

        // ---- max reduction ----
        float mx0 = -1e30f, mx1 = -1e30f;
#pragma unroll
        for (int nf = 0; nf < 8; nf++) {
            mx0 = fmaxf(mx0, fmaxf(s[nf][0], s[nf][1]));
            mx1 = fmaxf(mx1, fmaxf(s[nf][2], s[nf][3]));
        }
        mx0 = fmaxf(mx0, __shfl_xor_sync(0xffffffffu, mx0, 1));
        mx0 = fmaxf(mx0, __shfl_xor_sync(0xffffffffu, mx0, 2));
        mx1 = fmaxf(mx1, __shfl_xor_sync(0xffffffffu, mx1, 1));
        mx1 = fmaxf(mx1, __shfl_xor_sync(0xffffffffu, mx1, 2));

        float mn0 = fmaxf(m0, mx0), mn1 = fmaxf(m1, mx1);
        float c0 = exp2f(m0 - mn0), c1 = exp2f(m1 - mn1);
        m0 = mn0; m1 = mn1;
#pragma unroll
        for (int nf = 0; nf < 8; nf++) {
            o[nf][0] *= c0; o[nf][1] *= c0;
            o[nf][2] *= c1; o[nf][3] *= c1;
        }
        float rs0 = 0.f, rs1 = 0.f;

        // ---- exp + fp16 pack + PV MMAs (single V term) ----
#pragma unroll
        for (int kc = 0; kc < 4; kc++) {
            float e00 = exp2f(s[2*kc][0]     - mn0);
            float e01 = exp2f(s[2*kc][1]     - mn0);
            float e02 = exp2f(s[2*kc][2]     - mn1);
            float e03 = exp2f(s[2*kc][3]     - mn1);
            float e10 = exp2f(s[2*kc + 1][0] - mn0);
            float e11 = exp2f(s[2*kc + 1][1] - mn0);
            float e12 = exp2f(s[2*kc + 1][2] - mn1);
            float e13 = exp2f(s[2*kc + 1][3] - mn1);
            rs0 += (e00 + e01) + (e10 + e11);
            rs1 += (e02 + e03) + (e12 + e13);

            uint32_t pa[4];
            pa[0] = pack_f16x2(e00, e01);
            pa[1] = pack_f16x2(e02, e03);
            pa[2] = pack_f16x2(e10, e11);
            pa[3] = pack_f16x2(e12, e13);

            uint32_t v4[4][4];
#pragma unroll
            for (int nf2 = 0; nf2 < 4; nf2++) {
                uint32_t voff = (uint32_t)(((kc * 16 + vk_r) * FP + nf2 * 16 + vn_c) * 2);
                ldsm_x4_trans(v4[nf2], uVh + voff);
            }
#pragma unroll
            for (int nf2 = 0; nf2 < 4; nf2++) {
                mma_f16(o[2*nf2],     pa, v4[nf2]);
                mma_f16(o[2*nf2 + 1], pa, v4[nf2] + 2);
            }
        }
        rs0 += __shfl_xor_sync(0xffffffffu, rs0, 1);
        rs0 += __shfl_xor_sync(0xffffffffu, rs0, 2);
        rs1 += __shfl_xor_sync(0xffffffffu, rs1, 1);
        rs1 += __shfl_xor_sync(0xffffffffu, rs1, 2);
        l0 = l0 * c0 + rs0;
        l1 = l1 * c1 + rs1;
    }

    // ---- normalize + store as fp16 hi/lo ----
    float i0 = 1.f / l0, i1 = 1.f / l1;
    int row0 = qb * 128 + wid * 16 + g;
#pragma unroll
    for (int nf = 0; nf < 8; nf++) {
        int col = h * DK + nf * 8 + 2 * t;
        uint32_t hi, lo;
        split_pack2(o[nf][0] * i0, o[nf][1] * i0, hi, lo);
        *reinterpret_cast<uint32_t*>(Oh + (size_t)row0 * DM + col) = hi;
        *reinterpret_cast<uint32_t*>(Ol + (size_t)row0 * DM + col) = lo;
        split_pack2(o[nf][2] * i1, o[nf][3] * i1, hi, lo);
        *reinterpret_cast<uint32_t*>(Oh + (size_t)(row0 + 8) * DM + col) = hi;
        *reinterpret_cast<uint32_t*>(Ol + (size_t)(row0 + 8) * DM + col) = lo;
    }
}

// ---------------------------------------------------------------------------
extern "C" void kernel_launch(void* const* d_in, const int* in_sizes, int n_in,
                              void* d_out, int out_size)
{
    const float* query = (const float*)d_in[0];
    const float* key_t = (const float*)d_in[1];
    const float* value = (const float*)d_in[2];
    const float* w_q   = (const float*)d_in[3];
    const float* w_k   = (const float*)d_in[4];
    const float* w_v   = (const float*)d_in[5];
    const float* w_o   = (const float*)d_in[6];
    float* out = (float*)d_out;

    f16 *xqh, *xql, *xkh, *xkl, *xvh, *xvl;
    f16 *wqh, *wql, *wkh, *wkl, *wvh, *wvl, *woh, *wol;
    f16 *Qh, *Ql, *Kh, *Kl, *Vh, *Vl, *oh, *ol;
    cudaGetSymbolAddress((void**)&xqh, g_xqh); cudaGetSymbolAddress((void**)&xql, g_xql);
    cudaGetSymbolAddress((void**)&xkh, g_xkh); cudaGetSymbolAddress((void**)&xkl, g_xkl);
    cudaGetSymbolAddress((void**)&xvh, g_xvh); cudaGetSymbolAddress((void**)&xvl, g_xvl);
    cudaGetSymbolAddress((void**)&wqh, g_wqh); cudaGetSymbolAddress((void**)&wql, g_wql);
    cudaGetSymbolAddress((void**)&wkh, g_wkh); cudaGetSymbolAddress((void**)&wkl, g_wkl);
    cudaGetSymbolAddress((void**)&wvh, g_wvh); cudaGetSymbolAddress((void**)&wvl, g_wvl);
    cudaGetSymbolAddress((void**)&woh, g_woh); cudaGetSymbolAddress((void**)&wol, g_wol);
    cudaGetSymbolAddress((void**)&Qh,  g_Qh);  cudaGetSymbolAddress((void**)&Ql,  g_Ql);
    cudaGetSymbolAddress((void**)&Kh,  g_Kh);  cudaGetSymbolAddress((void**)&Kl,  g_Kl);
    cudaGetSymbolAddress((void**)&Vh,  g_Vh);  cudaGetSymbolAddress((void**)&Vl,  g_Vl);
    cudaGetSymbolAddress((void**)&oh,  g_oh);  cudaGetSymbolAddress((void**)&ol,  g_ol);

    const int smem_gemm = 2 * GSTAGE_B;     // 81920 B
    const int smem_attn = 4 * KV_STAGE;     // 73728 B
    cudaFuncSetAttribute(gemm_qkv,  cudaFuncAttributeMaxDynamicSharedMemorySize, smem_gemm);
    cudaFuncSetAttribute(gemm_out,  cudaFuncAttributeMaxDynamicSharedMemorySize, smem_gemm);
    cudaFuncSetAttribute(flash_mma, cudaFuncAttributeMaxDynamicSharedMemorySize, smem_attn);

    const int nAct = SEQ * DM, nW = DM * DM;

    SplitArgs sa{};
    sa.x[0] = query; sa.h[0] = xqh; sa.l[0] = xql;
    sa.x[1] = key_t; sa.h[1] = xkh; sa.l[1] = xkl;
    sa.x[2] = value; sa.h[2] = xvh; sa.l[2] = xvl;
    split_multi<<<dim3(nAct / 1024, 3), 256>>>(sa, nAct);

    SplitArgs sw{};
    sw.x[0] = w_q; sw.h[0] = wqh; sw.l[0] = wql;
    sw.x[1] = w_k; sw.h[1] = wkh; sw.l[1] = wkl;
    sw.x[2] = w_v; sw.h[2] = wvh; sw.l[2] = wvl;
    sw.x[3] = w_o; sw.h[3] = woh; sw.l[3] = wol;
    split_multi<<<dim3(nW / 1024, 4), 256>>>(sw, nW);

    QKVArgs qa{};
    qa.Ah[0] = xqh; qa.Al[0] = xql; qa.Bh[0] = wqh; qa.Bl[0] = wql; qa.Yh[0] = Qh; qa.Yl[0] = Ql;
    qa.Ah[1] = xkh; qa.Al[1] = xkl; qa.Bh[1] = wkh; qa.Bl[1] = wkl; qa.Yh[1] = Kh; qa.Yl[1] = Kl;
    qa.Ah[2] = xvh; qa.Al[2] = xvl; qa.Bh[2] = wvh; qa.Bl[2] = wvl; qa.Yh[2] = Vh; qa.Yl[2] = Vl;
    qa.sc[0] = 0.125f * 1.4426950408889634f;   // 1/sqrt(d_k) * log2(e) -> exp2 domain
    qa.sc[1] = 1.f; qa.sc[2] = 1.f;
    gemm_qkv<<<dim3(DM / 128, SEQ / 128, 3), 256, smem_gemm>>>(qa);

    dim3 agrid(NH, SEQ / 128);   // (16, 32)
    flash_mma<<<agrid, 256, smem_attn>>>(Qh, Ql, Kh, Vh, oh, ol);

    gemm_out<<<dim3(DM / 128, SEQ / 128), 256, smem_gemm>>>(oh, ol, woh, wol, out);
}

// round 17
// speedup vs baseline: 1.6965x; 1.1357x over previous
#include <cuda_runtime.h>
#include <cuda_fp16.h>
#include <cstdint>
#include <math.h>

#define SEQ 4096
#define DM  1024
#define NH  16
#define DK  64

using f16 = __half;

// ---------------------------------------------------------------------------
// Scratch (__device__ globals: allocation-guard safe)
// ---------------------------------------------------------------------------
__device__ f16 g_xqh[SEQ * DM], g_xql[SEQ * DM];
__device__ f16 g_xkh[SEQ * DM], g_xkl[SEQ * DM];
__device__ f16 g_xvh[SEQ * DM], g_xvl[SEQ * DM];
__device__ f16 g_wqh[DM * DM];            // weights: hi only (unsplit B)
__device__ f16 g_wkh[DM * DM];
__device__ f16 g_wvh[DM * DM];
__device__ f16 g_woh[DM * DM];
__device__ f16 g_Qh[SEQ * DM],  g_Ql[SEQ * DM];
__device__ f16 g_Kh[SEQ * DM],  g_Kl[SEQ * DM];
__device__ f16 g_Vh[SEQ * DM],  g_Vl[SEQ * DM];
__device__ f16 g_oh[SEQ * DM],  g_ol[SEQ * DM];

// ---------------------------------------------------------------------------
// PTX helpers — valid at compute_103 (no tcgen05)
// ---------------------------------------------------------------------------
__device__ __forceinline__ uint32_t smem_u32(const void* p) {
    uint32_t a;
    asm("{ .reg .u64 t; cvta.to.shared.u64 t, %1; cvt.u32.u64 %0, t; }" : "=r"(a) : "l"(p));
    return a;
}
__device__ __forceinline__ void ldsm_x4(uint32_t* r, uint32_t addr) {
    asm volatile("ldmatrix.sync.aligned.m8n8.x4.shared.b16 {%0,%1,%2,%3}, [%4];"
                 : "=r"(r[0]), "=r"(r[1]), "=r"(r[2]), "=r"(r[3]) : "r"(addr));
}
__device__ __forceinline__ void ldsm_x4_trans(uint32_t* r, uint32_t addr) {
    asm volatile("ldmatrix.sync.aligned.m8n8.x4.trans.shared.b16 {%0,%1,%2,%3}, [%4];"
                 : "=r"(r[0]), "=r"(r[1]), "=r"(r[2]), "=r"(r[3]) : "r"(addr));
}
__device__ __forceinline__ void mma_f16(float* c, const uint32_t* a, const uint32_t* b) {
    asm volatile(
        "mma.sync.aligned.m16n8k16.row.col.f32.f16.f16.f32 "
        "{%0,%1,%2,%3}, {%4,%5,%6,%7}, {%8,%9}, {%0,%1,%2,%3};"
        : "+f"(c[0]), "+f"(c[1]), "+f"(c[2]), "+f"(c[3])
        : "r"(a[0]), "r"(a[1]), "r"(a[2]), "r"(a[3]), "r"(b[0]), "r"(b[1]));
}
__device__ __forceinline__ void cp16(uint32_t s, const void* g) {
    asm volatile("cp.async.cg.shared.global [%0], [%1], 16;" :: "r"(s), "l"(g));
}
#define CP_COMMIT() asm volatile("cp.async.commit_group;" ::: "memory")
#define CP_WAIT(n)  asm volatile("cp.async.wait_group %0;" :: "n"(n) : "memory")

__device__ __forceinline__ void split_pack2(float x, float y, uint32_t& hi, uint32_t& lo) {
    __half2 h2 = __floats2half2_rn(x, y);
    float rx = x - __half2float(__low2half(h2));
    float ry = y - __half2float(__high2half(h2));
    __half2 l2 = __floats2half2_rn(rx, ry);
    hi = *reinterpret_cast<uint32_t*>(&h2);
    lo = *reinterpret_cast<uint32_t*>(&l2);
}
__device__ __forceinline__ uint32_t pack_f16x2(float x, float y) {
    __half2 h2 = __floats2half2_rn(x, y);
    return *reinterpret_cast<uint32_t*>(&h2);
}

// ---------------------------------------------------------------------------
// Fused fp32 -> fp16 hi/lo split (activations)
// ---------------------------------------------------------------------------
struct SplitArgs {
    const float* x[4];
    f16* h[4];
    f16* l[4];
};

__global__ __launch_bounds__(256) void split_multi(SplitArgs a, int n)
{
    int z = blockIdx.y;
    const float* x = a.x[z];
    f16 *h = a.h[z], *l = a.l[z];
    int i = (blockIdx.x * 256 + threadIdx.x) * 4;
    if (i >= n) return;
    float4 v = *reinterpret_cast<const float4*>(x + i);
    uint32_t h01, l01, h23, l23;
    split_pack2(v.x, v.y, h01, l01);
    split_pack2(v.z, v.w, h23, l23);
    *reinterpret_cast<uint32_t*>(h + i)     = h01;
    *reinterpret_cast<uint32_t*>(h + i + 2) = h23;
    *reinterpret_cast<uint32_t*>(l + i)     = l01;
    *reinterpret_cast<uint32_t*>(l + i + 2) = l23;
}

// fp32 -> fp16 convert only (weights: hi only)
struct ConvArgs {
    const float* x[4];
    f16* h[4];
};

__global__ __launch_bounds__(256) void conv_multi(ConvArgs a, int n)
{
    int z = blockIdx.y;
    const float* x = a.x[z];
    f16* h = a.h[z];
    int i = (blockIdx.x * 256 + threadIdx.x) * 4;
    if (i >= n) return;
    float4 v = *reinterpret_cast<const float4*>(x + i);
    *reinterpret_cast<uint32_t*>(h + i)     = pack_f16x2(v.x, v.y);
    *reinterpret_cast<uint32_t*>(h + i + 2) = pack_f16x2(v.z, v.w);
}

// ---------------------------------------------------------------------------
// HMMA GEMM body: Y = (Ah + Al) @ Bh^T  (A split, B unsplit fp16).
// 3-stage cp.async pipeline, one sync per K tile, 2 CTAs/SM. CTA 128x128.
// ---------------------------------------------------------------------------
#define GLD 40
#define GSTAGE_B 30720   // 3 tiles * 128 * GLD * 2 bytes

template<bool SPLIT_OUT>
__device__ __forceinline__ void gemm_body(
    const f16* __restrict__ Ah, const f16* __restrict__ Al,
    const f16* __restrict__ Bh,
    float* __restrict__ Yf, f16* __restrict__ Yh, f16* __restrict__ Yl,
    f16* smg, float oscale)
{
    const int tid  = threadIdx.x;
    const int lane = tid & 31;
    const int wid  = tid >> 5;
    const int wm   = wid >> 2;
    const int wn   = wid & 3;
    const int bm   = blockIdx.y, bn = blockIdx.x;
    const uint32_t uS = smem_u32(smg);

    auto issue = [&](int ktile) {
        const int kt = ktile * 32;
        const uint32_t sbase = uS + (ktile % 3) * GSTAGE_B;
#pragma unroll
        for (int it = 0; it < 6; it++) {
            int idx  = tid + it * 256;          // 0..1535
            int tile = idx >> 9;                // 0:Ah 1:Al 2:Bh
            int rem  = idx & 511;
            int r    = rem >> 2, j = rem & 3;
            const f16* gp = (tile == 0 ? Ah : tile == 1 ? Al : Bh);
            int row = ((tile < 2) ? bm : bn) * 128 + r;
            cp16(sbase + tile * 10240 + r * 80 + j * 16,
                 gp + (size_t)row * DM + kt + j * 8);
        }
    };

    float acc[4][4][4];
#pragma unroll
    for (int i = 0; i < 4; i++)
#pragma unroll
        for (int j = 0; j < 4; j++)
#pragma unroll
            for (int k = 0; k < 4; k++) acc[i][j][k] = 0.f;

    const int a_r  = (lane & 15), a_c = (lane >> 4) * 8;
    const int kn_r = (lane & 7) + ((lane >> 4) & 1) * 8;
    const int kn_c = ((lane >> 3) & 1) * 8;

    issue(0); CP_COMMIT();
    issue(1); CP_COMMIT();

    for (int kt = 0; kt < 32; kt++) {
        if (kt + 1 < 32) { CP_WAIT(1); } else { CP_WAIT(0); }
        __syncthreads();                       // stage kt ready; prev readers done
        if (kt + 2 < 32) { issue(kt + 2); CP_COMMIT(); }

        const uint32_t st = uS + (kt % 3) * GSTAGE_B;
        const uint32_t uAh = st, uAl = st + 10240, uBh = st + 20480;

#pragma unroll
        for (int s = 0; s < 2; s++) {
            uint32_t ah[4][4], al[4][4], bh[4][2];
#pragma unroll
            for (int i = 0; i < 4; i++) {
                uint32_t off = (uint32_t)(((wm * 64 + i * 16 + a_r) * GLD + s * 16 + a_c) * 2);
                ldsm_x4(ah[i], uAh + off);
                ldsm_x4(al[i], uAl + off);
            }
#pragma unroll
            for (int j2 = 0; j2 < 2; j2++) {
                uint32_t b4h[4];
                uint32_t off = (uint32_t)(((wn * 32 + j2 * 16 + kn_r) * GLD + s * 16 + kn_c) * 2);
                ldsm_x4(b4h, uBh + off);
                bh[2*j2][0]   = b4h[0]; bh[2*j2][1]   = b4h[1];
                bh[2*j2+1][0] = b4h[2]; bh[2*j2+1][1] = b4h[3];
            }
#pragma unroll
            for (int i = 0; i < 4; i++)
#pragma unroll
                for (int j = 0; j < 4; j++)
                    mma_f16(acc[i][j], ah[i], bh[j]);
#pragma unroll
            for (int i = 0; i < 4; i++)
#pragma unroll
                for (int j = 0; j < 4; j++)
                    mma_f16(acc[i][j], al[i], bh[j]);
        }
    }

    const int g = lane >> 2, t = lane & 3;
#pragma unroll
    for (int i = 0; i < 4; i++) {
        int row0 = bm * 128 + wm * 64 + i * 16 + g;
#pragma unroll
        for (int j = 0; j < 4; j++) {
            int col = bn * 128 + wn * 32 + j * 8 + 2 * t;
            if (SPLIT_OUT) {
                uint32_t hi, lo;
                split_pack2(acc[i][j][0] * oscale, acc[i][j][1] * oscale, hi, lo);
                *reinterpret_cast<uint32_t*>(Yh + (size_t)row0 * DM + col) = hi;
                *reinterpret_cast<uint32_t*>(Yl + (size_t)row0 * DM + col) = lo;
                split_pack2(acc[i][j][2] * oscale, acc[i][j][3] * oscale, hi, lo);
                *reinterpret_cast<uint32_t*>(Yh + (size_t)(row0 + 8) * DM + col) = hi;
                *reinterpret_cast<uint32_t*>(Yl + (size_t)(row0 + 8) * DM + col) = lo;
            } else {
                *reinterpret_cast<float2*>(Yf + (size_t)row0 * DM + col) =
                    make_float2(acc[i][j][0], acc[i][j][1]);
                *reinterpret_cast<float2*>(Yf + (size_t)(row0 + 8) * DM + col) =
                    make_float2(acc[i][j][2], acc[i][j][3]);
            }
        }
    }
}

struct QKVArgs {
    const f16 *Ah[3], *Al[3], *Bh[3];
    f16 *Yh[3], *Yl[3];
    float sc[3];
};

__global__ __launch_bounds__(256, 2) void gemm_qkv(QKVArgs a)
{
    extern __shared__ __align__(16) f16 smg[];
    int z = blockIdx.z;
    gemm_body<true>(a.Ah[z], a.Al[z], a.Bh[z], nullptr, a.Yh[z], a.Yl[z], smg, a.sc[z]);
}

__global__ __launch_bounds__(256, 2) void gemm_out(
    const f16* __restrict__ Ah, const f16* __restrict__ Al,
    const f16* __restrict__ Bh, float* __restrict__ Yf)
{
    extern __shared__ __align__(16) f16 smg[];
    gemm_body<false>(Ah, Al, Bh, Yf, nullptr, nullptr, smg, 1.f);
}

// ---------------------------------------------------------------------------
// HMMA flash attention, fp16 (unchanged from R16):
// QK^T = (Qh + Ql) @ Kh ; PV = P @ Vh. 4-stage KV pipeline; 2 CTAs/SM.
// ---------------------------------------------------------------------------
#define FP 72            // pitch f16 (144 B)
#define KV_STAGE 18432   // 2 arrays * 64 * FP * 2 B
#define NKV (SEQ / 64)

__global__ __launch_bounds__(256, 2) void flash_mma(
    const f16* __restrict__ Qh, const f16* __restrict__ Ql,
    const f16* __restrict__ Kh, const f16* __restrict__ Vh,
    f16* __restrict__ Oh, f16* __restrict__ Ol)
{
    extern __shared__ __align__(16) f16 sb[];
    const int tid  = threadIdx.x;
    const int lane = tid & 31;
    const int wid  = tid >> 5;
    const int g    = lane >> 2;
    const int t    = lane & 3;
    const int h    = blockIdx.x;
    const int qb   = blockIdx.y;
    const uint32_t uS = smem_u32(sb);

    const int a_r  = (lane & 15), a_c = (lane >> 4) * 8;
    const int kn_r = (lane & 7) + ((lane >> 4) & 1) * 8;
    const int kn_c = ((lane >> 3) & 1) * 8;
    const int vk_r = (lane & 7) + ((lane >> 3) & 1) * 8;
    const int vn_c = ((lane >> 4) & 1) * 8;

    // ---- stage Q (hi/lo), load fragments to registers ----
#pragma unroll
    for (int it = 0; it < 8; it++) {
        int idx = tid + it * 256;
        int arr = idx >> 10;
        int rem = idx & 1023;
        int r   = rem >> 3, j = rem & 7;
        const f16* gp = arr ? Ql : Qh;
        cp16(uS + arr * 18432 + r * 144 + j * 16,
             gp + (size_t)(qb * 128 + r) * DM + h * DK + j * 8);
    }
    CP_COMMIT(); CP_WAIT(0);
    __syncthreads();

    uint32_t qfh[4][4], qfl[4][4];
#pragma unroll
    for (int kc = 0; kc < 4; kc++) {
        uint32_t aoff = (uint32_t)(((wid * 16 + a_r) * FP + kc * 16 + a_c) * 2);
        ldsm_x4(qfh[kc], uS + aoff);
        ldsm_x4(qfl[kc], uS + 18432 + aoff);
    }
    __syncthreads();   // Q reads done before KV stages overwrite

    auto issue_kv = [&](int kv) {
        const uint32_t base = uS + (kv & 3) * KV_STAGE;
#pragma unroll
        for (int it = 0; it < 4; it++) {
            int idx = tid + it * 256;           // 0..1023
            int arr = idx >> 9;                 // 0:Kh 1:Vh
            int rem = idx & 511;
            int r   = rem >> 3, j = rem & 7;
            const f16* gp = (arr == 0 ? Kh : Vh);
            cp16(base + arr * 9216 + r * 144 + j * 16,
                 gp + (size_t)(kv * 64 + r) * DM + h * DK + j * 8);
        }
    };

    issue_kv(0); CP_COMMIT();
    issue_kv(1); CP_COMMIT();
    issue_kv(2); CP_COMMIT();

    float o[8][4];
#pragma unroll
    for (int nf = 0; nf < 8; nf++)
#pragma unroll
        for (int k = 0; k < 4; k++) o[nf][k] = 0.f;
    float m0 = -1e30f, m1 = -1e30f, l0 = 0.f, l1 = 0.f;

    for (int kv = 0; kv < NKV; kv++) {
        if (kv < NKV - 2)      { CP_WAIT(2); }
        else if (kv == NKV - 2){ CP_WAIT(1); }
        else                   { CP_WAIT(0); }
        __syncthreads();
        if (kv + 3 < NKV) { issue_kv(kv + 3); CP_COMMIT(); }

        const uint32_t kb  = uS + (kv & 3) * KV_STAGE;
        const uint32_t uKh = kb, uVh = kb + 9216;

        // ---- S = (Qh + Ql) @ Kh^T ----
        float s[8][4];
#pragma unroll
        for (int nf = 0; nf < 8; nf++)
#pragma unroll
            for (int k = 0; k < 4; k++) s[nf][k] = 0.f;

#pragma unroll
        for (int kc = 0; kc < 4; kc++) {
            uint32_t b4[4][4];
#pragma unroll
            for (int nf2 = 0; nf2 < 4; nf2++) {
                uint32_t boff = (uint32_t)(((nf2 * 16 + kn_r) * FP + kc * 16 + kn_c) * 2);
                ldsm_x4(b4[nf2], uKh + boff);
            }
#pragma unroll
            for (int nf2 = 0; nf2 < 4; nf2++) {
                mma_f16(s[2*nf2],     qfh[kc], b4[nf2]);
                mma_f16(s[2*nf2 + 1], qfh[kc], b4[nf2] + 2);
            }
#pragma unroll
            for (int nf2 = 0; nf2 < 4; nf2++) {
                mma_f16(s[2*nf2],     qfl[kc], b4[nf2]);
                mma_f16(s[2*nf2 + 1], qfl[kc], b4[nf2] + 2);
            }
        }

        // ---- max reduction ----
        float mx0 = -1e30f, mx1 = -1e30f;
#pragma unroll
        for (int nf = 0; nf < 8; nf++) {
            mx0 = fmaxf(mx0, fmaxf(s[nf][0], s[nf][1]));
            mx1 = fmaxf(mx1, fmaxf(s[nf][2], s[nf][3]));
        }
        mx0 = fmaxf(mx0, __shfl_xor_sync(0xffffffffu, mx0, 1));
        mx0 = fmaxf(mx0, __shfl_xor_sync(0xffffffffu, mx0, 2));
        mx1 = fmaxf(mx1, __shfl_xor_sync(0xffffffffu, mx1, 1));
        mx1 = fmaxf(mx1, __shfl_xor_sync(0xffffffffu, mx1, 2));

        float mn0 = fmaxf(m0, mx0), mn1 = fmaxf(m1, mx1);
        float c0 = exp2f(m0 - mn0), c1 = exp2f(m1 - mn1);
        m0 = mn0; m1 = mn1;
#pragma unroll
        for (int nf = 0; nf < 8; nf++) {
            o[nf][0] *= c0; o[nf][1] *= c0;
            o[nf][2] *= c1; o[nf][3] *= c1;
        }
        float rs0 = 0.f, rs1 = 0.f;

        // ---- exp + fp16 pack + PV MMAs (single V term) ----
#pragma unroll
        for (int kc = 0; kc < 4; kc++) {
            float e00 = exp2f(s[2*kc][0]     - mn0);
            float e01 = exp2f(s[2*kc][1]     - mn0);
            float e02 = exp2f(s[2*kc][2]     - mn1);
            float e03 = exp2f(s[2*kc][3]     - mn1);
            float e10 = exp2f(s[2*kc + 1][0] - mn0);
            float e11 = exp2f(s[2*kc + 1][1] - mn0);
            float e12 = exp2f(s[2*kc + 1][2] - mn1);
            float e13 = exp2f(s[2*kc + 1][3] - mn1);
            rs0 += (e00 + e01) + (e10 + e11);
            rs1 += (e02 + e03) + (e12 + e13);

            uint32_t pa[4];
            pa[0] = pack_f16x2(e00, e01);
            pa[1] = pack_f16x2(e02, e03);
            pa[2] = pack_f16x2(e10, e11);
            pa[3] = pack_f16x2(e12, e13);

            uint32_t v4[4][4];
#pragma unroll
            for (int nf2 = 0; nf2 < 4; nf2++) {
                uint32_t voff = (uint32_t)(((kc * 16 + vk_r) * FP + nf2 * 16 + vn_c) * 2);
                ldsm_x4_trans(v4[nf2], uVh + voff);
            }
#pragma unroll
            for (int nf2 = 0; nf2 < 4; nf2++) {
                mma_f16(o[2*nf2],     pa, v4[nf2]);
                mma_f16(o[2*nf2 + 1], pa, v4[nf2] + 2);
            }
        }
        rs0 += __shfl_xor_sync(0xffffffffu, rs0, 1);
        rs0 += __shfl_xor_sync(0xffffffffu, rs0, 2);
        rs1 += __shfl_xor_sync(0xffffffffu, rs1, 1);
        rs1 += __shfl_xor_sync(0xffffffffu, rs1, 2);
        l0 = l0 * c0 + rs0;
        l1 = l1 * c1 + rs1;
    }

    // ---- normalize + store as fp16 hi/lo ----
    float i0 = 1.f / l0, i1 = 1.f / l1;
    int row0 = qb * 128 + wid * 16 + g;
#pragma unroll
    for (int nf = 0; nf < 8; nf++) {
        int col = h * DK + nf * 8 + 2 * t;
        uint32_t hi, lo;
        split_pack2(o[nf][0] * i0, o[nf][1] * i0, hi, lo);
        *reinterpret_cast<uint32_t*>(Oh + (size_t)row0 * DM + col) = hi;
        *reinterpret_cast<uint32_t*>(Ol + (size_t)row0 * DM + col) = lo;
        split_pack2(o[nf][2] * i1, o[nf][3] * i1, hi, lo);
        *reinterpret_cast<uint32_t*>(Oh + (size_t)(row0 + 8) * DM + col) = hi;
        *reinterpret_cast<uint32_t*>(Ol + (size_t)(row0 + 8) * DM + col) = lo;
    }
}

// ---------------------------------------------------------------------------
extern "C" void kernel_launch(void* const* d_in, const int* in_sizes, int n_in,
                              void* d_out, int out_size)
{
    const float* query = (const float*)d_in[0];
    const float* key_t = (const float*)d_in[1];
    const float* value = (const float*)d_in[2];
    const float* w_q   = (const float*)d_in[3];
    const float* w_k   = (const float*)d_in[4];
    const float* w_v   = (const float*)d_in[5];
    const float* w_o   = (const float*)d_in[6];
    float* out = (float*)d_out;

    f16 *xqh, *xql, *xkh, *xkl, *xvh, *xvl;
    f16 *wqh, *wkh, *wvh, *woh;
    f16 *Qh, *Ql, *Kh, *Kl, *Vh, *Vl, *oh, *ol;
    cudaGetSymbolAddress((void**)&xqh, g_xqh); cudaGetSymbolAddress((void**)&xql, g_xql);
    cudaGetSymbolAddress((void**)&xkh, g_xkh); cudaGetSymbolAddress((void**)&xkl, g_xkl);
    cudaGetSymbolAddress((void**)&xvh, g_xvh); cudaGetSymbolAddress((void**)&xvl, g_xvl);
    cudaGetSymbolAddress((void**)&wqh, g_wqh);
    cudaGetSymbolAddress((void**)&wkh, g_wkh);
    cudaGetSymbolAddress((void**)&wvh, g_wvh);
    cudaGetSymbolAddress((void**)&woh, g_woh);
    cudaGetSymbolAddress((void**)&Qh,  g_Qh);  cudaGetSymbolAddress((void**)&Ql,  g_Ql);
    cudaGetSymbolAddress((void**)&Kh,  g_Kh);  cudaGetSymbolAddress((void**)&Kl,  g_Kl);
    cudaGetSymbolAddress((void**)&Vh,  g_Vh);  cudaGetSymbolAddress((void**)&Vl,  g_Vl);
    cudaGetSymbolAddress((void**)&oh,  g_oh);  cudaGetSymbolAddress((void**)&ol,  g_ol);

    const int smem_gemm = 3 * GSTAGE_B;     // 92160 B  (2 CTAs/SM)
    const int smem_attn = 4 * KV_STAGE;     // 73728 B  (2 CTAs/SM)
    cudaFuncSetAttribute(gemm_qkv,  cudaFuncAttributeMaxDynamicSharedMemorySize, smem_gemm);
    cudaFuncSetAttribute(gemm_out,  cudaFuncAttributeMaxDynamicSharedMemorySize, smem_gemm);
    cudaFuncSetAttribute(flash_mma, cudaFuncAttributeMaxDynamicSharedMemorySize, smem_attn);

    const int nAct = SEQ * DM, nW = DM * DM;

    SplitArgs sa{};
    sa.x[0] = query; sa.h[0] = xqh; sa.l[0] = xql;
    sa.x[1] = key_t; sa.h[1] = xkh; sa.l[1] = xkl;
    sa.x[2] = value; sa.h[2] = xvh; sa.l[2] = xvl;
    split_multi<<<dim3(nAct / 1024, 3), 256>>>(sa, nAct);

    ConvArgs cw{};
    cw.x[0] = w_q; cw.h[0] = wqh;
    cw.x[1] = w_k; cw.h[1] = wkh;
    cw.x[2] = w_v; cw.h[2] = wvh;
    cw.x[3] = w_o; cw.h[3] = woh;
    conv_multi<<<dim3(nW / 1024, 4), 256>>>(cw, nW);

    QKVArgs qa{};
    qa.Ah[0] = xqh; qa.Al[0] = xql; qa.Bh[0] = wqh; qa.Yh[0] = Qh; qa.Yl[0] = Ql;
    qa.Ah[1] = xkh; qa.Al[1] = xkl; qa.Bh[1] = wkh; qa.Yh[1] = Kh; qa.Yl[1] = Kl;
    qa.Ah[2] = xvh; qa.Al[2] = xvl; qa.Bh[2] = wvh; qa.Yh[2] = Vh; qa.Yl[2] = Vl;
    qa.sc[0] = 0.125f * 1.4426950408889634f;   // 1/sqrt(d_k) * log2(e) -> exp2 domain
    qa.sc[1] = 1.f; qa.sc[2] = 1.f;
    gemm_qkv<<<dim3(DM / 128, SEQ / 128, 3), 256, smem_gemm>>>(qa);

    dim3 agrid(NH, SEQ / 128);   // (16, 32)
    flash_mma<<<agrid, 256, smem_attn>>>(Qh, Ql, Kh, Vh, oh, ol);

    gemm_out<<<dim3(DM / 128, SEQ / 128), 256, smem_gemm>>>(oh, ol, woh, out);
}